// round 9
// baseline (speedup 1.0000x reference)
#include <cuda_runtime.h>
#include <cuda_bf16.h>
#include <math.h>
#include <stdint.h>

// Problem dims (fixed)
#define Dm   1024
#define Hh   16
#define DH   64
#define Rr   32
#define Bb   2
#define Ss   2048
#define BS   (Bb*Ss)        // 4096
#define HR   (Hh*Rr)        // 512
#define Ii   4096
#define RFC  512

// ---------------- scratch ----------------
__device__ float g_x [BS*Dm];
__device__ float g_Pq[BS*HR];
__device__ float g_Pk[BS*HR];
__device__ float g_Pv[BS*HR];
__device__ float g_Q [Bb*Hh*Ss*DH];
__device__ float g_K [Bb*Hh*Ss*DH];
__device__ float g_V [Bb*Hh*DH*Ss];   // V stored TRANSPOSED: [b,h,dh,s]
__device__ float g_Y [BS*Dm];
__device__ float g_t [BS*RFC];
__device__ float g_h [BS*Dm];
__device__ float g_a [BS*Ii];

// ---------------- PTX helpers ----------------
__device__ __forceinline__ void cp16(uint32_t saddr, const void* gptr) {
    asm volatile("cp.async.ca.shared.global [%0], [%1], 16;" :: "r"(saddr), "l"(gptr));
}
__device__ __forceinline__ uint32_t smem_u32(const void* p) {
    return (uint32_t)__cvta_generic_to_shared(p);
}
__device__ __forceinline__ void ldsm4(uint32_t& r0, uint32_t& r1, uint32_t& r2, uint32_t& r3,
                                      uint32_t addr) {
    asm volatile("ldmatrix.sync.aligned.m8n8.x4.shared.b16 {%0,%1,%2,%3}, [%4];"
                 : "=r"(r0), "=r"(r1), "=r"(r2), "=r"(r3) : "r"(addr));
}
// tf32 mma ignores low 13 mantissa bits: raw fp32 bits are a valid operand.
__device__ __forceinline__ void mma_tf32(float* d, const uint32_t* a, const uint32_t* b) {
    asm volatile(
        "mma.sync.aligned.m16n8k8.row.col.f32.tf32.tf32.f32 "
        "{%0,%1,%2,%3}, {%4,%5,%6,%7}, {%8,%9}, {%0,%1,%2,%3};"
        : "+f"(d[0]), "+f"(d[1]), "+f"(d[2]), "+f"(d[3])
        : "r"(a[0]), "r"(a[1]), "r"(a[2]), "r"(a[3]), "r"(b[0]), "r"(b[1]));
}
__device__ __forceinline__ float gelu_tanh(float x) {
    float u = 0.7978845608f * (x + 0.044715f * x * x * x);
    float t = 1.f - 2.f / (__expf(2.f * u) + 1.f);
    return 0.5f * x * (1.f + t);
}

// ---------------- LayerNorm ----------------
__global__ void ln_kernel(const float* __restrict__ in, const float* __restrict__ w,
                          const float* __restrict__ b, float* __restrict__ out) {
    __shared__ float xs[Dm];
    __shared__ float red[8];
    int row = blockIdx.x;
    int t = threadIdx.x;
    const float* x = in + (size_t)row * Dm;

    float s = 0.f;
    #pragma unroll
    for (int i = t; i < Dm; i += 256) { float v = x[i]; xs[i] = v; s += v; }
    #pragma unroll
    for (int o = 16; o; o >>= 1) s += __shfl_xor_sync(0xffffffffu, s, o);
    if ((t & 31) == 0) red[t >> 5] = s;
    __syncthreads();
    float tot = 0.f;
    #pragma unroll
    for (int i = 0; i < 8; i++) tot += red[i];
    float mean = tot * (1.0f / Dm);
    __syncthreads();

    float vs = 0.f;
    #pragma unroll
    for (int i = t; i < Dm; i += 256) { float d = xs[i] - mean; vs += d * d; }
    #pragma unroll
    for (int o = 16; o; o >>= 1) vs += __shfl_xor_sync(0xffffffffu, vs, o);
    if ((t & 31) == 0) red[t >> 5] = vs;
    __syncthreads();
    float vtot = 0.f;
    #pragma unroll
    for (int i = 0; i < 8; i++) vtot += red[i];
    float rstd = rsqrtf(vtot * (1.0f / Dm) + 1e-5f);

    #pragma unroll
    for (int i = t; i < Dm; i += 256)
        out[(size_t)row * Dm + i] = (xs[i] - mean) * rstd * w[i] + b[i];
}

// ---------------- TF32 GEMM: BK=32, 3-stage cp.async pipeline ----------------
#define GEMM_BK 32
#define GEMM_AKp 36
#define GEMM_SMEM(BN) ((3 * 128 * GEMM_AKp + 3 * GEMM_BK * ((BN) + 8)) * 4)

template<int EPI, int BN>
__device__ __forceinline__ void gemm_core(
    const float* __restrict__ A, const float* __restrict__ B, float* __restrict__ C,
    int M, int N, int K, const float* __restrict__ bias, const float* __restrict__ res,
    int m0, int n0)
{
    constexpr int BM = 128, BK = GEMM_BK, AKp = GEMM_AKp, BNp = BN + 8;
    constexpr int WM_ = (BN == 128) ? 2 : 4;
    constexpr int WTM = BM / WM_;
    constexpr int WTN = BN / (8 / WM_);
    constexpr int MT = WTM / 16;
    constexpr int NT = WTN / 8;

    extern __shared__ float smf[];
    float* As = smf;                           // [3][BM][AKp]
    float* Bsm = smf + 3 * BM * AKp;           // [3][BK][BNp]

    int tid = threadIdx.x;
    int w = tid >> 5, lane = tid & 31;
    int lr = lane >> 2, lc = lane & 3;
    int wm = (w % WM_) * WTM;
    int wn = (w / WM_) * WTN;
    int arow_f = (lane & 7) + ((lane >> 3) & 1) * 8;
    int acol_f = (lane >> 4) * 4;

    float acc[MT][NT][4];
    #pragma unroll
    for (int mt = 0; mt < MT; mt++)
        #pragma unroll
        for (int nt = 0; nt < NT; nt++)
            #pragma unroll
            for (int i = 0; i < 4; i++) acc[mt][nt][i] = 0.f;

    const float* Ag = A + (size_t)m0 * K;
    const float* Bg = B + n0;

    auto loadTile = [&](int kt, int buf) {
        int k0 = kt * BK;
        float* Abuf = As + buf * BM * AKp;
        float* Bbuf = Bsm + buf * BK * BNp;
        #pragma unroll
        for (int i = 0; i < 4; i++) {              // A: 128x32 = 1024 cp16
            int q = tid + i * 256;
            int m = q >> 3, c = q & 7;
            cp16(smem_u32(Abuf + m * AKp + c * 4), Ag + (size_t)m * K + k0 + c * 4);
        }
        #pragma unroll
        for (int i = 0; i < BN / 32; i++) {        // B: 32xBN
            int q = tid + i * 256;
            int k = q / (BN / 4), n4 = q % (BN / 4);
            cp16(smem_u32(Bbuf + k * BNp + n4 * 4), Bg + (size_t)(k0 + k) * N + n4 * 4);
        }
        asm volatile("cp.async.commit_group;");
    };

    int NTILES = K / BK;
    loadTile(0, 0);
    if (NTILES > 1) loadTile(1, 1);
    for (int kt = 0; kt < NTILES; kt++) {
        int buf = kt % 3;
        if (kt + 2 < NTILES) {
            loadTile(kt + 2, (kt + 2) % 3);
            asm volatile("cp.async.wait_group 2;");
        } else if (kt + 1 < NTILES) {
            asm volatile("cp.async.wait_group 1;");
        } else {
            asm volatile("cp.async.wait_group 0;");
        }
        __syncthreads();
        const float* Abuf = As + buf * BM * AKp;
        const float* Bbuf = Bsm + buf * BK * BNp;

        #pragma unroll
        for (int ks = 0; ks < 4; ks++) {
            int kb = ks * 8;
            uint32_t af[MT][4], bf[NT][2];
            #pragma unroll
            for (int mt = 0; mt < MT; mt++)
                ldsm4(af[mt][0], af[mt][1], af[mt][2], af[mt][3],
                      smem_u32(Abuf + (wm + mt * 16 + arow_f) * AKp + kb + acol_f));
            #pragma unroll
            for (int nt = 0; nt < NT; nt++) {
                int cn = wn + nt * 8 + lr;
                bf[nt][0] = __float_as_uint(Bbuf[(kb + lc) * BNp + cn]);
                bf[nt][1] = __float_as_uint(Bbuf[(kb + lc + 4) * BNp + cn]);
            }
            #pragma unroll
            for (int mt = 0; mt < MT; mt++)
                #pragma unroll
                for (int nt = 0; nt < NT; nt++)
                    mma_tf32(acc[mt][nt], af[mt], bf[nt]);
        }
        __syncthreads();
    }

    #pragma unroll
    for (int mt = 0; mt < MT; mt++) {
        #pragma unroll
        for (int hh = 0; hh < 2; hh++) {
            int row = m0 + wm + mt * 16 + lr + hh * 8;
            #pragma unroll
            for (int nt = 0; nt < NT; nt++) {
                int col = n0 + wn + nt * 8 + 2 * lc;
                float v0 = acc[mt][nt][2 * hh + 0];
                float v1 = acc[mt][nt][2 * hh + 1];
                if (EPI == 1) {
                    v0 += bias[col]     + res[(size_t)row * N + col];
                    v1 += bias[col + 1] + res[(size_t)row * N + col + 1];
                } else if (EPI == 2) {
                    v0 = gelu_tanh(v0 + bias[col]);
                    v1 = gelu_tanh(v1 + bias[col + 1]);
                }
                *(float2*)&C[(size_t)row * N + col] = make_float2(v0, v1);
            }
        }
    }
}

template<int EPI, int BN>
__global__ void __launch_bounds__(256, 2) sgemm_t(
    const float* __restrict__ A, const float* __restrict__ B, float* __restrict__ C,
    int M, int N, int K, const float* __restrict__ bias, const float* __restrict__ res)
{
    gemm_core<EPI, BN>(A, B, C, M, N, K, bias, res, blockIdx.y * 128, blockIdx.x * BN);
}

__global__ void __launch_bounds__(256, 2) sgemm_qkv(
    const float* __restrict__ A,
    const float* __restrict__ B0, const float* __restrict__ B1, const float* __restrict__ B2,
    float* __restrict__ C0, float* __restrict__ C1, float* __restrict__ C2,
    int M, int N, int K)
{
    int sel = blockIdx.x >> 2, nb = blockIdx.x & 3;
    const float* B = (sel == 0) ? B0 : (sel == 1) ? B1 : B2;
    float* C = (sel == 0) ? C0 : (sel == 1) ? C1 : C2;
    gemm_core<0, 128>(A, B, C, M, N, K, nullptr, nullptr, blockIdx.y * 128, nb * 128);
}

// ---------------- head_proj: q,k -> (b,h,s,e); v -> TRANSPOSED (b,h,e,s) ----------------
__global__ void __launch_bounds__(256) head_proj2(
    const float* __restrict__ Pq, const float* __restrict__ Pk, const float* __restrict__ Pv,
    const float* __restrict__ Vq, const float* __restrict__ Vk, const float* __restrict__ Vv,
    const float* __restrict__ bq, const float* __restrict__ bk, const float* __restrict__ bv,
    float* __restrict__ Oq, float* __restrict__ Ok, float* __restrict__ Ov)
{
    __shared__ float vw[Rr][DH];
    __shared__ float pt[64][Rr + 1];
    int z = blockIdx.z;
    const float* P  = (z == 0) ? Pq : (z == 1) ? Pk : Pv;
    const float* Vw = (z == 0) ? Vq : (z == 1) ? Vk : Vv;
    const float* bi = (z == 0) ? bq : (z == 1) ? bk : bv;
    float* O        = (z == 0) ? Oq : (z == 1) ? Ok : Ov;

    int h = blockIdx.y;
    int s0 = blockIdx.x * 64;
    int tid = threadIdx.x;

    #pragma unroll
    for (int i = 0; i < 8; i++) {
        int idx = tid + i * 256;
        vw[idx >> 6][idx & 63] = Vw[(size_t)h * Rr * DH + idx];
    }
    #pragma unroll
    for (int i = 0; i < 8; i++) {
        int idx = tid + i * 256;
        int r = idx >> 5, c = idx & 31;
        pt[r][c] = P[(size_t)(s0 + r) * HR + h * Rr + c];
    }
    __syncthreads();

    if (z < 2) {
        int e = tid & 63;
        int sl = tid >> 6;
        float bv_ = bi[h * DH + e];
        #pragma unroll
        for (int i = 0; i < 16; i++) {
            int r = sl + i * 4;
            float acc = bv_;
            #pragma unroll
            for (int rr = 0; rr < Rr; rr++) acc = fmaf(pt[r][rr], vw[rr][e], acc);
            int bs = s0 + r;
            int b = bs >> 11, s = bs & 2047;
            O[(((size_t)(b * Hh + h)) * Ss + s) * DH + e] = acc;
        }
    } else {
        int sl = tid & 63;
        int e0 = tid >> 6;
        int bs = s0 + sl;
        int b = bs >> 11, s = bs & 2047;
        float* obase = O + ((size_t)(b * Hh + h)) * DH * Ss + s;
        #pragma unroll
        for (int i = 0; i < 16; i++) {
            int e = e0 + i * 4;
            float acc = bi[h * DH + e];
            #pragma unroll
            for (int rr = 0; rr < Rr; rr++) acc = fmaf(pt[sl][rr], vw[rr][e], acc);
            obase[(size_t)e * Ss] = acc;
        }
    }
}

// ---------------- attention v6: double-buffered K/V + ldmatrix + reg cap ----------------
#define ASd 68
#define ATTN_SMEM ((4 * 64 * ASd + 128 * ASd) * 4)   // 104448 B

__global__ void __launch_bounds__(256, 2) attn_mma5(
    const float* __restrict__ Q, const float* __restrict__ K,
    const float* __restrict__ V, float* __restrict__ Y)
{
    extern __shared__ uint32_t sm[];
    uint32_t* KsB0 = sm;
    uint32_t* KsB1 = sm + 64 * ASd;
    uint32_t* VtB0 = sm + 2 * 64 * ASd;
    uint32_t* VtB1 = sm + 3 * 64 * ASd;
    uint32_t* Ps   = sm + 4 * 64 * ASd;      // [128][ASd]

    int bh = blockIdx.y;
    int qblk = gridDim.x - 1 - blockIdx.x;   // heavy blocks first
    int q0 = qblk * 128;
    int tid = threadIdx.x;
    int w = tid >> 5, lane = tid & 31;
    int lr = lane >> 2, lc = lane & 3;
    int wq = w * 16;
    int frow = (lane & 7) + ((lane >> 3) & 1) * 8;   // A-frag ldsm row-in-16
    int fcol = (lane >> 4) * 4;                       // A-frag ldsm col chunk
    int brow = lane & 7;                              // B-frag ldsm row-in-8
    int bcol = (lane >> 3) * 4;                       // B-frag ldsm col chunk

    // persistent Q fragments (raw fp32 bits)
    uint32_t qf[8][4];
    const float* Qb = Q + ((size_t)bh * Ss + q0 + wq) * DH;
    #pragma unroll
    for (int ks = 0; ks < 8; ks++) {
        qf[ks][0] = __float_as_uint(Qb[(size_t)lr * DH + ks * 8 + lc]);
        qf[ks][1] = __float_as_uint(Qb[(size_t)(lr + 8) * DH + ks * 8 + lc]);
        qf[ks][2] = __float_as_uint(Qb[(size_t)lr * DH + ks * 8 + lc + 4]);
        qf[ks][3] = __float_as_uint(Qb[(size_t)(lr + 8) * DH + ks * 8 + lc + 4]);
    }

    const float* Kg = K + (size_t)bh * Ss * DH;
    const float* Vg = V + (size_t)bh * DH * Ss;

    auto loadTile = [&](int kt, int buf) {
        uint32_t* Ks = buf ? KsB1 : KsB0;
        uint32_t* Vt = buf ? VtB1 : VtB0;
        #pragma unroll
        for (int i = 0; i < 4; i++) {
            int idx = tid + i * 256;
            int r = idx >> 4, c4 = (idx & 15) * 4;
            cp16(smem_u32(Ks + r * ASd + c4), Kg + (size_t)(kt * 64 + r) * DH + c4);
            cp16(smem_u32(Vt + r * ASd + c4), Vg + (size_t)r * Ss + kt * 64 + c4);
        }
        asm volatile("cp.async.commit_group;");
    };

    float o[8][4];
    #pragma unroll
    for (int nt = 0; nt < 8; nt++)
        #pragma unroll
        for (int i = 0; i < 4; i++) o[nt][i] = 0.f;
    float m0 = -1e30f, m1 = -1e30f, l0 = 0.f, l1 = 0.f;
    const float scale = 0.125f;

    int ktmax = 2 * qblk + 1;
    loadTile(0, 0);
    for (int kt = 0; kt <= ktmax; kt++) {
        int buf = kt & 1;
        if (kt < ktmax) {
            loadTile(kt + 1, buf ^ 1);
            asm volatile("cp.async.wait_group 1;");
        } else {
            asm volatile("cp.async.wait_group 0;");
        }
        __syncthreads();
        uint32_t* Ks = buf ? KsB1 : KsB0;
        uint32_t* Vt = buf ? VtB1 : VtB0;

        // S = Q @ K^T (per warp 16x64)
        float s[8][4];
        #pragma unroll
        for (int nt = 0; nt < 8; nt++)
            #pragma unroll
            for (int i = 0; i < 4; i++) s[nt][i] = 0.f;
        #pragma unroll
        for (int k2 = 0; k2 < 4; k2++) {
            #pragma unroll
            for (int nt = 0; nt < 8; nt++) {
                uint32_t b0, b1, b2, b3;
                ldsm4(b0, b1, b2, b3,
                      smem_u32(Ks + (nt * 8 + brow) * ASd + k2 * 16 + bcol));
                uint32_t bfa[2] = {b0, b1}, bfb[2] = {b2, b3};
                mma_tf32(s[nt], qf[2 * k2],     bfa);
                mma_tf32(s[nt], qf[2 * k2 + 1], bfb);
            }
        }

        // scale + causal mask
        bool diag = (kt >= 2 * qblk);
        int r0 = q0 + wq + lr, r1 = r0 + 8;
        int kc0 = kt * 64;
        #pragma unroll
        for (int nt = 0; nt < 8; nt++) {
            int c0 = kc0 + nt * 8 + 2 * lc, c1 = c0 + 1;
            s[nt][0] = (diag && c0 > r0) ? -1e30f : s[nt][0] * scale;
            s[nt][1] = (diag && c1 > r0) ? -1e30f : s[nt][1] * scale;
            s[nt][2] = (diag && c0 > r1) ? -1e30f : s[nt][2] * scale;
            s[nt][3] = (diag && c1 > r1) ? -1e30f : s[nt][3] * scale;
        }

        // online softmax
        float mx0 = -1e30f, mx1 = -1e30f;
        #pragma unroll
        for (int nt = 0; nt < 8; nt++) {
            mx0 = fmaxf(mx0, fmaxf(s[nt][0], s[nt][1]));
            mx1 = fmaxf(mx1, fmaxf(s[nt][2], s[nt][3]));
        }
        mx0 = fmaxf(mx0, __shfl_xor_sync(0xffffffffu, mx0, 1));
        mx0 = fmaxf(mx0, __shfl_xor_sync(0xffffffffu, mx0, 2));
        mx1 = fmaxf(mx1, __shfl_xor_sync(0xffffffffu, mx1, 1));
        mx1 = fmaxf(mx1, __shfl_xor_sync(0xffffffffu, mx1, 2));
        float mn0 = fmaxf(m0, mx0), mn1 = fmaxf(m1, mx1);
        float c0f = __expf(m0 - mn0), c1f = __expf(m1 - mn1);
        l0 *= c0f; l1 *= c1f;
        #pragma unroll
        for (int nt = 0; nt < 8; nt++) {
            o[nt][0] *= c0f; o[nt][1] *= c0f;
            o[nt][2] *= c1f; o[nt][3] *= c1f;
        }
        m0 = mn0; m1 = mn1;

        // P -> per-warp private smem rows
        #pragma unroll
        for (int nt = 0; nt < 8; nt++) {
            int c0 = nt * 8 + 2 * lc;
            float p00 = __expf(s[nt][0] - mn0);
            float p01 = __expf(s[nt][1] - mn0);
            float p10 = __expf(s[nt][2] - mn1);
            float p11 = __expf(s[nt][3] - mn1);
            l0 += p00 + p01; l1 += p10 + p11;
            Ps[(wq + lr) * ASd + c0]         = __float_as_uint(p00);
            Ps[(wq + lr) * ASd + c0 + 1]     = __float_as_uint(p01);
            Ps[(wq + lr + 8) * ASd + c0]     = __float_as_uint(p10);
            Ps[(wq + lr + 8) * ASd + c0 + 1] = __float_as_uint(p11);
        }
        __syncwarp();

        // O += P @ V
        #pragma unroll
        for (int k2 = 0; k2 < 4; k2++) {
            uint32_t paA[4], paB[4];
            ldsm4(paA[0], paA[1], paA[2], paA[3],
                  smem_u32(Ps + (wq + frow) * ASd + (2 * k2) * 8 + fcol));
            ldsm4(paB[0], paB[1], paB[2], paB[3],
                  smem_u32(Ps + (wq + frow) * ASd + (2 * k2 + 1) * 8 + fcol));
            #pragma unroll
            for (int nt = 0; nt < 8; nt++) {
                uint32_t b0, b1, b2, b3;
                ldsm4(b0, b1, b2, b3,
                      smem_u32(Vt + (nt * 8 + brow) * ASd + k2 * 16 + bcol));
                uint32_t bfa[2] = {b0, b1}, bfb[2] = {b2, b3};
                mma_tf32(o[nt], paA, bfa);
                mma_tf32(o[nt], paB, bfb);
            }
        }
        __syncthreads();    // buffer kt consumed -> reusable at kt+2
    }

    // epilogue
    l0 += __shfl_xor_sync(0xffffffffu, l0, 1);
    l0 += __shfl_xor_sync(0xffffffffu, l0, 2);
    l1 += __shfl_xor_sync(0xffffffffu, l1, 1);
    l1 += __shfl_xor_sync(0xffffffffu, l1, 2);
    float i0 = 1.f / l0, i1 = 1.f / l1;
    int b = bh >> 4, h = bh & 15;
    int row0 = q0 + wq + lr, row1 = row0 + 8;
    float* y0 = Y + (((size_t)(b * Ss + row0)) * Hh + h) * DH;
    float* y1 = Y + (((size_t)(b * Ss + row1)) * Hh + h) * DH;
    #pragma unroll
    for (int nt = 0; nt < 8; nt++) {
        int c = nt * 8 + 2 * lc;
        *(float2*)(y0 + c) = make_float2(o[nt][0] * i0, o[nt][1] * i0);
        *(float2*)(y1 + c) = make_float2(o[nt][2] * i1, o[nt][3] * i1);
    }
}

// ---------------- launch ----------------
extern "C" void kernel_launch(void* const* d_in, const int* in_sizes, int n_in,
                              void* d_out, int out_size) {
    const float* hidden = (const float*)d_in[0];
    const float* ln1_w = (const float*)d_in[2];
    const float* ln1_b = (const float*)d_in[3];
    const float* q_U = (const float*)d_in[4];
    const float* q_V = (const float*)d_in[5];
    const float* q_b = (const float*)d_in[6];
    const float* k_U = (const float*)d_in[7];
    const float* k_V = (const float*)d_in[8];
    const float* k_b = (const float*)d_in[9];
    const float* v_U = (const float*)d_in[10];
    const float* v_V = (const float*)d_in[11];
    const float* v_b = (const float*)d_in[12];
    const float* out_U = (const float*)d_in[13];
    const float* out_V = (const float*)d_in[14];
    const float* out_b = (const float*)d_in[15];
    const float* ln2_w = (const float*)d_in[16];
    const float* ln2_b = (const float*)d_in[17];
    const float* fc1_U = (const float*)d_in[18];
    const float* fc1_V = (const float*)d_in[19];
    const float* fc1_b = (const float*)d_in[20];
    const float* fc2_U = (const float*)d_in[21];
    const float* fc2_V = (const float*)d_in[22];
    const float* fc2_b = (const float*)d_in[23];
    float* out = (float*)d_out;

    float *x_, *Pq_, *Pk_, *Pv_, *Q_, *K_, *V_, *Y_, *t_, *h_, *a_;
    cudaGetSymbolAddress((void**)&x_,  g_x);
    cudaGetSymbolAddress((void**)&Pq_, g_Pq);
    cudaGetSymbolAddress((void**)&Pk_, g_Pk);
    cudaGetSymbolAddress((void**)&Pv_, g_Pv);
    cudaGetSymbolAddress((void**)&Q_,  g_Q);
    cudaGetSymbolAddress((void**)&K_,  g_K);
    cudaGetSymbolAddress((void**)&V_,  g_V);
    cudaGetSymbolAddress((void**)&Y_,  g_Y);
    cudaGetSymbolAddress((void**)&t_,  g_t);
    cudaGetSymbolAddress((void**)&h_,  g_h);
    cudaGetSymbolAddress((void**)&a_,  g_a);

    cudaFuncSetAttribute(attn_mma5, cudaFuncAttributeMaxDynamicSharedMemorySize, ATTN_SMEM);
    cudaFuncSetAttribute(sgemm_qkv, cudaFuncAttributeMaxDynamicSharedMemorySize, GEMM_SMEM(128));
    cudaFuncSetAttribute(sgemm_t<0, 64>,  cudaFuncAttributeMaxDynamicSharedMemorySize, GEMM_SMEM(64));
    cudaFuncSetAttribute(sgemm_t<1, 128>, cudaFuncAttributeMaxDynamicSharedMemorySize, GEMM_SMEM(128));
    cudaFuncSetAttribute(sgemm_t<2, 128>, cudaFuncAttributeMaxDynamicSharedMemorySize, GEMM_SMEM(128));

    // 1) x = LN1(hidden)
    ln_kernel<<<BS, 256>>>(hidden, ln1_w, ln1_b, x_);

    // 2) Pq/Pk/Pv = x @ {q,k,v}_U
    {
        dim3 g(12, BS / 128);
        sgemm_qkv<<<g, 256, GEMM_SMEM(128)>>>(x_, q_U, k_U, v_U, Pq_, Pk_, Pv_, BS, HR, Dm);
    }

    // 3) head expansion (V transposed)
    {
        dim3 g(BS / 64, Hh, 3);
        head_proj2<<<g, 256>>>(Pq_, Pk_, Pv_, q_V, k_V, v_V, q_b, k_b, v_b, Q_, K_, V_);
    }

    // 4) causal attention
    {
        dim3 g(Ss / 128, Bb * Hh);
        attn_mma5<<<g, 256, ATTN_SMEM>>>(Q_, K_, V_, Y_);
    }

    // 5) h = hidden + (Y @ out_U) @ out_V + out_b
    {
        dim3 g1(RFC / 64, BS / 128);
        sgemm_t<0, 64><<<g1, 256, GEMM_SMEM(64)>>>(Y_, out_U, t_, BS, RFC, Dm, nullptr, nullptr);
        dim3 g2(Dm / 128, BS / 128);
        sgemm_t<1, 128><<<g2, 256, GEMM_SMEM(128)>>>(t_, out_V, h_, BS, Dm, RFC, out_b, hidden);
    }

    // 6) z = LN2(h)
    ln_kernel<<<BS, 256>>>(h_, ln2_w, ln2_b, x_);

    // 7) a = gelu((z @ fc1_U) @ fc1_V + fc1_b)
    {
        dim3 g1(RFC / 64, BS / 128);
        sgemm_t<0, 64><<<g1, 256, GEMM_SMEM(64)>>>(x_, fc1_U, t_, BS, RFC, Dm, nullptr, nullptr);
        dim3 g2(Ii / 128, BS / 128);
        sgemm_t<2, 128><<<g2, 256, GEMM_SMEM(128)>>>(t_, fc1_V, a_, BS, Ii, RFC, fc1_b, nullptr);
    }

    // 8) out = h + (a @ fc2_U) @ fc2_V + fc2_b
    {
        dim3 g1(RFC / 64, BS / 128);
        sgemm_t<0, 64><<<g1, 256, GEMM_SMEM(64)>>>(a_, fc2_U, t_, BS, RFC, Ii, nullptr, nullptr);
        dim3 g2(Dm / 128, BS / 128);
        sgemm_t<1, 128><<<g2, 256, GEMM_SMEM(128)>>>(t_, fc2_V, out, BS, Dm, RFC, fc2_b, h_);
    }
}

// round 10
// speedup vs baseline: 1.0849x; 1.0849x over previous
#include <cuda_runtime.h>
#include <cuda_bf16.h>
#include <math.h>
#include <stdint.h>

// Problem dims (fixed)
#define Dm   1024
#define Hh   16
#define DH   64
#define Rr   32
#define Bb   2
#define Ss   2048
#define BS   (Bb*Ss)        // 4096
#define HR   (Hh*Rr)        // 512
#define Ii   4096
#define RFC  512

// ---------------- scratch ----------------
__device__ float g_x [BS*Dm];
__device__ float g_Pq[BS*HR];
__device__ float g_Pk[BS*HR];
__device__ float g_Pv[BS*HR];
__device__ float g_Q [Bb*Hh*Ss*DH];
__device__ float g_K [Bb*Hh*Ss*DH];
__device__ float g_V [Bb*Hh*DH*Ss];   // V stored TRANSPOSED: [b,h,dh,s]
__device__ float g_Y [BS*Dm];
__device__ float g_t [BS*RFC];
__device__ float g_h [BS*Dm];
__device__ float g_a [BS*Ii];

// ---------------- PTX helpers ----------------
__device__ __forceinline__ void cp16(uint32_t saddr, const void* gptr) {
    // .cg: bypass L1 — staged tiles have no L1 reuse; keep L1 for epilogue reads
    asm volatile("cp.async.cg.shared.global [%0], [%1], 16;" :: "r"(saddr), "l"(gptr));
}
__device__ __forceinline__ uint32_t smem_u32(const void* p) {
    return (uint32_t)__cvta_generic_to_shared(p);
}
__device__ __forceinline__ void ldsm4(uint32_t& r0, uint32_t& r1, uint32_t& r2, uint32_t& r3,
                                      uint32_t addr) {
    asm volatile("ldmatrix.sync.aligned.m8n8.x4.shared.b16 {%0,%1,%2,%3}, [%4];"
                 : "=r"(r0), "=r"(r1), "=r"(r2), "=r"(r3) : "r"(addr));
}
// tf32 mma ignores low 13 mantissa bits: raw fp32 bits are a valid operand.
__device__ __forceinline__ void mma_tf32(float* d, const uint32_t* a, const uint32_t* b) {
    asm volatile(
        "mma.sync.aligned.m16n8k8.row.col.f32.tf32.tf32.f32 "
        "{%0,%1,%2,%3}, {%4,%5,%6,%7}, {%8,%9}, {%0,%1,%2,%3};"
        : "+f"(d[0]), "+f"(d[1]), "+f"(d[2]), "+f"(d[3])
        : "r"(a[0]), "r"(a[1]), "r"(a[2]), "r"(a[3]), "r"(b[0]), "r"(b[1]));
}
__device__ __forceinline__ float gelu_tanh(float x) {
    float u = 0.7978845608f * (x + 0.044715f * x * x * x);
    float t = 1.f - 2.f / (__expf(2.f * u) + 1.f);
    return 0.5f * x * (1.f + t);
}

// ---------------- LayerNorm ----------------
__global__ void ln_kernel(const float* __restrict__ in, const float* __restrict__ w,
                          const float* __restrict__ b, float* __restrict__ out) {
    __shared__ float xs[Dm];
    __shared__ float red[8];
    int row = blockIdx.x;
    int t = threadIdx.x;
    const float* x = in + (size_t)row * Dm;

    float s = 0.f;
    #pragma unroll
    for (int i = t; i < Dm; i += 256) { float v = x[i]; xs[i] = v; s += v; }
    #pragma unroll
    for (int o = 16; o; o >>= 1) s += __shfl_xor_sync(0xffffffffu, s, o);
    if ((t & 31) == 0) red[t >> 5] = s;
    __syncthreads();
    float tot = 0.f;
    #pragma unroll
    for (int i = 0; i < 8; i++) tot += red[i];
    float mean = tot * (1.0f / Dm);
    __syncthreads();

    float vs = 0.f;
    #pragma unroll
    for (int i = t; i < Dm; i += 256) { float d = xs[i] - mean; vs += d * d; }
    #pragma unroll
    for (int o = 16; o; o >>= 1) vs += __shfl_xor_sync(0xffffffffu, vs, o);
    if ((t & 31) == 0) red[t >> 5] = vs;
    __syncthreads();
    float vtot = 0.f;
    #pragma unroll
    for (int i = 0; i < 8; i++) vtot += red[i];
    float rstd = rsqrtf(vtot * (1.0f / Dm) + 1e-5f);

    #pragma unroll
    for (int i = t; i < Dm; i += 256)
        out[(size_t)row * Dm + i] = (xs[i] - mean) * rstd * w[i] + b[i];
}

// ---------------- TF32 GEMM: BK=32, TRUE 3-stage pipeline (1 sync / k-tile) ----------------
#define GEMM_BK 32
#define GEMM_AKp 36
#define GEMM_SMEM(BN) ((3 * 128 * GEMM_AKp + 3 * GEMM_BK * ((BN) + 8)) * 4)

template<int EPI, int BN>
__device__ __forceinline__ void gemm_core(
    const float* __restrict__ A, const float* __restrict__ B, float* __restrict__ C,
    int M, int N, int K, const float* __restrict__ bias, const float* __restrict__ res,
    int m0, int n0)
{
    constexpr int BM = 128, BK = GEMM_BK, AKp = GEMM_AKp, BNp = BN + 8;
    constexpr int WM_ = (BN == 128) ? 2 : 4;
    constexpr int WTM = BM / WM_;
    constexpr int WTN = BN / (8 / WM_);
    constexpr int MT = WTM / 16;
    constexpr int NT = WTN / 8;

    extern __shared__ float smf[];
    float* As = smf;                           // [3][BM][AKp]
    float* Bsm = smf + 3 * BM * AKp;           // [3][BK][BNp]

    int tid = threadIdx.x;
    int w = tid >> 5, lane = tid & 31;
    int lr = lane >> 2, lc = lane & 3;
    int wm = (w % WM_) * WTM;
    int wn = (w / WM_) * WTN;
    int arow_f = (lane & 7) + ((lane >> 3) & 1) * 8;
    int acol_f = (lane >> 4) * 4;

    float acc[MT][NT][4];
    #pragma unroll
    for (int mt = 0; mt < MT; mt++)
        #pragma unroll
        for (int nt = 0; nt < NT; nt++)
            #pragma unroll
            for (int i = 0; i < 4; i++) acc[mt][nt][i] = 0.f;

    const float* Ag = A + (size_t)m0 * K;
    const float* Bg = B + n0;

    auto loadTile = [&](int kt, int buf) {
        int k0 = kt * BK;
        float* Abuf = As + buf * BM * AKp;
        float* Bbuf = Bsm + buf * BK * BNp;
        #pragma unroll
        for (int i = 0; i < 4; i++) {              // A: 128x32 = 1024 cp16
            int q = tid + i * 256;
            int m = q >> 3, c = q & 7;
            cp16(smem_u32(Abuf + m * AKp + c * 4), Ag + (size_t)m * K + k0 + c * 4);
        }
        #pragma unroll
        for (int i = 0; i < BN / 32; i++) {        // B: 32xBN
            int q = tid + i * 256;
            int k = q / (BN / 4), n4 = q % (BN / 4);
            cp16(smem_u32(Bbuf + k * BNp + n4 * 4), Bg + (size_t)(k0 + k) * N + n4 * 4);
        }
        asm volatile("cp.async.commit_group;");
    };

    int NTILES = K / BK;                           // >= 16 for all our GEMMs
    loadTile(0, 0);
    loadTile(1, 1);
    for (int kt = 0; kt < NTILES; kt++) {
        int buf = kt % 3;
        // wait for group kt on this thread, then barrier (all threads' kt done
        // AND all reads of buffer (kt+2)%3 from iteration kt-1 done)
        if (kt + 1 < NTILES) {
            asm volatile("cp.async.wait_group 1;");
        } else {
            asm volatile("cp.async.wait_group 0;");
        }
        __syncthreads();
        if (kt + 2 < NTILES) loadTile(kt + 2, (kt + 2) % 3);

        const float* Abuf = As + buf * BM * AKp;
        const float* Bbuf = Bsm + buf * BK * BNp;

        #pragma unroll
        for (int ks = 0; ks < 4; ks++) {
            int kb = ks * 8;
            uint32_t af[MT][4], bf[NT][2];
            #pragma unroll
            for (int mt = 0; mt < MT; mt++)
                ldsm4(af[mt][0], af[mt][1], af[mt][2], af[mt][3],
                      smem_u32(Abuf + (wm + mt * 16 + arow_f) * AKp + kb + acol_f));
            #pragma unroll
            for (int nt = 0; nt < NT; nt++) {
                int cn = wn + nt * 8 + lr;
                bf[nt][0] = __float_as_uint(Bbuf[(kb + lc) * BNp + cn]);
                bf[nt][1] = __float_as_uint(Bbuf[(kb + lc + 4) * BNp + cn]);
            }
            #pragma unroll
            for (int mt = 0; mt < MT; mt++)
                #pragma unroll
                for (int nt = 0; nt < NT; nt++)
                    mma_tf32(acc[mt][nt], af[mt], bf[nt]);
        }
    }

    #pragma unroll
    for (int mt = 0; mt < MT; mt++) {
        #pragma unroll
        for (int hh = 0; hh < 2; hh++) {
            int row = m0 + wm + mt * 16 + lr + hh * 8;
            #pragma unroll
            for (int nt = 0; nt < NT; nt++) {
                int col = n0 + wn + nt * 8 + 2 * lc;
                float v0 = acc[mt][nt][2 * hh + 0];
                float v1 = acc[mt][nt][2 * hh + 1];
                if (EPI == 1) {
                    v0 += bias[col]     + res[(size_t)row * N + col];
                    v1 += bias[col + 1] + res[(size_t)row * N + col + 1];
                } else if (EPI == 2) {
                    v0 = gelu_tanh(v0 + bias[col]);
                    v1 = gelu_tanh(v1 + bias[col + 1]);
                }
                *(float2*)&C[(size_t)row * N + col] = make_float2(v0, v1);
            }
        }
    }
}

template<int EPI, int BN>
__global__ void __launch_bounds__(256, 2) sgemm_t(
    const float* __restrict__ A, const float* __restrict__ B, float* __restrict__ C,
    int M, int N, int K, const float* __restrict__ bias, const float* __restrict__ res)
{
    gemm_core<EPI, BN>(A, B, C, M, N, K, bias, res, blockIdx.y * 128, blockIdx.x * BN);
}

__global__ void __launch_bounds__(256, 2) sgemm_qkv(
    const float* __restrict__ A,
    const float* __restrict__ B0, const float* __restrict__ B1, const float* __restrict__ B2,
    float* __restrict__ C0, float* __restrict__ C1, float* __restrict__ C2,
    int M, int N, int K)
{
    int sel = blockIdx.x >> 2, nb = blockIdx.x & 3;
    const float* B = (sel == 0) ? B0 : (sel == 1) ? B1 : B2;
    float* C = (sel == 0) ? C0 : (sel == 1) ? C1 : C2;
    gemm_core<0, 128>(A, B, C, M, N, K, nullptr, nullptr, blockIdx.y * 128, nb * 128);
}

// ---------------- head_proj: q,k -> (b,h,s,e); v -> TRANSPOSED (b,h,e,s) ----------------
__global__ void __launch_bounds__(256) head_proj2(
    const float* __restrict__ Pq, const float* __restrict__ Pk, const float* __restrict__ Pv,
    const float* __restrict__ Vq, const float* __restrict__ Vk, const float* __restrict__ Vv,
    const float* __restrict__ bq, const float* __restrict__ bk, const float* __restrict__ bv,
    float* __restrict__ Oq, float* __restrict__ Ok, float* __restrict__ Ov)
{
    __shared__ float vw[Rr][DH];
    __shared__ float pt[64][Rr + 1];
    int z = blockIdx.z;
    const float* P  = (z == 0) ? Pq : (z == 1) ? Pk : Pv;
    const float* Vw = (z == 0) ? Vq : (z == 1) ? Vk : Vv;
    const float* bi = (z == 0) ? bq : (z == 1) ? bk : bv;
    float* O        = (z == 0) ? Oq : (z == 1) ? Ok : Ov;

    int h = blockIdx.y;
    int s0 = blockIdx.x * 64;
    int tid = threadIdx.x;

    #pragma unroll
    for (int i = 0; i < 8; i++) {
        int idx = tid + i * 256;
        vw[idx >> 6][idx & 63] = Vw[(size_t)h * Rr * DH + idx];
    }
    #pragma unroll
    for (int i = 0; i < 8; i++) {
        int idx = tid + i * 256;
        int r = idx >> 5, c = idx & 31;
        pt[r][c] = P[(size_t)(s0 + r) * HR + h * Rr + c];
    }
    __syncthreads();

    if (z < 2) {
        int e = tid & 63;
        int sl = tid >> 6;
        float bv_ = bi[h * DH + e];
        #pragma unroll
        for (int i = 0; i < 16; i++) {
            int r = sl + i * 4;
            float acc = bv_;
            #pragma unroll
            for (int rr = 0; rr < Rr; rr++) acc = fmaf(pt[r][rr], vw[rr][e], acc);
            int bs = s0 + r;
            int b = bs >> 11, s = bs & 2047;
            O[(((size_t)(b * Hh + h)) * Ss + s) * DH + e] = acc;
        }
    } else {
        int sl = tid & 63;
        int e0 = tid >> 6;
        int bs = s0 + sl;
        int b = bs >> 11, s = bs & 2047;
        float* obase = O + ((size_t)(b * Hh + h)) * DH * Ss + s;
        #pragma unroll
        for (int i = 0; i < 16; i++) {
            int e = e0 + i * 4;
            float acc = bi[h * DH + e];
            #pragma unroll
            for (int rr = 0; rr < Rr; rr++) acc = fmaf(pt[sl][rr], vw[rr][e], acc);
            obase[(size_t)e * Ss] = acc;
        }
    }
}

// ---------------- attention: R7 winner, unchanged ----------------
#define ASd 68
#define ATTN_SMEM ((64 * ASd + 64 * ASd + 128 * ASd) * 4)   // 69632 B

__global__ void __launch_bounds__(256, 2) attn_mma4(
    const float* __restrict__ Q, const float* __restrict__ K,
    const float* __restrict__ V, float* __restrict__ Y)
{
    extern __shared__ uint32_t sm[];
    uint32_t* Ks = sm;                    // [64][ASd]
    uint32_t* Vt = sm + 64 * ASd;         // [64][ASd]  (V transposed: [dh][s])
    uint32_t* Ps = sm + 128 * ASd;        // [128][ASd]

    int bh = blockIdx.y;
    int qblk = gridDim.x - 1 - blockIdx.x;   // heavy blocks first
    int q0 = qblk * 128;
    int tid = threadIdx.x;
    int w = tid >> 5, lane = tid & 31;
    int lr = lane >> 2, lc = lane & 3;
    int wq = w * 16;
    int frow = (lane & 7) + ((lane >> 3) & 1) * 8;
    int fcol = (lane >> 4) * 4;
    int brow = lane & 7;
    int bcol = (lane >> 3) * 4;

    uint32_t qf[8][4];
    const float* Qb = Q + ((size_t)bh * Ss + q0 + wq) * DH;
    #pragma unroll
    for (int ks = 0; ks < 8; ks++) {
        qf[ks][0] = __float_as_uint(Qb[(size_t)lr * DH + ks * 8 + lc]);
        qf[ks][1] = __float_as_uint(Qb[(size_t)(lr + 8) * DH + ks * 8 + lc]);
        qf[ks][2] = __float_as_uint(Qb[(size_t)lr * DH + ks * 8 + lc + 4]);
        qf[ks][3] = __float_as_uint(Qb[(size_t)(lr + 8) * DH + ks * 8 + lc + 4]);
    }

    const float* Kg = K + (size_t)bh * Ss * DH;
    const float* Vg = V + (size_t)bh * DH * Ss;

    float o[8][4];
    #pragma unroll
    for (int nt = 0; nt < 8; nt++)
        #pragma unroll
        for (int i = 0; i < 4; i++) o[nt][i] = 0.f;
    float m0 = -1e30f, m1 = -1e30f, l0 = 0.f, l1 = 0.f;
    const float scale = 0.125f;

    int ktmax = 2 * qblk + 1;
    for (int kt = 0; kt <= ktmax; kt++) {
        __syncthreads();
        #pragma unroll
        for (int i = 0; i < 4; i++) {
            int idx = tid + i * 256;
            int r = idx >> 4, c4 = (idx & 15) * 4;
            cp16(smem_u32(Ks + r * ASd + c4), Kg + (size_t)(kt * 64 + r) * DH + c4);
            cp16(smem_u32(Vt + r * ASd + c4), Vg + (size_t)r * Ss + kt * 64 + c4);
        }
        asm volatile("cp.async.commit_group;");
        asm volatile("cp.async.wait_group 0;");
        __syncthreads();

        float s[8][4];
        #pragma unroll
        for (int nt = 0; nt < 8; nt++)
            #pragma unroll
            for (int i = 0; i < 4; i++) s[nt][i] = 0.f;
        #pragma unroll
        for (int k2 = 0; k2 < 4; k2++) {
            #pragma unroll
            for (int nt = 0; nt < 8; nt++) {
                uint32_t b0, b1, b2, b3;
                ldsm4(b0, b1, b2, b3,
                      smem_u32(Ks + (nt * 8 + brow) * ASd + k2 * 16 + bcol));
                uint32_t bfa[2] = {b0, b1}, bfb[2] = {b2, b3};
                mma_tf32(s[nt], qf[2 * k2],     bfa);
                mma_tf32(s[nt], qf[2 * k2 + 1], bfb);
            }
        }

        bool diag = (kt >= 2 * qblk);
        int r0 = q0 + wq + lr, r1 = r0 + 8;
        int kc0 = kt * 64;
        #pragma unroll
        for (int nt = 0; nt < 8; nt++) {
            int c0 = kc0 + nt * 8 + 2 * lc, c1 = c0 + 1;
            s[nt][0] = (diag && c0 > r0) ? -1e30f : s[nt][0] * scale;
            s[nt][1] = (diag && c1 > r0) ? -1e30f : s[nt][1] * scale;
            s[nt][2] = (diag && c0 > r1) ? -1e30f : s[nt][2] * scale;
            s[nt][3] = (diag && c1 > r1) ? -1e30f : s[nt][3] * scale;
        }

        float mx0 = -1e30f, mx1 = -1e30f;
        #pragma unroll
        for (int nt = 0; nt < 8; nt++) {
            mx0 = fmaxf(mx0, fmaxf(s[nt][0], s[nt][1]));
            mx1 = fmaxf(mx1, fmaxf(s[nt][2], s[nt][3]));
        }
        mx0 = fmaxf(mx0, __shfl_xor_sync(0xffffffffu, mx0, 1));
        mx0 = fmaxf(mx0, __shfl_xor_sync(0xffffffffu, mx0, 2));
        mx1 = fmaxf(mx1, __shfl_xor_sync(0xffffffffu, mx1, 1));
        mx1 = fmaxf(mx1, __shfl_xor_sync(0xffffffffu, mx1, 2));
        float mn0 = fmaxf(m0, mx0), mn1 = fmaxf(m1, mx1);
        float c0f = __expf(m0 - mn0), c1f = __expf(m1 - mn1);
        l0 *= c0f; l1 *= c1f;
        #pragma unroll
        for (int nt = 0; nt < 8; nt++) {
            o[nt][0] *= c0f; o[nt][1] *= c0f;
            o[nt][2] *= c1f; o[nt][3] *= c1f;
        }
        m0 = mn0; m1 = mn1;

        #pragma unroll
        for (int nt = 0; nt < 8; nt++) {
            int c0 = nt * 8 + 2 * lc;
            float p00 = __expf(s[nt][0] - mn0);
            float p01 = __expf(s[nt][1] - mn0);
            float p10 = __expf(s[nt][2] - mn1);
            float p11 = __expf(s[nt][3] - mn1);
            l0 += p00 + p01; l1 += p10 + p11;
            Ps[(wq + lr) * ASd + c0]         = __float_as_uint(p00);
            Ps[(wq + lr) * ASd + c0 + 1]     = __float_as_uint(p01);
            Ps[(wq + lr + 8) * ASd + c0]     = __float_as_uint(p10);
            Ps[(wq + lr + 8) * ASd + c0 + 1] = __float_as_uint(p11);
        }
        __syncwarp();

        #pragma unroll
        for (int k2 = 0; k2 < 4; k2++) {
            uint32_t paA[4], paB[4];
            ldsm4(paA[0], paA[1], paA[2], paA[3],
                  smem_u32(Ps + (wq + frow) * ASd + (2 * k2) * 8 + fcol));
            ldsm4(paB[0], paB[1], paB[2], paB[3],
                  smem_u32(Ps + (wq + frow) * ASd + (2 * k2 + 1) * 8 + fcol));
            #pragma unroll
            for (int nt = 0; nt < 8; nt++) {
                uint32_t b0, b1, b2, b3;
                ldsm4(b0, b1, b2, b3,
                      smem_u32(Vt + (nt * 8 + brow) * ASd + k2 * 16 + bcol));
                uint32_t bfa[2] = {b0, b1}, bfb[2] = {b2, b3};
                mma_tf32(o[nt], paA, bfa);
                mma_tf32(o[nt], paB, bfb);
            }
        }
    }

    l0 += __shfl_xor_sync(0xffffffffu, l0, 1);
    l0 += __shfl_xor_sync(0xffffffffu, l0, 2);
    l1 += __shfl_xor_sync(0xffffffffu, l1, 1);
    l1 += __shfl_xor_sync(0xffffffffu, l1, 2);
    float i0 = 1.f / l0, i1 = 1.f / l1;
    int b = bh >> 4, h = bh & 15;
    int row0 = q0 + wq + lr, row1 = row0 + 8;
    float* y0 = Y + (((size_t)(b * Ss + row0)) * Hh + h) * DH;
    float* y1 = Y + (((size_t)(b * Ss + row1)) * Hh + h) * DH;
    #pragma unroll
    for (int nt = 0; nt < 8; nt++) {
        int c = nt * 8 + 2 * lc;
        *(float2*)(y0 + c) = make_float2(o[nt][0] * i0, o[nt][1] * i0);
        *(float2*)(y1 + c) = make_float2(o[nt][2] * i1, o[nt][3] * i1);
    }
}

// ---------------- launch ----------------
extern "C" void kernel_launch(void* const* d_in, const int* in_sizes, int n_in,
                              void* d_out, int out_size) {
    const float* hidden = (const float*)d_in[0];
    const float* ln1_w = (const float*)d_in[2];
    const float* ln1_b = (const float*)d_in[3];
    const float* q_U = (const float*)d_in[4];
    const float* q_V = (const float*)d_in[5];
    const float* q_b = (const float*)d_in[6];
    const float* k_U = (const float*)d_in[7];
    const float* k_V = (const float*)d_in[8];
    const float* k_b = (const float*)d_in[9];
    const float* v_U = (const float*)d_in[10];
    const float* v_V = (const float*)d_in[11];
    const float* v_b = (const float*)d_in[12];
    const float* out_U = (const float*)d_in[13];
    const float* out_V = (const float*)d_in[14];
    const float* out_b = (const float*)d_in[15];
    const float* ln2_w = (const float*)d_in[16];
    const float* ln2_b = (const float*)d_in[17];
    const float* fc1_U = (const float*)d_in[18];
    const float* fc1_V = (const float*)d_in[19];
    const float* fc1_b = (const float*)d_in[20];
    const float* fc2_U = (const float*)d_in[21];
    const float* fc2_V = (const float*)d_in[22];
    const float* fc2_b = (const float*)d_in[23];
    float* out = (float*)d_out;

    float *x_, *Pq_, *Pk_, *Pv_, *Q_, *K_, *V_, *Y_, *t_, *h_, *a_;
    cudaGetSymbolAddress((void**)&x_,  g_x);
    cudaGetSymbolAddress((void**)&Pq_, g_Pq);
    cudaGetSymbolAddress((void**)&Pk_, g_Pk);
    cudaGetSymbolAddress((void**)&Pv_, g_Pv);
    cudaGetSymbolAddress((void**)&Q_,  g_Q);
    cudaGetSymbolAddress((void**)&K_,  g_K);
    cudaGetSymbolAddress((void**)&V_,  g_V);
    cudaGetSymbolAddress((void**)&Y_,  g_Y);
    cudaGetSymbolAddress((void**)&t_,  g_t);
    cudaGetSymbolAddress((void**)&h_,  g_h);
    cudaGetSymbolAddress((void**)&a_,  g_a);

    cudaFuncSetAttribute(attn_mma4, cudaFuncAttributeMaxDynamicSharedMemorySize, ATTN_SMEM);
    cudaFuncSetAttribute(sgemm_qkv, cudaFuncAttributeMaxDynamicSharedMemorySize, GEMM_SMEM(128));
    cudaFuncSetAttribute(sgemm_t<0, 64>,  cudaFuncAttributeMaxDynamicSharedMemorySize, GEMM_SMEM(64));
    cudaFuncSetAttribute(sgemm_t<1, 128>, cudaFuncAttributeMaxDynamicSharedMemorySize, GEMM_SMEM(128));
    cudaFuncSetAttribute(sgemm_t<2, 128>, cudaFuncAttributeMaxDynamicSharedMemorySize, GEMM_SMEM(128));

    // 1) x = LN1(hidden)
    ln_kernel<<<BS, 256>>>(hidden, ln1_w, ln1_b, x_);

    // 2) Pq/Pk/Pv = x @ {q,k,v}_U
    {
        dim3 g(12, BS / 128);
        sgemm_qkv<<<g, 256, GEMM_SMEM(128)>>>(x_, q_U, k_U, v_U, Pq_, Pk_, Pv_, BS, HR, Dm);
    }

    // 3) head expansion (V transposed)
    {
        dim3 g(BS / 64, Hh, 3);
        head_proj2<<<g, 256>>>(Pq_, Pk_, Pv_, q_V, k_V, v_V, q_b, k_b, v_b, Q_, K_, V_);
    }

    // 4) causal attention
    {
        dim3 g(Ss / 128, Bb * Hh);
        attn_mma4<<<g, 256, ATTN_SMEM>>>(Q_, K_, V_, Y_);
    }

    // 5) h = hidden + (Y @ out_U) @ out_V + out_b
    {
        dim3 g1(RFC / 64, BS / 128);
        sgemm_t<0, 64><<<g1, 256, GEMM_SMEM(64)>>>(Y_, out_U, t_, BS, RFC, Dm, nullptr, nullptr);
        dim3 g2(Dm / 128, BS / 128);
        sgemm_t<1, 128><<<g2, 256, GEMM_SMEM(128)>>>(t_, out_V, h_, BS, Dm, RFC, out_b, hidden);
    }

    // 6) z = LN2(h)
    ln_kernel<<<BS, 256>>>(h_, ln2_w, ln2_b, x_);

    // 7) a = gelu((z @ fc1_U) @ fc1_V + fc1_b)
    {
        dim3 g1(RFC / 64, BS / 128);
        sgemm_t<0, 64><<<g1, 256, GEMM_SMEM(64)>>>(x_, fc1_U, t_, BS, RFC, Dm, nullptr, nullptr);
        dim3 g2(Ii / 128, BS / 128);
        sgemm_t<2, 128><<<g2, 256, GEMM_SMEM(128)>>>(t_, fc1_V, a_, BS, Ii, RFC, fc1_b, nullptr);
    }

    // 8) out = h + (a @ fc2_U) @ fc2_V + fc2_b
    {
        dim3 g1(RFC / 64, BS / 128);
        sgemm_t<0, 64><<<g1, 256, GEMM_SMEM(64)>>>(a_, fc2_U, t_, BS, RFC, Ii, nullptr, nullptr);
        dim3 g2(Dm / 128, BS / 128);
        sgemm_t<1, 128><<<g2, 256, GEMM_SMEM(128)>>>(t_, fc2_V, out, BS, Dm, RFC, fc2_b, h_);
    }
}

// round 11
// speedup vs baseline: 1.6503x; 1.5211x over previous
#include <cuda_runtime.h>
#include <cuda_fp16.h>
#include <math.h>
#include <stdint.h>

// Problem dims (fixed)
#define Dm   1024
#define Hh   16
#define DH   64
#define Rr   32
#define Bb   2
#define Ss   2048
#define BS   (Bb*Ss)        // 4096
#define HR   (Hh*Rr)        // 512
#define Ii   4096
#define RFC  512

// ---------------- scratch ----------------
__device__ __half g_x16[BS*Dm];            // LN out (fp16), reused for z
__device__ float  g_Pq[BS*HR];
__device__ float  g_Pk[BS*HR];
__device__ float  g_Pv[BS*HR];
__device__ __half g_Q16[Bb*Hh*Ss*DH];
__device__ __half g_K16[Bb*Hh*Ss*DH];
__device__ __half g_V16[Bb*Hh*DH*Ss];      // V TRANSPOSED: [b,h,dh,s]
__device__ __half g_Y16[BS*Dm];
__device__ __half g_t16[BS*RFC];
__device__ float  g_h  [BS*Dm];
__device__ __half g_a16[BS*Ii];
__device__ __half g_w16[7864320];          // fp16 weights, TRANSPOSED [N][K]

// transposed-weight offsets (halves)
#define WT_QU   0
#define WT_KU   524288
#define WT_VU   1048576
#define WT_OU   1572864
#define WT_OV   2097152
#define WT_F1U  2621440
#define WT_F1V  3145728
#define WT_F2U  5242880
#define WT_F2V  7340032

// ---------------- PTX helpers ----------------
__device__ __forceinline__ void cp16(uint32_t saddr, const void* gptr) {
    asm volatile("cp.async.cg.shared.global [%0], [%1], 16;" :: "r"(saddr), "l"(gptr));
}
__device__ __forceinline__ uint32_t smem_u32(const void* p) {
    return (uint32_t)__cvta_generic_to_shared(p);
}
__device__ __forceinline__ void ldsm4(uint32_t& r0, uint32_t& r1, uint32_t& r2, uint32_t& r3,
                                      uint32_t addr) {
    asm volatile("ldmatrix.sync.aligned.m8n8.x4.shared.b16 {%0,%1,%2,%3}, [%4];"
                 : "=r"(r0), "=r"(r1), "=r"(r2), "=r"(r3) : "r"(addr));
}
__device__ __forceinline__ void mma_f16(float* d, const uint32_t* a, uint32_t b0, uint32_t b1) {
    asm volatile(
        "mma.sync.aligned.m16n8k16.row.col.f32.f16.f16.f32 "
        "{%0,%1,%2,%3}, {%4,%5,%6,%7}, {%8,%9}, {%0,%1,%2,%3};"
        : "+f"(d[0]), "+f"(d[1]), "+f"(d[2]), "+f"(d[3])
        : "r"(a[0]), "r"(a[1]), "r"(a[2]), "r"(a[3]), "r"(b0), "r"(b1));
}
__device__ __forceinline__ uint32_t packh2(float a, float b) {
    __half2 h = __floats2half2_rn(a, b);
    return *(uint32_t*)&h;
}
__device__ __forceinline__ float gelu_tanh(float x) {
    float u = 0.7978845608f * (x + 0.044715f * x * x * x);
    float t = 1.f - 2.f / (__expf(2.f * u) + 1.f);
    return 0.5f * x * (1.f + t);
}

// ---------------- weight convert + transpose: fp32 [K][N] -> fp16 [N][K] ----------------
__global__ void __launch_bounds__(256) conv_w(
    const float* s0, const float* s1, const float* s2, const float* s3, const float* s4,
    const float* s5, const float* s6, const float* s7, const float* s8, __half* dst)
{
    const int Ksz[9]  = {1024,1024,1024,1024,512,1024,512,4096,512};
    const int Nsz[9]  = {512,512,512,512,1024,512,4096,512,1024};
    const int toff[9] = {0,512,1024,1536,2048,2560,3072,5120,7168};
    const int doff[9] = {WT_QU,WT_KU,WT_VU,WT_OU,WT_OV,WT_F1U,WT_F1V,WT_F2U,WT_F2V};
    int bx = blockIdx.x;
    int i = 0;
    #pragma unroll
    for (int j = 1; j < 9; j++) if (bx >= toff[j]) i = j;
    const float* src = (i==0)?s0:(i==1)?s1:(i==2)?s2:(i==3)?s3:(i==4)?s4:(i==5)?s5:(i==6)?s6:(i==7)?s7:s8;
    int local = bx - toff[i];
    int K = Ksz[i], N = Nsz[i];
    int ntile = N >> 5;
    int tk = local / ntile, tn = local % ntile;

    __shared__ float tsm[32][33];
    int cc = threadIdx.x & 31, r0 = threadIdx.x >> 5;
    #pragma unroll
    for (int j = 0; j < 4; j++) {
        int r = r0 + j * 8;
        tsm[r][cc] = src[(size_t)(tk * 32 + r) * N + tn * 32 + cc];
    }
    __syncthreads();
    __half* d = dst + doff[i];
    #pragma unroll
    for (int j = 0; j < 4; j++) {
        int r = r0 + j * 8;
        d[(size_t)(tn * 32 + r) * K + tk * 32 + cc] = __float2half(tsm[cc][r]);
    }
}

// ---------------- LayerNorm (fp32 in, fp16 out) ----------------
__global__ void ln_kernel(const float* __restrict__ in, const float* __restrict__ w,
                          const float* __restrict__ b, __half* __restrict__ out) {
    __shared__ float xs[Dm];
    __shared__ float red[8];
    int row = blockIdx.x;
    int t = threadIdx.x;
    const float* x = in + (size_t)row * Dm;

    float s = 0.f;
    #pragma unroll
    for (int i = t; i < Dm; i += 256) { float v = x[i]; xs[i] = v; s += v; }
    #pragma unroll
    for (int o = 16; o; o >>= 1) s += __shfl_xor_sync(0xffffffffu, s, o);
    if ((t & 31) == 0) red[t >> 5] = s;
    __syncthreads();
    float tot = 0.f;
    #pragma unroll
    for (int i = 0; i < 8; i++) tot += red[i];
    float mean = tot * (1.0f / Dm);
    __syncthreads();

    float vs = 0.f;
    #pragma unroll
    for (int i = t; i < Dm; i += 256) { float d = xs[i] - mean; vs += d * d; }
    #pragma unroll
    for (int o = 16; o; o >>= 1) vs += __shfl_xor_sync(0xffffffffu, vs, o);
    if ((t & 31) == 0) red[t >> 5] = vs;
    __syncthreads();
    float vtot = 0.f;
    #pragma unroll
    for (int i = 0; i < 8; i++) vtot += red[i];
    float rstd = rsqrtf(vtot * (1.0f / Dm) + 1e-5f);

    #pragma unroll
    for (int i = t; i < Dm; i += 256)
        out[(size_t)row * Dm + i] = __float2half((xs[i] - mean) * rstd * w[i] + b[i]);
}

// ---------------- FP16 GEMM: A[M][K] fp16 row-major, Bt[N][K] fp16, fp32 accum ----------------
// EPI: 0 = fp32 out plain; 1 = fp32 out + bias + res; 2 = fp16 out gelu(v+bias); 3 = fp16 out plain
#define BKh 64
#define AKp 72
#define GEMM16_SMEM(BN) ((2 * 128 * AKp + 2 * (BN) * AKp) * 2)

template<int EPI, int BN>
__device__ __forceinline__ void gemm16_core(
    const __half* __restrict__ A, const __half* __restrict__ Bt, void* __restrict__ Cv,
    int M, int N, int K, const float* __restrict__ bias, const float* __restrict__ res,
    int m0, int n0)
{
    constexpr int BM = 128;
    constexpr int WM_ = (BN == 128) ? 2 : 4;
    constexpr int WTM = BM / WM_;            // 64 or 32
    constexpr int MT = WTM / 16;             // 4 or 2
    constexpr int NT = 4;                    // 32 cols / 8

    extern __shared__ __half smh[];
    __half* As = smh;                        // [2][128][AKp]
    __half* Bs = smh + 2 * BM * AKp;         // [2][BN][AKp]

    int tid = threadIdx.x;
    int w = tid >> 5, lane = tid & 31;
    int lr = lane >> 2, lc = lane & 3;
    int wm = (w % WM_) * WTM;
    int wn = (w / WM_) * 32;
    int fr = lane & 15;                      // ldsm row-in-16
    int fcsel = (lane >> 4) * 8;             // ldsm k-chunk (halves)

    float acc[MT][NT][4];
    #pragma unroll
    for (int mt = 0; mt < MT; mt++)
        #pragma unroll
        for (int nt = 0; nt < NT; nt++)
            #pragma unroll
            for (int i = 0; i < 4; i++) acc[mt][nt][i] = 0.f;

    const __half* Ag = A + (size_t)m0 * K;
    const __half* Bg = Bt + (size_t)n0 * K;

    auto loadTile = [&](int kt, int buf) {
        __half* Abuf = As + buf * BM * AKp;
        __half* Bbuf = Bs + buf * BN * AKp;
        #pragma unroll
        for (int i = 0; i < 4; i++) {              // A: 128 rows x 128B = 1024 chunks
            int q = tid + i * 256;
            int r = q >> 3, c = q & 7;
            cp16(smem_u32(Abuf + r * AKp + c * 8), Ag + (size_t)r * K + kt * BKh + c * 8);
        }
        #pragma unroll
        for (int i = 0; i < BN / 32; i++) {        // B: BN rows x 128B
            int q = tid + i * 256;
            int r = q >> 3, c = q & 7;
            cp16(smem_u32(Bbuf + r * AKp + c * 8), Bg + (size_t)r * K + kt * BKh + c * 8);
        }
        asm volatile("cp.async.commit_group;");
    };

    int NTILES = K / BKh;
    loadTile(0, 0);
    for (int kt = 0; kt < NTILES; kt++) {
        int buf = kt & 1;
        if (kt + 1 < NTILES) {
            loadTile(kt + 1, buf ^ 1);
            asm volatile("cp.async.wait_group 1;");
        } else {
            asm volatile("cp.async.wait_group 0;");
        }
        __syncthreads();
        const __half* Abuf = As + buf * BM * AKp;
        const __half* Bbuf = Bs + buf * BN * AKp;

        #pragma unroll
        for (int ks = 0; ks < 4; ks++) {
            int kb = ks * 16;
            uint32_t af[MT][4], bf[NT][2];
            #pragma unroll
            for (int mt = 0; mt < MT; mt++)
                ldsm4(af[mt][0], af[mt][1], af[mt][2], af[mt][3],
                      smem_u32(Abuf + (wm + mt * 16 + fr) * AKp + kb + fcsel));
            #pragma unroll
            for (int ntp = 0; ntp < 2; ntp++) {
                uint32_t r0, r1, r2, r3;
                ldsm4(r0, r1, r2, r3,
                      smem_u32(Bbuf + (wn + ntp * 16 + fr) * AKp + kb + fcsel));
                bf[2 * ntp][0] = r0; bf[2 * ntp][1] = r2;
                bf[2 * ntp + 1][0] = r1; bf[2 * ntp + 1][1] = r3;
            }
            #pragma unroll
            for (int mt = 0; mt < MT; mt++)
                #pragma unroll
                for (int nt = 0; nt < NT; nt++)
                    mma_f16(acc[mt][nt], af[mt], bf[nt][0], bf[nt][1]);
        }
        __syncthreads();
    }

    #pragma unroll
    for (int mt = 0; mt < MT; mt++) {
        #pragma unroll
        for (int hh = 0; hh < 2; hh++) {
            int row = m0 + wm + mt * 16 + lr + hh * 8;
            #pragma unroll
            for (int nt = 0; nt < NT; nt++) {
                int col = n0 + wn + nt * 8 + 2 * lc;
                float v0 = acc[mt][nt][2 * hh + 0];
                float v1 = acc[mt][nt][2 * hh + 1];
                if (EPI == 0) {
                    *(float2*)&((float*)Cv)[(size_t)row * N + col] = make_float2(v0, v1);
                } else if (EPI == 1) {
                    const float* rr = res + (size_t)row * N + col;
                    v0 += bias[col] + rr[0];
                    v1 += bias[col + 1] + rr[1];
                    *(float2*)&((float*)Cv)[(size_t)row * N + col] = make_float2(v0, v1);
                } else if (EPI == 2) {
                    v0 = gelu_tanh(v0 + bias[col]);
                    v1 = gelu_tanh(v1 + bias[col + 1]);
                    *(uint32_t*)&((__half*)Cv)[(size_t)row * N + col] = packh2(v0, v1);
                } else {
                    *(uint32_t*)&((__half*)Cv)[(size_t)row * N + col] = packh2(v0, v1);
                }
            }
        }
    }
}

template<int EPI, int BN>
__global__ void __launch_bounds__(256, 2) gemm16(
    const __half* __restrict__ A, const __half* __restrict__ Bt, void* __restrict__ C,
    int M, int N, int K, const float* __restrict__ bias, const float* __restrict__ res)
{
    gemm16_core<EPI, BN>(A, Bt, C, M, N, K, bias, res, blockIdx.y * 128, blockIdx.x * BN);
}

__global__ void __launch_bounds__(256, 2) gemm16_qkv(
    const __half* __restrict__ A, const __half* __restrict__ wt,
    float* __restrict__ C0, float* __restrict__ C1, float* __restrict__ C2)
{
    int sel = blockIdx.x >> 2, nb = blockIdx.x & 3;
    const __half* Bt = wt + (sel == 0 ? WT_QU : sel == 1 ? WT_KU : WT_VU);
    float* C = (sel == 0) ? C0 : (sel == 1) ? C1 : C2;
    gemm16_core<0, 128>(A, Bt, C, BS, HR, Dm, nullptr, nullptr, blockIdx.y * 128, nb * 128);
}

// ---------------- head_proj: fp32 P -> fp16 Q,K (b,h,s,e); V TRANSPOSED (b,h,e,s) ----------------
__global__ void __launch_bounds__(256) head_proj2(
    const float* __restrict__ Pq, const float* __restrict__ Pk, const float* __restrict__ Pv,
    const float* __restrict__ Vq, const float* __restrict__ Vk, const float* __restrict__ Vv,
    const float* __restrict__ bq, const float* __restrict__ bk, const float* __restrict__ bv,
    __half* __restrict__ Oq, __half* __restrict__ Ok, __half* __restrict__ Ov)
{
    __shared__ float vw[Rr][DH];
    __shared__ float pt[64][Rr + 1];
    int z = blockIdx.z;
    const float* P  = (z == 0) ? Pq : (z == 1) ? Pk : Pv;
    const float* Vw = (z == 0) ? Vq : (z == 1) ? Vk : Vv;
    const float* bi = (z == 0) ? bq : (z == 1) ? bk : bv;
    __half* O       = (z == 0) ? Oq : (z == 1) ? Ok : Ov;

    int h = blockIdx.y;
    int s0 = blockIdx.x * 64;
    int tid = threadIdx.x;

    #pragma unroll
    for (int i = 0; i < 8; i++) {
        int idx = tid + i * 256;
        vw[idx >> 6][idx & 63] = Vw[(size_t)h * Rr * DH + idx];
    }
    #pragma unroll
    for (int i = 0; i < 8; i++) {
        int idx = tid + i * 256;
        int r = idx >> 5, c = idx & 31;
        pt[r][c] = P[(size_t)(s0 + r) * HR + h * Rr + c];
    }
    __syncthreads();

    if (z < 2) {
        int e = tid & 63;
        int sl = tid >> 6;
        float bv_ = bi[h * DH + e];
        #pragma unroll
        for (int i = 0; i < 16; i++) {
            int r = sl + i * 4;
            float acc = bv_;
            #pragma unroll
            for (int rr = 0; rr < Rr; rr++) acc = fmaf(pt[r][rr], vw[rr][e], acc);
            int bs = s0 + r;
            int b = bs >> 11, s = bs & 2047;
            O[(((size_t)(b * Hh + h)) * Ss + s) * DH + e] = __float2half(acc);
        }
    } else {
        int sl = tid & 63;
        int e0 = tid >> 6;
        int bs = s0 + sl;
        int b = bs >> 11, s = bs & 2047;
        __half* obase = O + ((size_t)(b * Hh + h)) * DH * Ss + s;
        #pragma unroll
        for (int i = 0; i < 16; i++) {
            int e = e0 + i * 4;
            float acc = bi[h * DH + e];
            #pragma unroll
            for (int rr = 0; rr < Rr; rr++) acc = fmaf(pt[sl][rr], vw[rr][e], acc);
            obase[(size_t)e * Ss] = __float2half(acc);
        }
    }
}

// ---------------- FP16 causal flash attention: 128 q/CTA, 8 warps ----------------
#define APd 72    // padded row stride (halves): 144B -> ldsm conflict-free

__global__ void __launch_bounds__(256, 2) attn_f16(
    const __half* __restrict__ Q, const __half* __restrict__ K,
    const __half* __restrict__ V, __half* __restrict__ Y)
{
    __shared__ __half Ks[64 * APd];     //  9216 B
    __shared__ __half Vt[64 * APd];     //  9216 B
    __shared__ __half Ps[128 * APd];    // 18432 B

    int bh = blockIdx.y;
    int qblk = gridDim.x - 1 - blockIdx.x;   // heavy blocks first
    int q0 = qblk * 128;
    int tid = threadIdx.x;
    int w = tid >> 5, lane = tid & 31;
    int lr = lane >> 2, lc = lane & 3;
    int wq = w * 16;
    int fr = lane & 15;
    int fcsel = (lane >> 4) * 8;

    // persistent Q fragments (fp16): 4 k16-steps x 4 regs
    uint32_t qf[4][4];
    const __half* Qb = Q + ((size_t)bh * Ss + q0 + wq) * DH;
    #pragma unroll
    for (int ks = 0; ks < 4; ks++) {
        qf[ks][0] = *(const uint32_t*)(Qb + (size_t)lr * DH + ks * 16 + 2 * lc);
        qf[ks][1] = *(const uint32_t*)(Qb + (size_t)(lr + 8) * DH + ks * 16 + 2 * lc);
        qf[ks][2] = *(const uint32_t*)(Qb + (size_t)lr * DH + ks * 16 + 8 + 2 * lc);
        qf[ks][3] = *(const uint32_t*)(Qb + (size_t)(lr + 8) * DH + ks * 16 + 8 + 2 * lc);
    }

    const __half* Kg = K + (size_t)bh * Ss * DH;
    const __half* Vg = V + (size_t)bh * DH * Ss;

    float o[8][4];
    #pragma unroll
    for (int nt = 0; nt < 8; nt++)
        #pragma unroll
        for (int i = 0; i < 4; i++) o[nt][i] = 0.f;
    float m0 = -1e30f, m1 = -1e30f, l0 = 0.f, l1 = 0.f;
    const float scale = 0.125f;

    int ktmax = 2 * qblk + 1;
    for (int kt = 0; kt <= ktmax; kt++) {
        __syncthreads();                      // prior tile fully consumed
        #pragma unroll
        for (int i = 0; i < 2; i++) {         // K tile: 512 chunks
            int idx = tid + i * 256;
            int r = idx >> 3, c = idx & 7;
            cp16(smem_u32(Ks + r * APd + c * 8), Kg + (size_t)(kt * 64 + r) * DH + c * 8);
        }
        #pragma unroll
        for (int i = 0; i < 2; i++) {         // V tile: 512 chunks
            int idx = tid + i * 256;
            int r = idx >> 3, c = idx & 7;
            cp16(smem_u32(Vt + r * APd + c * 8), Vg + (size_t)r * Ss + kt * 64 + c * 8);
        }
        asm volatile("cp.async.commit_group;");
        asm volatile("cp.async.wait_group 0;");
        __syncthreads();

        // S = Q @ K^T (per warp 16x64)
        float s[8][4];
        #pragma unroll
        for (int nt = 0; nt < 8; nt++)
            #pragma unroll
            for (int i = 0; i < 4; i++) s[nt][i] = 0.f;
        #pragma unroll
        for (int ks = 0; ks < 4; ks++) {
            #pragma unroll
            for (int ntp = 0; ntp < 4; ntp++) {
                uint32_t r0, r1, r2, r3;
                ldsm4(r0, r1, r2, r3,
                      smem_u32(Ks + (ntp * 16 + fr) * APd + ks * 16 + fcsel));
                mma_f16(s[2 * ntp],     qf[ks], r0, r2);
                mma_f16(s[2 * ntp + 1], qf[ks], r1, r3);
            }
        }

        // scale + causal mask
        bool diag = (kt >= 2 * qblk);
        int r0_ = q0 + wq + lr, r1_ = r0_ + 8;
        int kc0 = kt * 64;
        #pragma unroll
        for (int nt = 0; nt < 8; nt++) {
            int c0 = kc0 + nt * 8 + 2 * lc, c1 = c0 + 1;
            s[nt][0] = (diag && c0 > r0_) ? -1e30f : s[nt][0] * scale;
            s[nt][1] = (diag && c1 > r0_) ? -1e30f : s[nt][1] * scale;
            s[nt][2] = (diag && c0 > r1_) ? -1e30f : s[nt][2] * scale;
            s[nt][3] = (diag && c1 > r1_) ? -1e30f : s[nt][3] * scale;
        }

        // online softmax
        float mx0 = -1e30f, mx1 = -1e30f;
        #pragma unroll
        for (int nt = 0; nt < 8; nt++) {
            mx0 = fmaxf(mx0, fmaxf(s[nt][0], s[nt][1]));
            mx1 = fmaxf(mx1, fmaxf(s[nt][2], s[nt][3]));
        }
        mx0 = fmaxf(mx0, __shfl_xor_sync(0xffffffffu, mx0, 1));
        mx0 = fmaxf(mx0, __shfl_xor_sync(0xffffffffu, mx0, 2));
        mx1 = fmaxf(mx1, __shfl_xor_sync(0xffffffffu, mx1, 1));
        mx1 = fmaxf(mx1, __shfl_xor_sync(0xffffffffu, mx1, 2));
        float mn0 = fmaxf(m0, mx0), mn1 = fmaxf(m1, mx1);
        float c0f = __expf(m0 - mn0), c1f = __expf(m1 - mn1);
        l0 *= c0f; l1 *= c1f;
        #pragma unroll
        for (int nt = 0; nt < 8; nt++) {
            o[nt][0] *= c0f; o[nt][1] *= c0f;
            o[nt][2] *= c1f; o[nt][3] *= c1f;
        }
        m0 = mn0; m1 = mn1;

        // P = exp(s-m) -> fp16, per-warp private smem rows
        #pragma unroll
        for (int nt = 0; nt < 8; nt++) {
            int c0 = nt * 8 + 2 * lc;
            float p00 = __expf(s[nt][0] - mn0);
            float p01 = __expf(s[nt][1] - mn0);
            float p10 = __expf(s[nt][2] - mn1);
            float p11 = __expf(s[nt][3] - mn1);
            l0 += p00 + p01; l1 += p10 + p11;
            *(uint32_t*)&Ps[(wq + lr) * APd + c0]     = packh2(p00, p01);
            *(uint32_t*)&Ps[(wq + lr + 8) * APd + c0] = packh2(p10, p11);
        }
        __syncwarp();

        // O += P @ V
        #pragma unroll
        for (int ks = 0; ks < 4; ks++) {
            uint32_t pa[4];
            ldsm4(pa[0], pa[1], pa[2], pa[3],
                  smem_u32(Ps + (wq + fr) * APd + ks * 16 + fcsel));
            #pragma unroll
            for (int ntp = 0; ntp < 4; ntp++) {
                uint32_t r0, r1, r2, r3;
                ldsm4(r0, r1, r2, r3,
                      smem_u32(Vt + (ntp * 16 + fr) * APd + ks * 16 + fcsel));
                mma_f16(o[2 * ntp],     pa, r0, r2);
                mma_f16(o[2 * ntp + 1], pa, r1, r3);
            }
        }
    }

    // epilogue: normalize, store fp16 Y (b,s,h,e)
    l0 += __shfl_xor_sync(0xffffffffu, l0, 1);
    l0 += __shfl_xor_sync(0xffffffffu, l0, 2);
    l1 += __shfl_xor_sync(0xffffffffu, l1, 1);
    l1 += __shfl_xor_sync(0xffffffffu, l1, 2);
    float i0 = 1.f / l0, i1 = 1.f / l1;
    int b = bh >> 4, h = bh & 15;
    int row0 = q0 + wq + lr, row1 = row0 + 8;
    __half* y0 = Y + (((size_t)(b * Ss + row0)) * Hh + h) * DH;
    __half* y1 = Y + (((size_t)(b * Ss + row1)) * Hh + h) * DH;
    #pragma unroll
    for (int nt = 0; nt < 8; nt++) {
        int c = nt * 8 + 2 * lc;
        *(uint32_t*)(y0 + c) = packh2(o[nt][0] * i0, o[nt][1] * i0);
        *(uint32_t*)(y1 + c) = packh2(o[nt][2] * i1, o[nt][3] * i1);
    }
}

// ---------------- launch ----------------
extern "C" void kernel_launch(void* const* d_in, const int* in_sizes, int n_in,
                              void* d_out, int out_size) {
    const float* hidden = (const float*)d_in[0];
    const float* ln1_w = (const float*)d_in[2];
    const float* ln1_b = (const float*)d_in[3];
    const float* q_U = (const float*)d_in[4];
    const float* q_V = (const float*)d_in[5];
    const float* q_b = (const float*)d_in[6];
    const float* k_U = (const float*)d_in[7];
    const float* k_V = (const float*)d_in[8];
    const float* k_b = (const float*)d_in[9];
    const float* v_U = (const float*)d_in[10];
    const float* v_V = (const float*)d_in[11];
    const float* v_b = (const float*)d_in[12];
    const float* out_U = (const float*)d_in[13];
    const float* out_V = (const float*)d_in[14];
    const float* out_b = (const float*)d_in[15];
    const float* ln2_w = (const float*)d_in[16];
    const float* ln2_b = (const float*)d_in[17];
    const float* fc1_U = (const float*)d_in[18];
    const float* fc1_V = (const float*)d_in[19];
    const float* fc1_b = (const float*)d_in[20];
    const float* fc2_U = (const float*)d_in[21];
    const float* fc2_V = (const float*)d_in[22];
    const float* fc2_b = (const float*)d_in[23];
    float* out = (float*)d_out;

    __half *x16_, *Q16_, *K16_, *V16_, *Y16_, *t16_, *a16_, *w16_;
    float *Pq_, *Pk_, *Pv_, *h_;
    cudaGetSymbolAddress((void**)&x16_, g_x16);
    cudaGetSymbolAddress((void**)&Pq_,  g_Pq);
    cudaGetSymbolAddress((void**)&Pk_,  g_Pk);
    cudaGetSymbolAddress((void**)&Pv_,  g_Pv);
    cudaGetSymbolAddress((void**)&Q16_, g_Q16);
    cudaGetSymbolAddress((void**)&K16_, g_K16);
    cudaGetSymbolAddress((void**)&V16_, g_V16);
    cudaGetSymbolAddress((void**)&Y16_, g_Y16);
    cudaGetSymbolAddress((void**)&t16_, g_t16);
    cudaGetSymbolAddress((void**)&h_,   g_h);
    cudaGetSymbolAddress((void**)&a16_, g_a16);
    cudaGetSymbolAddress((void**)&w16_, g_w16);

    cudaFuncSetAttribute(gemm16_qkv,      cudaFuncAttributeMaxDynamicSharedMemorySize, GEMM16_SMEM(128));
    cudaFuncSetAttribute(gemm16<3, 64>,   cudaFuncAttributeMaxDynamicSharedMemorySize, GEMM16_SMEM(64));
    cudaFuncSetAttribute(gemm16<1, 128>,  cudaFuncAttributeMaxDynamicSharedMemorySize, GEMM16_SMEM(128));
    cudaFuncSetAttribute(gemm16<2, 128>,  cudaFuncAttributeMaxDynamicSharedMemorySize, GEMM16_SMEM(128));

    // 0) convert + transpose weights -> fp16 [N][K]
    conv_w<<<7680, 256>>>(q_U, k_U, v_U, out_U, out_V, fc1_U, fc1_V, fc2_U, fc2_V, w16_);

    // 1) x = LN1(hidden) -> fp16
    ln_kernel<<<BS, 256>>>(hidden, ln1_w, ln1_b, x16_);

    // 2) Pq/Pk/Pv = x @ {q,k,v}_U (fused, fp32 out)
    {
        dim3 g(12, BS / 128);
        gemm16_qkv<<<g, 256, GEMM16_SMEM(128)>>>(x16_, w16_, Pq_, Pk_, Pv_);
    }

    // 3) head expansion -> fp16 Q,K ; V transposed
    {
        dim3 g(BS / 64, Hh, 3);
        head_proj2<<<g, 256>>>(Pq_, Pk_, Pv_, q_V, k_V, v_V, q_b, k_b, v_b, Q16_, K16_, V16_);
    }

    // 4) causal attention -> fp16 Y
    {
        dim3 g(Ss / 128, Bb * Hh);
        attn_f16<<<g, 256>>>(Q16_, K16_, V16_, Y16_);
    }

    // 5) h = hidden + (Y @ out_U) @ out_V + out_b
    {
        dim3 g1(RFC / 64, BS / 128);
        gemm16<3, 64><<<g1, 256, GEMM16_SMEM(64)>>>(Y16_, w16_ + WT_OU, t16_, BS, RFC, Dm, nullptr, nullptr);
        dim3 g2(Dm / 128, BS / 128);
        gemm16<1, 128><<<g2, 256, GEMM16_SMEM(128)>>>(t16_, w16_ + WT_OV, h_, BS, Dm, RFC, out_b, hidden);
    }

    // 6) z = LN2(h) -> fp16
    ln_kernel<<<BS, 256>>>(h_, ln2_w, ln2_b, x16_);

    // 7) a = gelu((z @ fc1_U) @ fc1_V + fc1_b) -> fp16
    {
        dim3 g1(RFC / 64, BS / 128);
        gemm16<3, 64><<<g1, 256, GEMM16_SMEM(64)>>>(x16_, w16_ + WT_F1U, t16_, BS, RFC, Dm, nullptr, nullptr);
        dim3 g2(Ii / 128, BS / 128);
        gemm16<2, 128><<<g2, 256, GEMM16_SMEM(128)>>>(t16_, w16_ + WT_F1V, a16_, BS, Ii, RFC, fc1_b, nullptr);
    }

    // 8) out = h + (a @ fc2_U) @ fc2_V + fc2_b
    {
        dim3 g1(RFC / 64, BS / 128);
        gemm16<3, 64><<<g1, 256, GEMM16_SMEM(64)>>>(a16_, w16_ + WT_F2U, t16_, BS, RFC, Ii, nullptr, nullptr);
        dim3 g2(Dm / 128, BS / 128);
        gemm16<1, 128><<<g2, 256, GEMM16_SMEM(128)>>>(t16_, w16_ + WT_F2V, out, BS, Dm, RFC, fc2_b, h_);
    }
}

// round 12
// speedup vs baseline: 1.7626x; 1.0680x over previous
#include <cuda_runtime.h>
#include <cuda_fp16.h>
#include <math.h>
#include <stdint.h>

// Problem dims (fixed)
#define Dm   1024
#define Hh   16
#define DH   64
#define Rr   32
#define Bb   2
#define Ss   2048
#define BS   (Bb*Ss)        // 4096
#define HR   (Hh*Rr)        // 512
#define Ii   4096
#define RFC  512

// ---------------- scratch ----------------
__device__ __half g_x16[BS*Dm];            // LN out (fp16), reused for z
__device__ __half g_Pq[BS*HR];
__device__ __half g_Pk[BS*HR];
__device__ __half g_Pv[BS*HR];
__device__ __half g_Q16[Bb*Hh*Ss*DH];
__device__ __half g_K16[Bb*Hh*Ss*DH];
__device__ __half g_V16[Bb*Hh*DH*Ss];      // V TRANSPOSED: [b,h,dh,s]
__device__ __half g_Y16[BS*Dm];
__device__ __half g_t16[BS*RFC];
__device__ float  g_h  [BS*Dm];
__device__ __half g_a16[BS*Ii];
__device__ __half g_w16[7864320];          // fp16 weights, TRANSPOSED [N][K]
__device__ __half g_wv16[3*Hh*DH*Rr];      // q/k/v head weights, per-head TRANSPOSED [e][r]

// transposed-weight offsets (halves)
#define WT_QU   0
#define WT_KU   524288
#define WT_VU   1048576
#define WT_OU   1572864
#define WT_OV   2097152
#define WT_F1U  2621440
#define WT_F1V  3145728
#define WT_F2U  5242880
#define WT_F2V  7340032

// ---------------- PTX helpers ----------------
__device__ __forceinline__ void cp16(uint32_t saddr, const void* gptr) {
    asm volatile("cp.async.cg.shared.global [%0], [%1], 16;" :: "r"(saddr), "l"(gptr));
}
__device__ __forceinline__ uint32_t smem_u32(const void* p) {
    return (uint32_t)__cvta_generic_to_shared(p);
}
__device__ __forceinline__ void ldsm4(uint32_t& r0, uint32_t& r1, uint32_t& r2, uint32_t& r3,
                                      uint32_t addr) {
    asm volatile("ldmatrix.sync.aligned.m8n8.x4.shared.b16 {%0,%1,%2,%3}, [%4];"
                 : "=r"(r0), "=r"(r1), "=r"(r2), "=r"(r3) : "r"(addr));
}
__device__ __forceinline__ void mma_f16(float* d, const uint32_t* a, uint32_t b0, uint32_t b1) {
    asm volatile(
        "mma.sync.aligned.m16n8k16.row.col.f32.f16.f16.f32 "
        "{%0,%1,%2,%3}, {%4,%5,%6,%7}, {%8,%9}, {%0,%1,%2,%3};"
        : "+f"(d[0]), "+f"(d[1]), "+f"(d[2]), "+f"(d[3])
        : "r"(a[0]), "r"(a[1]), "r"(a[2]), "r"(a[3]), "r"(b0), "r"(b1));
}
__device__ __forceinline__ uint32_t packh2(float a, float b) {
    __half2 h = __floats2half2_rn(a, b);
    return *(uint32_t*)&h;
}
__device__ __forceinline__ float gelu_tanh(float x) {
    float u = 0.7978845608f * (x + 0.044715f * x * x * x);
    float t = 1.f - 2.f / (__expf(2.f * u) + 1.f);
    return 0.5f * x * (1.f + t);
}

// ---------------- weight convert + transpose: fp32 [K][N] -> fp16 [N][K] ----------------
__global__ void __launch_bounds__(256) conv_w(
    const float* s0, const float* s1, const float* s2, const float* s3, const float* s4,
    const float* s5, const float* s6, const float* s7, const float* s8, __half* dst)
{
    const int Ksz[9]  = {1024,1024,1024,1024,512,1024,512,4096,512};
    const int Nsz[9]  = {512,512,512,512,1024,512,4096,512,1024};
    const int toff[9] = {0,512,1024,1536,2048,2560,3072,5120,7168};
    const int doff[9] = {WT_QU,WT_KU,WT_VU,WT_OU,WT_OV,WT_F1U,WT_F1V,WT_F2U,WT_F2V};
    int bx = blockIdx.x;
    int i = 0;
    #pragma unroll
    for (int j = 1; j < 9; j++) if (bx >= toff[j]) i = j;
    const float* src = (i==0)?s0:(i==1)?s1:(i==2)?s2:(i==3)?s3:(i==4)?s4:(i==5)?s5:(i==6)?s6:(i==7)?s7:s8;
    int local = bx - toff[i];
    int K = Ksz[i], N = Nsz[i];
    int ntile = N >> 5;
    int tk = local / ntile, tn = local % ntile;

    __shared__ float tsm[32][33];
    int cc = threadIdx.x & 31, r0 = threadIdx.x >> 5;
    #pragma unroll
    for (int j = 0; j < 4; j++) {
        int r = r0 + j * 8;
        tsm[r][cc] = src[(size_t)(tk * 32 + r) * N + tn * 32 + cc];
    }
    __syncthreads();
    __half* d = dst + doff[i];
    #pragma unroll
    for (int j = 0; j < 4; j++) {
        int r = r0 + j * 8;
        d[(size_t)(tn * 32 + r) * K + tk * 32 + cc] = __float2half(tsm[cc][r]);
    }
}

// ---------------- per-head q_V/k_V/v_V: fp32 [h][r][e] -> fp16 [z][h][e][r] ----------------
__global__ void __launch_bounds__(256) conv_v(
    const float* vq, const float* vk, const float* vv, __half* dst)
{
    int h = blockIdx.x, z = blockIdx.y;
    const float* src = ((z == 0) ? vq : (z == 1) ? vk : vv) + (size_t)h * Rr * DH;
    __half* d = dst + ((size_t)(z * Hh + h)) * DH * Rr;
    for (int i = threadIdx.x; i < Rr * DH; i += 256) {
        int r = i / DH, e = i % DH;
        d[e * Rr + r] = __float2half(src[i]);
    }
}

// ---------------- LayerNorm (fp32 in, fp16 out) ----------------
__global__ void ln_kernel(const float* __restrict__ in, const float* __restrict__ w,
                          const float* __restrict__ b, __half* __restrict__ out) {
    __shared__ float xs[Dm];
    __shared__ float red[8];
    int row = blockIdx.x;
    int t = threadIdx.x;
    const float* x = in + (size_t)row * Dm;

    float s = 0.f;
    #pragma unroll
    for (int i = t; i < Dm; i += 256) { float v = x[i]; xs[i] = v; s += v; }
    #pragma unroll
    for (int o = 16; o; o >>= 1) s += __shfl_xor_sync(0xffffffffu, s, o);
    if ((t & 31) == 0) red[t >> 5] = s;
    __syncthreads();
    float tot = 0.f;
    #pragma unroll
    for (int i = 0; i < 8; i++) tot += red[i];
    float mean = tot * (1.0f / Dm);
    __syncthreads();

    float vs = 0.f;
    #pragma unroll
    for (int i = t; i < Dm; i += 256) { float d = xs[i] - mean; vs += d * d; }
    #pragma unroll
    for (int o = 16; o; o >>= 1) vs += __shfl_xor_sync(0xffffffffu, vs, o);
    if ((t & 31) == 0) red[t >> 5] = vs;
    __syncthreads();
    float vtot = 0.f;
    #pragma unroll
    for (int i = 0; i < 8; i++) vtot += red[i];
    float rstd = rsqrtf(vtot * (1.0f / Dm) + 1e-5f);

    #pragma unroll
    for (int i = t; i < Dm; i += 256)
        out[(size_t)row * Dm + i] = __float2half((xs[i] - mean) * rstd * w[i] + b[i]);
}

// ---------------- FP16 GEMM (unchanged from R11) ----------------
// EPI: 0 = fp32 out plain; 1 = fp32 out + bias + res; 2 = fp16 out gelu(v+bias); 3 = fp16 out plain
#define BKh 64
#define AKp 72
#define GEMM16_SMEM(BN) ((2 * 128 * AKp + 2 * (BN) * AKp) * 2)

template<int EPI, int BN>
__device__ __forceinline__ void gemm16_core(
    const __half* __restrict__ A, const __half* __restrict__ Bt, void* __restrict__ Cv,
    int M, int N, int K, const float* __restrict__ bias, const float* __restrict__ res,
    int m0, int n0)
{
    constexpr int BM = 128;
    constexpr int WM_ = (BN == 128) ? 2 : 4;
    constexpr int WTM = BM / WM_;
    constexpr int MT = WTM / 16;
    constexpr int NT = 4;

    extern __shared__ __half smh[];
    __half* As = smh;
    __half* Bs = smh + 2 * BM * AKp;

    int tid = threadIdx.x;
    int w = tid >> 5, lane = tid & 31;
    int lr = lane >> 2, lc = lane & 3;
    int wm = (w % WM_) * WTM;
    int wn = (w / WM_) * 32;
    int fr = lane & 15;
    int fcsel = (lane >> 4) * 8;

    float acc[MT][NT][4];
    #pragma unroll
    for (int mt = 0; mt < MT; mt++)
        #pragma unroll
        for (int nt = 0; nt < NT; nt++)
            #pragma unroll
            for (int i = 0; i < 4; i++) acc[mt][nt][i] = 0.f;

    const __half* Ag = A + (size_t)m0 * K;
    const __half* Bg = Bt + (size_t)n0 * K;

    auto loadTile = [&](int kt, int buf) {
        __half* Abuf = As + buf * BM * AKp;
        __half* Bbuf = Bs + buf * BN * AKp;
        #pragma unroll
        for (int i = 0; i < 4; i++) {
            int q = tid + i * 256;
            int r = q >> 3, c = q & 7;
            cp16(smem_u32(Abuf + r * AKp + c * 8), Ag + (size_t)r * K + kt * BKh + c * 8);
        }
        #pragma unroll
        for (int i = 0; i < BN / 32; i++) {
            int q = tid + i * 256;
            int r = q >> 3, c = q & 7;
            cp16(smem_u32(Bbuf + r * AKp + c * 8), Bg + (size_t)r * K + kt * BKh + c * 8);
        }
        asm volatile("cp.async.commit_group;");
    };

    int NTILES = K / BKh;
    loadTile(0, 0);
    for (int kt = 0; kt < NTILES; kt++) {
        int buf = kt & 1;
        if (kt + 1 < NTILES) {
            loadTile(kt + 1, buf ^ 1);
            asm volatile("cp.async.wait_group 1;");
        } else {
            asm volatile("cp.async.wait_group 0;");
        }
        __syncthreads();
        const __half* Abuf = As + buf * BM * AKp;
        const __half* Bbuf = Bs + buf * BN * AKp;

        #pragma unroll
        for (int ks = 0; ks < 4; ks++) {
            int kb = ks * 16;
            uint32_t af[MT][4], bf[NT][2];
            #pragma unroll
            for (int mt = 0; mt < MT; mt++)
                ldsm4(af[mt][0], af[mt][1], af[mt][2], af[mt][3],
                      smem_u32(Abuf + (wm + mt * 16 + fr) * AKp + kb + fcsel));
            #pragma unroll
            for (int ntp = 0; ntp < 2; ntp++) {
                uint32_t r0, r1, r2, r3;
                ldsm4(r0, r1, r2, r3,
                      smem_u32(Bbuf + (wn + ntp * 16 + fr) * AKp + kb + fcsel));
                bf[2 * ntp][0] = r0; bf[2 * ntp][1] = r2;
                bf[2 * ntp + 1][0] = r1; bf[2 * ntp + 1][1] = r3;
            }
            #pragma unroll
            for (int mt = 0; mt < MT; mt++)
                #pragma unroll
                for (int nt = 0; nt < NT; nt++)
                    mma_f16(acc[mt][nt], af[mt], bf[nt][0], bf[nt][1]);
        }
        __syncthreads();
    }

    #pragma unroll
    for (int mt = 0; mt < MT; mt++) {
        #pragma unroll
        for (int hh = 0; hh < 2; hh++) {
            int row = m0 + wm + mt * 16 + lr + hh * 8;
            #pragma unroll
            for (int nt = 0; nt < NT; nt++) {
                int col = n0 + wn + nt * 8 + 2 * lc;
                float v0 = acc[mt][nt][2 * hh + 0];
                float v1 = acc[mt][nt][2 * hh + 1];
                if (EPI == 0) {
                    *(float2*)&((float*)Cv)[(size_t)row * N + col] = make_float2(v0, v1);
                } else if (EPI == 1) {
                    const float* rr = res + (size_t)row * N + col;
                    v0 += bias[col] + rr[0];
                    v1 += bias[col + 1] + rr[1];
                    *(float2*)&((float*)Cv)[(size_t)row * N + col] = make_float2(v0, v1);
                } else if (EPI == 2) {
                    v0 = gelu_tanh(v0 + bias[col]);
                    v1 = gelu_tanh(v1 + bias[col + 1]);
                    *(uint32_t*)&((__half*)Cv)[(size_t)row * N + col] = packh2(v0, v1);
                } else {
                    *(uint32_t*)&((__half*)Cv)[(size_t)row * N + col] = packh2(v0, v1);
                }
            }
        }
    }
}

template<int EPI, int BN>
__global__ void __launch_bounds__(256, 2) gemm16(
    const __half* __restrict__ A, const __half* __restrict__ Bt, void* __restrict__ C,
    int M, int N, int K, const float* __restrict__ bias, const float* __restrict__ res)
{
    gemm16_core<EPI, BN>(A, Bt, C, M, N, K, bias, res, blockIdx.y * 128, blockIdx.x * BN);
}

__global__ void __launch_bounds__(256, 2) gemm16_qkv(
    const __half* __restrict__ A, const __half* __restrict__ wt,
    __half* __restrict__ C0, __half* __restrict__ C1, __half* __restrict__ C2)
{
    int sel = blockIdx.x >> 2, nb = blockIdx.x & 3;
    const __half* Bt = wt + (sel == 0 ? WT_QU : sel == 1 ? WT_KU : WT_VU);
    __half* C = (sel == 0) ? C0 : (sel == 1) ? C1 : C2;
    gemm16_core<3, 128>(A, Bt, C, BS, HR, Dm, nullptr, nullptr, blockIdx.y * 128, nb * 128);
}

// ---------------- head_proj v3: tensor-core per-head projection ----------------
// P16[64 s][32 r] @ wv16[h] (as B: [64 e][32 r]) -> Q/K (b,h,s,e) fp16 ; V^T (b,h,e,s) fp16
#define HPd 40
#define OTd 72

__global__ void __launch_bounds__(128) head_proj3(
    const __half* __restrict__ Pq, const __half* __restrict__ Pk, const __half* __restrict__ Pv,
    const __half* __restrict__ wv,
    const float* __restrict__ bq, const float* __restrict__ bk, const float* __restrict__ bv,
    __half* __restrict__ Oq, __half* __restrict__ Ok, __half* __restrict__ Ov)
{
    __shared__ __half Pt[64 * HPd];
    __shared__ __half Wt[64 * HPd];
    __shared__ __half Ot[64 * OTd];      // V path only

    int z = blockIdx.z, h = blockIdx.y;
    int s0 = blockIdx.x * 64;
    const __half* P  = (z == 0) ? Pq : (z == 1) ? Pk : Pv;
    const float* bi  = ((z == 0) ? bq : (z == 1) ? bk : bv) + h * DH;
    __half* O        = (z == 0) ? Oq : (z == 1) ? Ok : Ov;
    const __half* W  = wv + ((size_t)(z * Hh + h)) * DH * Rr;

    int tid = threadIdx.x;
    int w = tid >> 5, lane = tid & 31;
    int lr = lane >> 2, lc = lane & 3;
    int fr = lane & 15;
    int fcsel = (lane >> 4) * 8;

    // stage P tile [64][32] and W tile [64 e][32 r]
    #pragma unroll
    for (int i = 0; i < 2; i++) {
        int idx = tid + i * 128;         // 256 chunks
        int r = idx >> 2, c = idx & 3;
        cp16(smem_u32(Pt + r * HPd + c * 8), P + (size_t)(s0 + r) * HR + h * Rr + c * 8);
        cp16(smem_u32(Wt + r * HPd + c * 8), W + (size_t)r * Rr + c * 8);
    }
    asm volatile("cp.async.commit_group;");
    asm volatile("cp.async.wait_group 0;");
    __syncthreads();

    // A frags: warp w rows 16w..16w+15, k=32 (2 chunks)
    uint32_t af[2][4];
    #pragma unroll
    for (int k = 0; k < 2; k++)
        ldsm4(af[k][0], af[k][1], af[k][2], af[k][3],
              smem_u32(Pt + (w * 16 + fr) * HPd + k * 16 + fcsel));

    float acc[8][4];
    #pragma unroll
    for (int nt = 0; nt < 8; nt++)
        #pragma unroll
        for (int i = 0; i < 4; i++) acc[nt][i] = 0.f;

    #pragma unroll
    for (int k = 0; k < 2; k++) {
        #pragma unroll
        for (int t = 0; t < 4; t++) {
            uint32_t r0, r1, r2, r3;
            ldsm4(r0, r1, r2, r3,
                  smem_u32(Wt + (t * 16 + fr) * HPd + k * 16 + fcsel));
            mma_f16(acc[2 * t],     af[k], r0, r2);
            mma_f16(acc[2 * t + 1], af[k], r1, r3);
        }
    }

    if (z < 2) {
        // direct store (b,h,s,e)
        int bsr0 = s0 + w * 16 + lr;
        #pragma unroll
        for (int hh = 0; hh < 2; hh++) {
            int bs = bsr0 + hh * 8;
            int b = bs >> 11, s = bs & 2047;
            __half* yb = O + (((size_t)(b * Hh + h)) * Ss + s) * DH;
            #pragma unroll
            for (int nt = 0; nt < 8; nt++) {
                int e = nt * 8 + 2 * lc;
                *(uint32_t*)(yb + e) = packh2(acc[nt][2 * hh] + bi[e],
                                              acc[nt][2 * hh + 1] + bi[e + 1]);
            }
        }
    } else {
        // store to Ot[e][s], then coalesced transposed write (b,h,e,s)
        int sr0 = w * 16 + lr;
        #pragma unroll
        for (int hh = 0; hh < 2; hh++) {
            int sl = sr0 + hh * 8;
            #pragma unroll
            for (int nt = 0; nt < 8; nt++) {
                int e = nt * 8 + 2 * lc;
                Ot[e * OTd + sl]       = __float2half(acc[nt][2 * hh] + bi[e]);
                Ot[(e + 1) * OTd + sl] = __float2half(acc[nt][2 * hh + 1] + bi[e + 1]);
            }
        }
        __syncthreads();
        int b = s0 >> 11, sbase = s0 & 2047;
        __half* ob = O + ((size_t)(b * Hh + h)) * DH * Ss + sbase;
        #pragma unroll
        for (int i = 0; i < 4; i++) {            // 64 e-rows x 8 chunks = 512 chunks
            int idx = tid + i * 128;
            int e = idx >> 3, c = idx & 7;
            *(uint4*)(ob + (size_t)e * Ss + c * 8) = *(uint4*)(Ot + e * OTd + c * 8);
        }
    }
}

// ---------------- FP16 causal flash attention (unchanged from R11) ----------------
#define APd 72

__global__ void __launch_bounds__(256, 2) attn_f16(
    const __half* __restrict__ Q, const __half* __restrict__ K,
    const __half* __restrict__ V, __half* __restrict__ Y)
{
    __shared__ __half Ks[64 * APd];
    __shared__ __half Vt[64 * APd];
    __shared__ __half Ps[128 * APd];

    int bh = blockIdx.y;
    int qblk = gridDim.x - 1 - blockIdx.x;
    int q0 = qblk * 128;
    int tid = threadIdx.x;
    int w = tid >> 5, lane = tid & 31;
    int lr = lane >> 2, lc = lane & 3;
    int wq = w * 16;
    int fr = lane & 15;
    int fcsel = (lane >> 4) * 8;

    uint32_t qf[4][4];
    const __half* Qb = Q + ((size_t)bh * Ss + q0 + wq) * DH;
    #pragma unroll
    for (int ks = 0; ks < 4; ks++) {
        qf[ks][0] = *(const uint32_t*)(Qb + (size_t)lr * DH + ks * 16 + 2 * lc);
        qf[ks][1] = *(const uint32_t*)(Qb + (size_t)(lr + 8) * DH + ks * 16 + 2 * lc);
        qf[ks][2] = *(const uint32_t*)(Qb + (size_t)lr * DH + ks * 16 + 8 + 2 * lc);
        qf[ks][3] = *(const uint32_t*)(Qb + (size_t)(lr + 8) * DH + ks * 16 + 8 + 2 * lc);
    }

    const __half* Kg = K + (size_t)bh * Ss * DH;
    const __half* Vg = V + (size_t)bh * DH * Ss;

    float o[8][4];
    #pragma unroll
    for (int nt = 0; nt < 8; nt++)
        #pragma unroll
        for (int i = 0; i < 4; i++) o[nt][i] = 0.f;
    float m0 = -1e30f, m1 = -1e30f, l0 = 0.f, l1 = 0.f;
    const float scale = 0.125f;

    int ktmax = 2 * qblk + 1;
    for (int kt = 0; kt <= ktmax; kt++) {
        __syncthreads();
        #pragma unroll
        for (int i = 0; i < 2; i++) {
            int idx = tid + i * 256;
            int r = idx >> 3, c = idx & 7;
            cp16(smem_u32(Ks + r * APd + c * 8), Kg + (size_t)(kt * 64 + r) * DH + c * 8);
        }
        #pragma unroll
        for (int i = 0; i < 2; i++) {
            int idx = tid + i * 256;
            int r = idx >> 3, c = idx & 7;
            cp16(smem_u32(Vt + r * APd + c * 8), Vg + (size_t)r * Ss + kt * 64 + c * 8);
        }
        asm volatile("cp.async.commit_group;");
        asm volatile("cp.async.wait_group 0;");
        __syncthreads();

        float s[8][4];
        #pragma unroll
        for (int nt = 0; nt < 8; nt++)
            #pragma unroll
            for (int i = 0; i < 4; i++) s[nt][i] = 0.f;
        #pragma unroll
        for (int ks = 0; ks < 4; ks++) {
            #pragma unroll
            for (int ntp = 0; ntp < 4; ntp++) {
                uint32_t r0, r1, r2, r3;
                ldsm4(r0, r1, r2, r3,
                      smem_u32(Ks + (ntp * 16 + fr) * APd + ks * 16 + fcsel));
                mma_f16(s[2 * ntp],     qf[ks], r0, r2);
                mma_f16(s[2 * ntp + 1], qf[ks], r1, r3);
            }
        }

        bool diag = (kt >= 2 * qblk);
        int r0_ = q0 + wq + lr, r1_ = r0_ + 8;
        int kc0 = kt * 64;
        #pragma unroll
        for (int nt = 0; nt < 8; nt++) {
            int c0 = kc0 + nt * 8 + 2 * lc, c1 = c0 + 1;
            s[nt][0] = (diag && c0 > r0_) ? -1e30f : s[nt][0] * scale;
            s[nt][1] = (diag && c1 > r0_) ? -1e30f : s[nt][1] * scale;
            s[nt][2] = (diag && c0 > r1_) ? -1e30f : s[nt][2] * scale;
            s[nt][3] = (diag && c1 > r1_) ? -1e30f : s[nt][3] * scale;
        }

        float mx0 = -1e30f, mx1 = -1e30f;
        #pragma unroll
        for (int nt = 0; nt < 8; nt++) {
            mx0 = fmaxf(mx0, fmaxf(s[nt][0], s[nt][1]));
            mx1 = fmaxf(mx1, fmaxf(s[nt][2], s[nt][3]));
        }
        mx0 = fmaxf(mx0, __shfl_xor_sync(0xffffffffu, mx0, 1));
        mx0 = fmaxf(mx0, __shfl_xor_sync(0xffffffffu, mx0, 2));
        mx1 = fmaxf(mx1, __shfl_xor_sync(0xffffffffu, mx1, 1));
        mx1 = fmaxf(mx1, __shfl_xor_sync(0xffffffffu, mx1, 2));
        float mn0 = fmaxf(m0, mx0), mn1 = fmaxf(m1, mx1);
        float c0f = __expf(m0 - mn0), c1f = __expf(m1 - mn1);
        l0 *= c0f; l1 *= c1f;
        #pragma unroll
        for (int nt = 0; nt < 8; nt++) {
            o[nt][0] *= c0f; o[nt][1] *= c0f;
            o[nt][2] *= c1f; o[nt][3] *= c1f;
        }
        m0 = mn0; m1 = mn1;

        #pragma unroll
        for (int nt = 0; nt < 8; nt++) {
            int c0 = nt * 8 + 2 * lc;
            float p00 = __expf(s[nt][0] - mn0);
            float p01 = __expf(s[nt][1] - mn0);
            float p10 = __expf(s[nt][2] - mn1);
            float p11 = __expf(s[nt][3] - mn1);
            l0 += p00 + p01; l1 += p10 + p11;
            *(uint32_t*)&Ps[(wq + lr) * APd + c0]     = packh2(p00, p01);
            *(uint32_t*)&Ps[(wq + lr + 8) * APd + c0] = packh2(p10, p11);
        }
        __syncwarp();

        #pragma unroll
        for (int ks = 0; ks < 4; ks++) {
            uint32_t pa[4];
            ldsm4(pa[0], pa[1], pa[2], pa[3],
                  smem_u32(Ps + (wq + fr) * APd + ks * 16 + fcsel));
            #pragma unroll
            for (int ntp = 0; ntp < 4; ntp++) {
                uint32_t r0, r1, r2, r3;
                ldsm4(r0, r1, r2, r3,
                      smem_u32(Vt + (ntp * 16 + fr) * APd + ks * 16 + fcsel));
                mma_f16(o[2 * ntp],     pa, r0, r2);
                mma_f16(o[2 * ntp + 1], pa, r1, r3);
            }
        }
    }

    l0 += __shfl_xor_sync(0xffffffffu, l0, 1);
    l0 += __shfl_xor_sync(0xffffffffu, l0, 2);
    l1 += __shfl_xor_sync(0xffffffffu, l1, 1);
    l1 += __shfl_xor_sync(0xffffffffu, l1, 2);
    float i0 = 1.f / l0, i1 = 1.f / l1;
    int b = bh >> 4, h = bh & 15;
    int row0 = q0 + wq + lr, row1 = row0 + 8;
    __half* y0 = Y + (((size_t)(b * Ss + row0)) * Hh + h) * DH;
    __half* y1 = Y + (((size_t)(b * Ss + row1)) * Hh + h) * DH;
    #pragma unroll
    for (int nt = 0; nt < 8; nt++) {
        int c = nt * 8 + 2 * lc;
        *(uint32_t*)(y0 + c) = packh2(o[nt][0] * i0, o[nt][1] * i0);
        *(uint32_t*)(y1 + c) = packh2(o[nt][2] * i1, o[nt][3] * i1);
    }
}

// ---------------- launch ----------------
extern "C" void kernel_launch(void* const* d_in, const int* in_sizes, int n_in,
                              void* d_out, int out_size) {
    const float* hidden = (const float*)d_in[0];
    const float* ln1_w = (const float*)d_in[2];
    const float* ln1_b = (const float*)d_in[3];
    const float* q_U = (const float*)d_in[4];
    const float* q_V = (const float*)d_in[5];
    const float* q_b = (const float*)d_in[6];
    const float* k_U = (const float*)d_in[7];
    const float* k_V = (const float*)d_in[8];
    const float* k_b = (const float*)d_in[9];
    const float* v_U = (const float*)d_in[10];
    const float* v_V = (const float*)d_in[11];
    const float* v_b = (const float*)d_in[12];
    const float* out_U = (const float*)d_in[13];
    const float* out_V = (const float*)d_in[14];
    const float* out_b = (const float*)d_in[15];
    const float* ln2_w = (const float*)d_in[16];
    const float* ln2_b = (const float*)d_in[17];
    const float* fc1_U = (const float*)d_in[18];
    const float* fc1_V = (const float*)d_in[19];
    const float* fc1_b = (const float*)d_in[20];
    const float* fc2_U = (const float*)d_in[21];
    const float* fc2_V = (const float*)d_in[22];
    const float* fc2_b = (const float*)d_in[23];
    float* out = (float*)d_out;

    __half *x16_, *Pq_, *Pk_, *Pv_, *Q16_, *K16_, *V16_, *Y16_, *t16_, *a16_, *w16_, *wv16_;
    float *h_;
    cudaGetSymbolAddress((void**)&x16_,  g_x16);
    cudaGetSymbolAddress((void**)&Pq_,   g_Pq);
    cudaGetSymbolAddress((void**)&Pk_,   g_Pk);
    cudaGetSymbolAddress((void**)&Pv_,   g_Pv);
    cudaGetSymbolAddress((void**)&Q16_,  g_Q16);
    cudaGetSymbolAddress((void**)&K16_,  g_K16);
    cudaGetSymbolAddress((void**)&V16_,  g_V16);
    cudaGetSymbolAddress((void**)&Y16_,  g_Y16);
    cudaGetSymbolAddress((void**)&t16_,  g_t16);
    cudaGetSymbolAddress((void**)&h_,    g_h);
    cudaGetSymbolAddress((void**)&a16_,  g_a16);
    cudaGetSymbolAddress((void**)&w16_,  g_w16);
    cudaGetSymbolAddress((void**)&wv16_, g_wv16);

    cudaFuncSetAttribute(gemm16_qkv,      cudaFuncAttributeMaxDynamicSharedMemorySize, GEMM16_SMEM(128));
    cudaFuncSetAttribute(gemm16<3, 64>,   cudaFuncAttributeMaxDynamicSharedMemorySize, GEMM16_SMEM(64));
    cudaFuncSetAttribute(gemm16<1, 128>,  cudaFuncAttributeMaxDynamicSharedMemorySize, GEMM16_SMEM(128));
    cudaFuncSetAttribute(gemm16<2, 128>,  cudaFuncAttributeMaxDynamicSharedMemorySize, GEMM16_SMEM(128));

    // 0) weight conversion
    conv_w<<<7680, 256>>>(q_U, k_U, v_U, out_U, out_V, fc1_U, fc1_V, fc2_U, fc2_V, w16_);
    {
        dim3 g(Hh, 3);
        conv_v<<<g, 256>>>(q_V, k_V, v_V, wv16_);
    }

    // 1) x = LN1(hidden) -> fp16
    ln_kernel<<<BS, 256>>>(hidden, ln1_w, ln1_b, x16_);

    // 2) Pq/Pk/Pv = x @ {q,k,v}_U  (fp16 out)
    {
        dim3 g(12, BS / 128);
        gemm16_qkv<<<g, 256, GEMM16_SMEM(128)>>>(x16_, w16_, Pq_, Pk_, Pv_);
    }

    // 3) head expansion (tensor cores)
    {
        dim3 g(BS / 64, Hh, 3);
        head_proj3<<<g, 128>>>(Pq_, Pk_, Pv_, wv16_, q_b, k_b, v_b, Q16_, K16_, V16_);
    }

    // 4) causal attention -> fp16 Y
    {
        dim3 g(Ss / 128, Bb * Hh);
        attn_f16<<<g, 256>>>(Q16_, K16_, V16_, Y16_);
    }

    // 5) h = hidden + (Y @ out_U) @ out_V + out_b
    {
        dim3 g1(RFC / 64, BS / 128);
        gemm16<3, 64><<<g1, 256, GEMM16_SMEM(64)>>>(Y16_, w16_ + WT_OU, t16_, BS, RFC, Dm, nullptr, nullptr);
        dim3 g2(Dm / 128, BS / 128);
        gemm16<1, 128><<<g2, 256, GEMM16_SMEM(128)>>>(t16_, w16_ + WT_OV, h_, BS, Dm, RFC, out_b, hidden);
    }

    // 6) z = LN2(h) -> fp16
    ln_kernel<<<BS, 256>>>(h_, ln2_w, ln2_b, x16_);

    // 7) a = gelu((z @ fc1_U) @ fc1_V + fc1_b) -> fp16
    {
        dim3 g1(RFC / 64, BS / 128);
        gemm16<3, 64><<<g1, 256, GEMM16_SMEM(64)>>>(x16_, w16_ + WT_F1U, t16_, BS, RFC, Dm, nullptr, nullptr);
        dim3 g2(Ii / 128, BS / 128);
        gemm16<2, 128><<<g2, 256, GEMM16_SMEM(128)>>>(t16_, w16_ + WT_F1V, a16_, BS, Ii, RFC, fc1_b, nullptr);
    }

    // 8) out = h + (a @ fc2_U) @ fc2_V + fc2_b
    {
        dim3 g1(RFC / 64, BS / 128);
        gemm16<3, 64><<<g1, 256, GEMM16_SMEM(64)>>>(a16_, w16_ + WT_F2U, t16_, BS, RFC, Ii, nullptr, nullptr);
        dim3 g2(Dm / 128, BS / 128);
        gemm16<1, 128><<<g2, 256, GEMM16_SMEM(128)>>>(t16_, w16_ + WT_F2V, out, BS, Dm, RFC, fc2_b, h_);
    }
}

// round 13
// speedup vs baseline: 1.7790x; 1.0093x over previous
#include <cuda_runtime.h>
#include <cuda_fp16.h>
#include <math.h>
#include <stdint.h>

// Problem dims (fixed)
#define Dm   1024
#define Hh   16
#define DH   64
#define Rr   32
#define Bb   2
#define Ss   2048
#define BS   (Bb*Ss)        // 4096
#define HR   (Hh*Rr)        // 512
#define Ii   4096
#define RFC  512

// ---------------- scratch ----------------
__device__ __half g_x16[BS*Dm];
__device__ __half g_Pq[BS*HR];
__device__ __half g_Pk[BS*HR];
__device__ __half g_Pv[BS*HR];
__device__ __half g_Q16[Bb*Hh*Ss*DH];
__device__ __half g_K16[Bb*Hh*Ss*DH];
__device__ __half g_V16[Bb*Hh*DH*Ss];      // V TRANSPOSED: [b,h,dh,s]
__device__ __half g_Y16[BS*Dm];
__device__ __half g_t16[BS*RFC];
__device__ float  g_h  [BS*Dm];
__device__ __half g_a16[BS*Ii];
__device__ __half g_w16[7864320];          // fp16 weights, TRANSPOSED [N][K]
__device__ __half g_wv16[3*Hh*DH*Rr];      // q/k/v head weights, per-head TRANSPOSED [e][r]

// transposed-weight offsets (halves)
#define WT_QU   0
#define WT_KU   524288
#define WT_VU   1048576
#define WT_OU   1572864
#define WT_OV   2097152
#define WT_F1U  2621440
#define WT_F1V  3145728
#define WT_F2U  5242880
#define WT_F2V  7340032

// ---------------- PTX helpers ----------------
__device__ __forceinline__ void cp16(uint32_t saddr, const void* gptr) {
    asm volatile("cp.async.cg.shared.global [%0], [%1], 16;" :: "r"(saddr), "l"(gptr));
}
__device__ __forceinline__ uint32_t smem_u32(const void* p) {
    return (uint32_t)__cvta_generic_to_shared(p);
}
__device__ __forceinline__ void ldsm4(uint32_t& r0, uint32_t& r1, uint32_t& r2, uint32_t& r3,
                                      uint32_t addr) {
    asm volatile("ldmatrix.sync.aligned.m8n8.x4.shared.b16 {%0,%1,%2,%3}, [%4];"
                 : "=r"(r0), "=r"(r1), "=r"(r2), "=r"(r3) : "r"(addr));
}
__device__ __forceinline__ void mma_f16(float* d, const uint32_t* a, uint32_t b0, uint32_t b1) {
    asm volatile(
        "mma.sync.aligned.m16n8k16.row.col.f32.f16.f16.f32 "
        "{%0,%1,%2,%3}, {%4,%5,%6,%7}, {%8,%9}, {%0,%1,%2,%3};"
        : "+f"(d[0]), "+f"(d[1]), "+f"(d[2]), "+f"(d[3])
        : "r"(a[0]), "r"(a[1]), "r"(a[2]), "r"(a[3]), "r"(b0), "r"(b1));
}
__device__ __forceinline__ uint32_t packh2(float a, float b) {
    __half2 h = __floats2half2_rn(a, b);
    return *(uint32_t*)&h;
}
__device__ __forceinline__ float gelu_tanh(float x) {
    float u = 0.7978845608f * (x + 0.044715f * x * x * x);
    float t = 1.f - 2.f / (__expf(2.f * u) + 1.f);
    return 0.5f * x * (1.f + t);
}

// ---------------- weight convert + transpose: fp32 [K][N] -> fp16 [N][K] ----------------
__global__ void __launch_bounds__(256) conv_w(
    const float* s0, const float* s1, const float* s2, const float* s3, const float* s4,
    const float* s5, const float* s6, const float* s7, const float* s8, __half* dst)
{
    const int Ksz[9]  = {1024,1024,1024,1024,512,1024,512,4096,512};
    const int Nsz[9]  = {512,512,512,512,1024,512,4096,512,1024};
    const int toff[9] = {0,512,1024,1536,2048,2560,3072,5120,7168};
    const int doff[9] = {WT_QU,WT_KU,WT_VU,WT_OU,WT_OV,WT_F1U,WT_F1V,WT_F2U,WT_F2V};
    int bx = blockIdx.x;
    int i = 0;
    #pragma unroll
    for (int j = 1; j < 9; j++) if (bx >= toff[j]) i = j;
    const float* src = (i==0)?s0:(i==1)?s1:(i==2)?s2:(i==3)?s3:(i==4)?s4:(i==5)?s5:(i==6)?s6:(i==7)?s7:s8;
    int local = bx - toff[i];
    int K = Ksz[i], N = Nsz[i];
    int ntile = N >> 5;
    int tk = local / ntile, tn = local % ntile;

    __shared__ float tsm[32][33];
    int cc = threadIdx.x & 31, r0 = threadIdx.x >> 5;
    #pragma unroll
    for (int j = 0; j < 4; j++) {
        int r = r0 + j * 8;
        tsm[r][cc] = src[(size_t)(tk * 32 + r) * N + tn * 32 + cc];
    }
    __syncthreads();
    __half* d = dst + doff[i];
    #pragma unroll
    for (int j = 0; j < 4; j++) {
        int r = r0 + j * 8;
        d[(size_t)(tn * 32 + r) * K + tk * 32 + cc] = __float2half(tsm[cc][r]);
    }
}

// ---------------- per-head q_V/k_V/v_V: fp32 [h][r][e] -> fp16 [z][h][e][r] ----------------
__global__ void __launch_bounds__(256) conv_v(
    const float* vq, const float* vk, const float* vv, __half* dst)
{
    int h = blockIdx.x, z = blockIdx.y;
    const float* src = ((z == 0) ? vq : (z == 1) ? vk : vv) + (size_t)h * Rr * DH;
    __half* d = dst + ((size_t)(z * Hh + h)) * DH * Rr;
    for (int i = threadIdx.x; i < Rr * DH; i += 256) {
        int r = i / DH, e = i % DH;
        d[e * Rr + r] = __float2half(src[i]);
    }
}

// ---------------- LayerNorm (fp32 in, fp16 out) ----------------
__global__ void ln_kernel(const float* __restrict__ in, const float* __restrict__ w,
                          const float* __restrict__ b, __half* __restrict__ out) {
    __shared__ float xs[Dm];
    __shared__ float red[8];
    int row = blockIdx.x;
    int t = threadIdx.x;
    const float* x = in + (size_t)row * Dm;

    float s = 0.f;
    #pragma unroll
    for (int i = t; i < Dm; i += 256) { float v = x[i]; xs[i] = v; s += v; }
    #pragma unroll
    for (int o = 16; o; o >>= 1) s += __shfl_xor_sync(0xffffffffu, s, o);
    if ((t & 31) == 0) red[t >> 5] = s;
    __syncthreads();
    float tot = 0.f;
    #pragma unroll
    for (int i = 0; i < 8; i++) tot += red[i];
    float mean = tot * (1.0f / Dm);
    __syncthreads();

    float vs = 0.f;
    #pragma unroll
    for (int i = t; i < Dm; i += 256) { float d = xs[i] - mean; vs += d * d; }
    #pragma unroll
    for (int o = 16; o; o >>= 1) vs += __shfl_xor_sync(0xffffffffu, vs, o);
    if ((t & 31) == 0) red[t >> 5] = vs;
    __syncthreads();
    float vtot = 0.f;
    #pragma unroll
    for (int i = 0; i < 8; i++) vtot += red[i];
    float rstd = rsqrtf(vtot * (1.0f / Dm) + 1e-5f);

    #pragma unroll
    for (int i = t; i < Dm; i += 256)
        out[(size_t)row * Dm + i] = __float2half((xs[i] - mean) * rstd * w[i] + b[i]);
}

// ---------------- FP16 GEMM: single-sync double-buffered mainloop ----------------
// EPI: 0 = fp32 out plain; 1 = fp32 out + bias + res; 2 = fp16 out gelu(v+bias); 3 = fp16 out plain
#define BKh 64
#define AKp 72
#define GEMM16_SMEM(BN) ((2 * 128 * AKp + 2 * (BN) * AKp) * 2)

template<int EPI, int BN>
__device__ __forceinline__ void gemm16_core(
    const __half* __restrict__ A, const __half* __restrict__ Bt, void* __restrict__ Cv,
    int M, int N, int K, const float* __restrict__ bias, const float* __restrict__ res,
    int m0, int n0)
{
    constexpr int BM = 128;
    constexpr int WM_ = (BN == 128) ? 2 : 4;
    constexpr int WTM = BM / WM_;
    constexpr int MT = WTM / 16;
    constexpr int NT = 4;

    extern __shared__ __half smh[];
    __half* As = smh;
    __half* Bs = smh + 2 * BM * AKp;

    int tid = threadIdx.x;
    int w = tid >> 5, lane = tid & 31;
    int lr = lane >> 2, lc = lane & 3;
    int wm = (w % WM_) * WTM;
    int wn = (w / WM_) * 32;
    int fr = lane & 15;
    int fcsel = (lane >> 4) * 8;

    float acc[MT][NT][4];
    #pragma unroll
    for (int mt = 0; mt < MT; mt++)
        #pragma unroll
        for (int nt = 0; nt < NT; nt++)
            #pragma unroll
            for (int i = 0; i < 4; i++) acc[mt][nt][i] = 0.f;

    const __half* Ag = A + (size_t)m0 * K;
    const __half* Bg = Bt + (size_t)n0 * K;

    auto loadTile = [&](int kt, int buf) {
        __half* Abuf = As + buf * BM * AKp;
        __half* Bbuf = Bs + buf * BN * AKp;
        #pragma unroll
        for (int i = 0; i < 4; i++) {
            int q = tid + i * 256;
            int r = q >> 3, c = q & 7;
            cp16(smem_u32(Abuf + r * AKp + c * 8), Ag + (size_t)r * K + kt * BKh + c * 8);
        }
        #pragma unroll
        for (int i = 0; i < BN / 32; i++) {
            int q = tid + i * 256;
            int r = q >> 3, c = q & 7;
            cp16(smem_u32(Bbuf + r * AKp + c * 8), Bg + (size_t)r * K + kt * BKh + c * 8);
        }
        asm volatile("cp.async.commit_group;");
    };

    int NTILES = K / BKh;
    loadTile(0, 0);
    for (int kt = 0; kt < NTILES; kt++) {
        int buf = kt & 1;
        asm volatile("cp.async.wait_group 0;");   // load kt complete (1 group in flight)
        __syncthreads();                          // + all reads of buf^1 (compute kt-1) done
        if (kt + 1 < NTILES) loadTile(kt + 1, buf ^ 1);   // overlaps with compute kt

        const __half* Abuf = As + buf * BM * AKp;
        const __half* Bbuf = Bs + buf * BN * AKp;

        #pragma unroll
        for (int ks = 0; ks < 4; ks++) {
            int kb = ks * 16;
            uint32_t af[MT][4], bf[NT][2];
            #pragma unroll
            for (int mt = 0; mt < MT; mt++)
                ldsm4(af[mt][0], af[mt][1], af[mt][2], af[mt][3],
                      smem_u32(Abuf + (wm + mt * 16 + fr) * AKp + kb + fcsel));
            #pragma unroll
            for (int ntp = 0; ntp < 2; ntp++) {
                uint32_t r0, r1, r2, r3;
                ldsm4(r0, r1, r2, r3,
                      smem_u32(Bbuf + (wn + ntp * 16 + fr) * AKp + kb + fcsel));
                bf[2 * ntp][0] = r0; bf[2 * ntp][1] = r2;
                bf[2 * ntp + 1][0] = r1; bf[2 * ntp + 1][1] = r3;
            }
            #pragma unroll
            for (int mt = 0; mt < MT; mt++)
                #pragma unroll
                for (int nt = 0; nt < NT; nt++)
                    mma_f16(acc[mt][nt], af[mt], bf[nt][0], bf[nt][1]);
        }
    }

    #pragma unroll
    for (int mt = 0; mt < MT; mt++) {
        #pragma unroll
        for (int hh = 0; hh < 2; hh++) {
            int row = m0 + wm + mt * 16 + lr + hh * 8;
            #pragma unroll
            for (int nt = 0; nt < NT; nt++) {
                int col = n0 + wn + nt * 8 + 2 * lc;
                float v0 = acc[mt][nt][2 * hh + 0];
                float v1 = acc[mt][nt][2 * hh + 1];
                if (EPI == 0) {
                    *(float2*)&((float*)Cv)[(size_t)row * N + col] = make_float2(v0, v1);
                } else if (EPI == 1) {
                    const float* rr = res + (size_t)row * N + col;
                    v0 += bias[col] + rr[0];
                    v1 += bias[col + 1] + rr[1];
                    *(float2*)&((float*)Cv)[(size_t)row * N + col] = make_float2(v0, v1);
                } else if (EPI == 2) {
                    v0 = gelu_tanh(v0 + bias[col]);
                    v1 = gelu_tanh(v1 + bias[col + 1]);
                    *(uint32_t*)&((__half*)Cv)[(size_t)row * N + col] = packh2(v0, v1);
                } else {
                    *(uint32_t*)&((__half*)Cv)[(size_t)row * N + col] = packh2(v0, v1);
                }
            }
        }
    }
}

template<int EPI, int BN>
__global__ void __launch_bounds__(256, 2) gemm16(
    const __half* __restrict__ A, const __half* __restrict__ Bt, void* __restrict__ C,
    int M, int N, int K, const float* __restrict__ bias, const float* __restrict__ res)
{
    gemm16_core<EPI, BN>(A, Bt, C, M, N, K, bias, res, blockIdx.y * 128, blockIdx.x * BN);
}

__global__ void __launch_bounds__(256, 2) gemm16_qkv(
    const __half* __restrict__ A, const __half* __restrict__ wt,
    __half* __restrict__ C0, __half* __restrict__ C1, __half* __restrict__ C2)
{
    int sel = blockIdx.x >> 2, nb = blockIdx.x & 3;
    const __half* Bt = wt + (sel == 0 ? WT_QU : sel == 1 ? WT_KU : WT_VU);
    __half* C = (sel == 0) ? C0 : (sel == 1) ? C1 : C2;
    gemm16_core<3, 128>(A, Bt, C, BS, HR, Dm, nullptr, nullptr, blockIdx.y * 128, nb * 128);
}

// ---------------- head_proj v3 (tensor cores, unchanged from R12) ----------------
#define HPd 40
#define OTd 72

__global__ void __launch_bounds__(128) head_proj3(
    const __half* __restrict__ Pq, const __half* __restrict__ Pk, const __half* __restrict__ Pv,
    const __half* __restrict__ wv,
    const float* __restrict__ bq, const float* __restrict__ bk, const float* __restrict__ bv,
    __half* __restrict__ Oq, __half* __restrict__ Ok, __half* __restrict__ Ov)
{
    __shared__ __half Pt[64 * HPd];
    __shared__ __half Wt[64 * HPd];
    __shared__ __half Ot[64 * OTd];

    int z = blockIdx.z, h = blockIdx.y;
    int s0 = blockIdx.x * 64;
    const __half* P  = (z == 0) ? Pq : (z == 1) ? Pk : Pv;
    const float* bi  = ((z == 0) ? bq : (z == 1) ? bk : bv) + h * DH;
    __half* O        = (z == 0) ? Oq : (z == 1) ? Ok : Ov;
    const __half* W  = wv + ((size_t)(z * Hh + h)) * DH * Rr;

    int tid = threadIdx.x;
    int w = tid >> 5, lane = tid & 31;
    int lr = lane >> 2, lc = lane & 3;
    int fr = lane & 15;
    int fcsel = (lane >> 4) * 8;

    #pragma unroll
    for (int i = 0; i < 2; i++) {
        int idx = tid + i * 128;
        int r = idx >> 2, c = idx & 3;
        cp16(smem_u32(Pt + r * HPd + c * 8), P + (size_t)(s0 + r) * HR + h * Rr + c * 8);
        cp16(smem_u32(Wt + r * HPd + c * 8), W + (size_t)r * Rr + c * 8);
    }
    asm volatile("cp.async.commit_group;");
    asm volatile("cp.async.wait_group 0;");
    __syncthreads();

    uint32_t af[2][4];
    #pragma unroll
    for (int k = 0; k < 2; k++)
        ldsm4(af[k][0], af[k][1], af[k][2], af[k][3],
              smem_u32(Pt + (w * 16 + fr) * HPd + k * 16 + fcsel));

    float acc[8][4];
    #pragma unroll
    for (int nt = 0; nt < 8; nt++)
        #pragma unroll
        for (int i = 0; i < 4; i++) acc[nt][i] = 0.f;

    #pragma unroll
    for (int k = 0; k < 2; k++) {
        #pragma unroll
        for (int t = 0; t < 4; t++) {
            uint32_t r0, r1, r2, r3;
            ldsm4(r0, r1, r2, r3,
                  smem_u32(Wt + (t * 16 + fr) * HPd + k * 16 + fcsel));
            mma_f16(acc[2 * t],     af[k], r0, r2);
            mma_f16(acc[2 * t + 1], af[k], r1, r3);
        }
    }

    if (z < 2) {
        int bsr0 = s0 + w * 16 + lr;
        #pragma unroll
        for (int hh = 0; hh < 2; hh++) {
            int bs = bsr0 + hh * 8;
            int b = bs >> 11, s = bs & 2047;
            __half* yb = O + (((size_t)(b * Hh + h)) * Ss + s) * DH;
            #pragma unroll
            for (int nt = 0; nt < 8; nt++) {
                int e = nt * 8 + 2 * lc;
                *(uint32_t*)(yb + e) = packh2(acc[nt][2 * hh] + bi[e],
                                              acc[nt][2 * hh + 1] + bi[e + 1]);
            }
        }
    } else {
        int sr0 = w * 16 + lr;
        #pragma unroll
        for (int hh = 0; hh < 2; hh++) {
            int sl = sr0 + hh * 8;
            #pragma unroll
            for (int nt = 0; nt < 8; nt++) {
                int e = nt * 8 + 2 * lc;
                Ot[e * OTd + sl]       = __float2half(acc[nt][2 * hh] + bi[e]);
                Ot[(e + 1) * OTd + sl] = __float2half(acc[nt][2 * hh + 1] + bi[e + 1]);
            }
        }
        __syncthreads();
        int b = s0 >> 11, sbase = s0 & 2047;
        __half* ob = O + ((size_t)(b * Hh + h)) * DH * Ss + sbase;
        #pragma unroll
        for (int i = 0; i < 4; i++) {
            int idx = tid + i * 128;
            int e = idx >> 3, c = idx & 7;
            *(uint4*)(ob + (size_t)e * Ss + c * 8) = *(uint4*)(Ot + e * OTd + c * 8);
        }
    }
}

// ---------------- FP16 causal flash attention (unchanged from R11/R12) ----------------
#define APd 72

__global__ void __launch_bounds__(256, 2) attn_f16(
    const __half* __restrict__ Q, const __half* __restrict__ K,
    const __half* __restrict__ V, __half* __restrict__ Y)
{
    __shared__ __half Ks[64 * APd];
    __shared__ __half Vt[64 * APd];
    __shared__ __half Ps[128 * APd];

    int bh = blockIdx.y;
    int qblk = gridDim.x - 1 - blockIdx.x;
    int q0 = qblk * 128;
    int tid = threadIdx.x;
    int w = tid >> 5, lane = tid & 31;
    int lr = lane >> 2, lc = lane & 3;
    int wq = w * 16;
    int fr = lane & 15;
    int fcsel = (lane >> 4) * 8;

    uint32_t qf[4][4];
    const __half* Qb = Q + ((size_t)bh * Ss + q0 + wq) * DH;
    #pragma unroll
    for (int ks = 0; ks < 4; ks++) {
        qf[ks][0] = *(const uint32_t*)(Qb + (size_t)lr * DH + ks * 16 + 2 * lc);
        qf[ks][1] = *(const uint32_t*)(Qb + (size_t)(lr + 8) * DH + ks * 16 + 2 * lc);
        qf[ks][2] = *(const uint32_t*)(Qb + (size_t)lr * DH + ks * 16 + 8 + 2 * lc);
        qf[ks][3] = *(const uint32_t*)(Qb + (size_t)(lr + 8) * DH + ks * 16 + 8 + 2 * lc);
    }

    const __half* Kg = K + (size_t)bh * Ss * DH;
    const __half* Vg = V + (size_t)bh * DH * Ss;

    float o[8][4];
    #pragma unroll
    for (int nt = 0; nt < 8; nt++)
        #pragma unroll
        for (int i = 0; i < 4; i++) o[nt][i] = 0.f;
    float m0 = -1e30f, m1 = -1e30f, l0 = 0.f, l1 = 0.f;
    const float scale = 0.125f;

    int ktmax = 2 * qblk + 1;
    for (int kt = 0; kt <= ktmax; kt++) {
        __syncthreads();
        #pragma unroll
        for (int i = 0; i < 2; i++) {
            int idx = tid + i * 256;
            int r = idx >> 3, c = idx & 7;
            cp16(smem_u32(Ks + r * APd + c * 8), Kg + (size_t)(kt * 64 + r) * DH + c * 8);
        }
        #pragma unroll
        for (int i = 0; i < 2; i++) {
            int idx = tid + i * 256;
            int r = idx >> 3, c = idx & 7;
            cp16(smem_u32(Vt + r * APd + c * 8), Vg + (size_t)r * Ss + kt * 64 + c * 8);
        }
        asm volatile("cp.async.commit_group;");
        asm volatile("cp.async.wait_group 0;");
        __syncthreads();

        float s[8][4];
        #pragma unroll
        for (int nt = 0; nt < 8; nt++)
            #pragma unroll
            for (int i = 0; i < 4; i++) s[nt][i] = 0.f;
        #pragma unroll
        for (int ks = 0; ks < 4; ks++) {
            #pragma unroll
            for (int ntp = 0; ntp < 4; ntp++) {
                uint32_t r0, r1, r2, r3;
                ldsm4(r0, r1, r2, r3,
                      smem_u32(Ks + (ntp * 16 + fr) * APd + ks * 16 + fcsel));
                mma_f16(s[2 * ntp],     qf[ks], r0, r2);
                mma_f16(s[2 * ntp + 1], qf[ks], r1, r3);
            }
        }

        bool diag = (kt >= 2 * qblk);
        int r0_ = q0 + wq + lr, r1_ = r0_ + 8;
        int kc0 = kt * 64;
        #pragma unroll
        for (int nt = 0; nt < 8; nt++) {
            int c0 = kc0 + nt * 8 + 2 * lc, c1 = c0 + 1;
            s[nt][0] = (diag && c0 > r0_) ? -1e30f : s[nt][0] * scale;
            s[nt][1] = (diag && c1 > r0_) ? -1e30f : s[nt][1] * scale;
            s[nt][2] = (diag && c0 > r1_) ? -1e30f : s[nt][2] * scale;
            s[nt][3] = (diag && c1 > r1_) ? -1e30f : s[nt][3] * scale;
        }

        float mx0 = -1e30f, mx1 = -1e30f;
        #pragma unroll
        for (int nt = 0; nt < 8; nt++) {
            mx0 = fmaxf(mx0, fmaxf(s[nt][0], s[nt][1]));
            mx1 = fmaxf(mx1, fmaxf(s[nt][2], s[nt][3]));
        }
        mx0 = fmaxf(mx0, __shfl_xor_sync(0xffffffffu, mx0, 1));
        mx0 = fmaxf(mx0, __shfl_xor_sync(0xffffffffu, mx0, 2));
        mx1 = fmaxf(mx1, __shfl_xor_sync(0xffffffffu, mx1, 1));
        mx1 = fmaxf(mx1, __shfl_xor_sync(0xffffffffu, mx1, 2));
        float mn0 = fmaxf(m0, mx0), mn1 = fmaxf(m1, mx1);
        float c0f = __expf(m0 - mn0), c1f = __expf(m1 - mn1);
        l0 *= c0f; l1 *= c1f;
        #pragma unroll
        for (int nt = 0; nt < 8; nt++) {
            o[nt][0] *= c0f; o[nt][1] *= c0f;
            o[nt][2] *= c1f; o[nt][3] *= c1f;
        }
        m0 = mn0; m1 = mn1;

        #pragma unroll
        for (int nt = 0; nt < 8; nt++) {
            int c0 = nt * 8 + 2 * lc;
            float p00 = __expf(s[nt][0] - mn0);
            float p01 = __expf(s[nt][1] - mn0);
            float p10 = __expf(s[nt][2] - mn1);
            float p11 = __expf(s[nt][3] - mn1);
            l0 += p00 + p01; l1 += p10 + p11;
            *(uint32_t*)&Ps[(wq + lr) * APd + c0]     = packh2(p00, p01);
            *(uint32_t*)&Ps[(wq + lr + 8) * APd + c0] = packh2(p10, p11);
        }
        __syncwarp();

        #pragma unroll
        for (int ks = 0; ks < 4; ks++) {
            uint32_t pa[4];
            ldsm4(pa[0], pa[1], pa[2], pa[3],
                  smem_u32(Ps + (wq + fr) * APd + ks * 16 + fcsel));
            #pragma unroll
            for (int ntp = 0; ntp < 4; ntp++) {
                uint32_t r0, r1, r2, r3;
                ldsm4(r0, r1, r2, r3,
                      smem_u32(Vt + (ntp * 16 + fr) * APd + ks * 16 + fcsel));
                mma_f16(o[2 * ntp],     pa, r0, r2);
                mma_f16(o[2 * ntp + 1], pa, r1, r3);
            }
        }
    }

    l0 += __shfl_xor_sync(0xffffffffu, l0, 1);
    l0 += __shfl_xor_sync(0xffffffffu, l0, 2);
    l1 += __shfl_xor_sync(0xffffffffu, l1, 1);
    l1 += __shfl_xor_sync(0xffffffffu, l1, 2);
    float i0 = 1.f / l0, i1 = 1.f / l1;
    int b = bh >> 4, h = bh & 15;
    int row0 = q0 + wq + lr, row1 = row0 + 8;
    __half* y0 = Y + (((size_t)(b * Ss + row0)) * Hh + h) * DH;
    __half* y1 = Y + (((size_t)(b * Ss + row1)) * Hh + h) * DH;
    #pragma unroll
    for (int nt = 0; nt < 8; nt++) {
        int c = nt * 8 + 2 * lc;
        *(uint32_t*)(y0 + c) = packh2(o[nt][0] * i0, o[nt][1] * i0);
        *(uint32_t*)(y1 + c) = packh2(o[nt][2] * i1, o[nt][3] * i1);
    }
}

// ---------------- launch ----------------
extern "C" void kernel_launch(void* const* d_in, const int* in_sizes, int n_in,
                              void* d_out, int out_size) {
    const float* hidden = (const float*)d_in[0];
    const float* ln1_w = (const float*)d_in[2];
    const float* ln1_b = (const float*)d_in[3];
    const float* q_U = (const float*)d_in[4];
    const float* q_V = (const float*)d_in[5];
    const float* q_b = (const float*)d_in[6];
    const float* k_U = (const float*)d_in[7];
    const float* k_V = (const float*)d_in[8];
    const float* k_b = (const float*)d_in[9];
    const float* v_U = (const float*)d_in[10];
    const float* v_V = (const float*)d_in[11];
    const float* v_b = (const float*)d_in[12];
    const float* out_U = (const float*)d_in[13];
    const float* out_V = (const float*)d_in[14];
    const float* out_b = (const float*)d_in[15];
    const float* ln2_w = (const float*)d_in[16];
    const float* ln2_b = (const float*)d_in[17];
    const float* fc1_U = (const float*)d_in[18];
    const float* fc1_V = (const float*)d_in[19];
    const float* fc1_b = (const float*)d_in[20];
    const float* fc2_U = (const float*)d_in[21];
    const float* fc2_V = (const float*)d_in[22];
    const float* fc2_b = (const float*)d_in[23];
    float* out = (float*)d_out;

    __half *x16_, *Pq_, *Pk_, *Pv_, *Q16_, *K16_, *V16_, *Y16_, *t16_, *a16_, *w16_, *wv16_;
    float *h_;
    cudaGetSymbolAddress((void**)&x16_,  g_x16);
    cudaGetSymbolAddress((void**)&Pq_,   g_Pq);
    cudaGetSymbolAddress((void**)&Pk_,   g_Pk);
    cudaGetSymbolAddress((void**)&Pv_,   g_Pv);
    cudaGetSymbolAddress((void**)&Q16_,  g_Q16);
    cudaGetSymbolAddress((void**)&K16_,  g_K16);
    cudaGetSymbolAddress((void**)&V16_,  g_V16);
    cudaGetSymbolAddress((void**)&Y16_,  g_Y16);
    cudaGetSymbolAddress((void**)&t16_,  g_t16);
    cudaGetSymbolAddress((void**)&h_,    g_h);
    cudaGetSymbolAddress((void**)&a16_,  g_a16);
    cudaGetSymbolAddress((void**)&w16_,  g_w16);
    cudaGetSymbolAddress((void**)&wv16_, g_wv16);

    cudaFuncSetAttribute(gemm16_qkv,      cudaFuncAttributeMaxDynamicSharedMemorySize, GEMM16_SMEM(128));
    cudaFuncSetAttribute(gemm16<3, 64>,   cudaFuncAttributeMaxDynamicSharedMemorySize, GEMM16_SMEM(64));
    cudaFuncSetAttribute(gemm16<1, 128>,  cudaFuncAttributeMaxDynamicSharedMemorySize, GEMM16_SMEM(128));
    cudaFuncSetAttribute(gemm16<2, 128>,  cudaFuncAttributeMaxDynamicSharedMemorySize, GEMM16_SMEM(128));

    // 0) weight conversion
    conv_w<<<7680, 256>>>(q_U, k_U, v_U, out_U, out_V, fc1_U, fc1_V, fc2_U, fc2_V, w16_);
    {
        dim3 g(Hh, 3);
        conv_v<<<g, 256>>>(q_V, k_V, v_V, wv16_);
    }

    // 1) x = LN1(hidden) -> fp16
    ln_kernel<<<BS, 256>>>(hidden, ln1_w, ln1_b, x16_);

    // 2) Pq/Pk/Pv = x @ {q,k,v}_U  (fp16 out)
    {
        dim3 g(12, BS / 128);
        gemm16_qkv<<<g, 256, GEMM16_SMEM(128)>>>(x16_, w16_, Pq_, Pk_, Pv_);
    }

    // 3) head expansion (tensor cores)
    {
        dim3 g(BS / 64, Hh, 3);
        head_proj3<<<g, 128>>>(Pq_, Pk_, Pv_, wv16_, q_b, k_b, v_b, Q16_, K16_, V16_);
    }

    // 4) causal attention -> fp16 Y
    {
        dim3 g(Ss / 128, Bb * Hh);
        attn_f16<<<g, 256>>>(Q16_, K16_, V16_, Y16_);
    }

    // 5) h = hidden + (Y @ out_U) @ out_V + out_b
    {
        dim3 g1(RFC / 64, BS / 128);
        gemm16<3, 64><<<g1, 256, GEMM16_SMEM(64)>>>(Y16_, w16_ + WT_OU, t16_, BS, RFC, Dm, nullptr, nullptr);
        dim3 g2(Dm / 128, BS / 128);
        gemm16<1, 128><<<g2, 256, GEMM16_SMEM(128)>>>(t16_, w16_ + WT_OV, h_, BS, Dm, RFC, out_b, hidden);
    }

    // 6) z = LN2(h) -> fp16
    ln_kernel<<<BS, 256>>>(h_, ln2_w, ln2_b, x16_);

    // 7) a = gelu((z @ fc1_U) @ fc1_V + fc1_b) -> fp16
    {
        dim3 g1(RFC / 64, BS / 128);
        gemm16<3, 64><<<g1, 256, GEMM16_SMEM(64)>>>(x16_, w16_ + WT_F1U, t16_, BS, RFC, Dm, nullptr, nullptr);
        dim3 g2(Ii / 128, BS / 128);
        gemm16<2, 128><<<g2, 256, GEMM16_SMEM(128)>>>(t16_, w16_ + WT_F1V, a16_, BS, Ii, RFC, fc1_b, nullptr);
    }

    // 8) out = h + (a @ fc2_U) @ fc2_V + fc2_b
    {
        dim3 g1(RFC / 64, BS / 128);
        gemm16<3, 64><<<g1, 256, GEMM16_SMEM(64)>>>(a16_, w16_ + WT_F2U, t16_, BS, RFC, Ii, nullptr, nullptr);
        dim3 g2(Dm / 128, BS / 128);
        gemm16<1, 128><<<g2, 256, GEMM16_SMEM(128)>>>(t16_, w16_ + WT_F2V, out, BS, Dm, RFC, fc2_b, h_);
    }
}

// round 14
// speedup vs baseline: 1.8781x; 1.0557x over previous
#include <cuda_runtime.h>
#include <cuda_fp16.h>
#include <math.h>
#include <stdint.h>

// Problem dims (fixed)
#define Dm   1024
#define Hh   16
#define DH   64
#define Rr   32
#define Bb   2
#define Ss   2048
#define BS   (Bb*Ss)        // 4096
#define HR   (Hh*Rr)        // 512
#define Ii   4096
#define RFC  512

// ---------------- scratch ----------------
__device__ __half g_x16[BS*Dm];
__device__ __half g_Pq[BS*HR];
__device__ __half g_Pk[BS*HR];
__device__ __half g_Pv[BS*HR];
__device__ __half g_Q16[Bb*Hh*Ss*DH];
__device__ __half g_K16[Bb*Hh*Ss*DH];
__device__ __half g_V16[Bb*Hh*DH*Ss];      // V TRANSPOSED: [b,h,dh,s]
__device__ __half g_Y16[BS*Dm];
__device__ __half g_t16[BS*RFC];
__device__ float  g_h  [BS*Dm];
__device__ __half g_a16[BS*Ii];
__device__ __half g_w16[7864320];          // fp16 weights, TRANSPOSED [N][K]
__device__ __half g_wv16[3*Hh*DH*Rr];      // q/k/v head weights, per-head TRANSPOSED [e][r]

// transposed-weight offsets (halves)
#define WT_QU   0
#define WT_KU   524288
#define WT_VU   1048576
#define WT_OU   1572864
#define WT_OV   2097152
#define WT_F1U  2621440
#define WT_F1V  3145728
#define WT_F2U  5242880
#define WT_F2V  7340032

// ---------------- PTX helpers ----------------
__device__ __forceinline__ void cp16(uint32_t saddr, const void* gptr) {
    asm volatile("cp.async.cg.shared.global [%0], [%1], 16;" :: "r"(saddr), "l"(gptr));
}
__device__ __forceinline__ uint32_t smem_u32(const void* p) {
    return (uint32_t)__cvta_generic_to_shared(p);
}
__device__ __forceinline__ void ldsm4(uint32_t& r0, uint32_t& r1, uint32_t& r2, uint32_t& r3,
                                      uint32_t addr) {
    asm volatile("ldmatrix.sync.aligned.m8n8.x4.shared.b16 {%0,%1,%2,%3}, [%4];"
                 : "=r"(r0), "=r"(r1), "=r"(r2), "=r"(r3) : "r"(addr));
}
__device__ __forceinline__ void mma_f16(float* d, const uint32_t* a, uint32_t b0, uint32_t b1) {
    asm volatile(
        "mma.sync.aligned.m16n8k16.row.col.f32.f16.f16.f32 "
        "{%0,%1,%2,%3}, {%4,%5,%6,%7}, {%8,%9}, {%0,%1,%2,%3};"
        : "+f"(d[0]), "+f"(d[1]), "+f"(d[2]), "+f"(d[3])
        : "r"(a[0]), "r"(a[1]), "r"(a[2]), "r"(a[3]), "r"(b0), "r"(b1));
}
__device__ __forceinline__ uint32_t packh2(float a, float b) {
    __half2 h = __floats2half2_rn(a, b);
    return *(uint32_t*)&h;
}
__device__ __forceinline__ float gelu_tanh(float x) {
    float u = 0.7978845608f * (x + 0.044715f * x * x * x);
    float t = 1.f - 2.f / (__expf(2.f * u) + 1.f);
    return 0.5f * x * (1.f + t);
}

// ---------------- weight convert + transpose: fp32 [K][N] -> fp16 [N][K] ----------------
__global__ void __launch_bounds__(256) conv_w(
    const float* s0, const float* s1, const float* s2, const float* s3, const float* s4,
    const float* s5, const float* s6, const float* s7, const float* s8, __half* dst)
{
    const int Ksz[9]  = {1024,1024,1024,1024,512,1024,512,4096,512};
    const int Nsz[9]  = {512,512,512,512,1024,512,4096,512,1024};
    const int toff[9] = {0,512,1024,1536,2048,2560,3072,5120,7168};
    const int doff[9] = {WT_QU,WT_KU,WT_VU,WT_OU,WT_OV,WT_F1U,WT_F1V,WT_F2U,WT_F2V};
    int bx = blockIdx.x;
    int i = 0;
    #pragma unroll
    for (int j = 1; j < 9; j++) if (bx >= toff[j]) i = j;
    const float* src = (i==0)?s0:(i==1)?s1:(i==2)?s2:(i==3)?s3:(i==4)?s4:(i==5)?s5:(i==6)?s6:(i==7)?s7:s8;
    int local = bx - toff[i];
    int K = Ksz[i], N = Nsz[i];
    int ntile = N >> 5;
    int tk = local / ntile, tn = local % ntile;

    __shared__ float tsm[32][33];
    int cc = threadIdx.x & 31, r0 = threadIdx.x >> 5;
    #pragma unroll
    for (int j = 0; j < 4; j++) {
        int r = r0 + j * 8;
        tsm[r][cc] = src[(size_t)(tk * 32 + r) * N + tn * 32 + cc];
    }
    __syncthreads();
    __half* d = dst + doff[i];
    #pragma unroll
    for (int j = 0; j < 4; j++) {
        int r = r0 + j * 8;
        d[(size_t)(tn * 32 + r) * K + tk * 32 + cc] = __float2half(tsm[cc][r]);
    }
}

// ---------------- per-head q_V/k_V/v_V: fp32 [h][r][e] -> fp16 [z][h][e][r] ----------------
__global__ void __launch_bounds__(256) conv_v(
    const float* vq, const float* vk, const float* vv, __half* dst)
{
    int h = blockIdx.x, z = blockIdx.y;
    const float* src = ((z == 0) ? vq : (z == 1) ? vk : vv) + (size_t)h * Rr * DH;
    __half* d = dst + ((size_t)(z * Hh + h)) * DH * Rr;
    for (int i = threadIdx.x; i < Rr * DH; i += 256) {
        int r = i / DH, e = i % DH;
        d[e * Rr + r] = __float2half(src[i]);
    }
}

// ---------------- LayerNorm (fp32 in, fp16 out), vectorized ----------------
__global__ void ln_kernel(const float* __restrict__ in, const float* __restrict__ w,
                          const float* __restrict__ b, __half* __restrict__ out) {
    __shared__ float red[8];
    int row = blockIdx.x;
    int t = threadIdx.x;
    const float* x = in + (size_t)row * Dm;

    float4 v = *(const float4*)(x + t * 4);
    float s = v.x + v.y + v.z + v.w;
    #pragma unroll
    for (int o = 16; o; o >>= 1) s += __shfl_xor_sync(0xffffffffu, s, o);
    if ((t & 31) == 0) red[t >> 5] = s;
    __syncthreads();
    float tot = 0.f;
    #pragma unroll
    for (int i = 0; i < 8; i++) tot += red[i];
    float mean = tot * (1.0f / Dm);
    __syncthreads();

    float dx = v.x - mean, dy = v.y - mean, dz = v.z - mean, dw = v.w - mean;
    float vs = dx * dx + dy * dy + dz * dz + dw * dw;
    #pragma unroll
    for (int o = 16; o; o >>= 1) vs += __shfl_xor_sync(0xffffffffu, vs, o);
    if ((t & 31) == 0) red[t >> 5] = vs;
    __syncthreads();
    float vtot = 0.f;
    #pragma unroll
    for (int i = 0; i < 8; i++) vtot += red[i];
    float rstd = rsqrtf(vtot * (1.0f / Dm) + 1e-5f);

    float4 wv = *(const float4*)(w + t * 4);
    float4 bv = *(const float4*)(b + t * 4);
    uint32_t lo = packh2(dx * rstd * wv.x + bv.x, dy * rstd * wv.y + bv.y);
    uint32_t hi = packh2(dz * rstd * wv.z + bv.z, dw * rstd * wv.w + bv.w);
    *(uint2*)(out + (size_t)row * Dm + t * 4) = make_uint2(lo, hi);
}

// ---------------- FP16 GEMM: single-sync double-buffered mainloop ----------------
// EPI: 0 = fp32 out plain; 1 = fp32 out + bias + res; 2 = fp16 out gelu(v+bias); 3 = fp16 out plain
#define BKh 64
#define AKp 72
#define GEMM16_SMEM(BN) ((2 * 128 * AKp + 2 * (BN) * AKp) * 2)

template<int EPI, int BN>
__device__ __forceinline__ void gemm16_core(
    const __half* __restrict__ A, const __half* __restrict__ Bt, void* __restrict__ Cv,
    int M, int N, int K, const float* __restrict__ bias, const float* __restrict__ res,
    int m0, int n0)
{
    constexpr int BM = 128;
    constexpr int WM_ = (BN == 128) ? 2 : 4;
    constexpr int WTM = BM / WM_;
    constexpr int MT = WTM / 16;
    constexpr int NT = 4;

    extern __shared__ __half smh[];
    __half* As = smh;
    __half* Bs = smh + 2 * BM * AKp;

    int tid = threadIdx.x;
    int w = tid >> 5, lane = tid & 31;
    int lr = lane >> 2, lc = lane & 3;
    int wm = (w % WM_) * WTM;
    int wn = (w / WM_) * 32;
    int fr = lane & 15;
    int fcsel = (lane >> 4) * 8;

    float acc[MT][NT][4];
    #pragma unroll
    for (int mt = 0; mt < MT; mt++)
        #pragma unroll
        for (int nt = 0; nt < NT; nt++)
            #pragma unroll
            for (int i = 0; i < 4; i++) acc[mt][nt][i] = 0.f;

    const __half* Ag = A + (size_t)m0 * K;
    const __half* Bg = Bt + (size_t)n0 * K;

    auto loadTile = [&](int kt, int buf) {
        __half* Abuf = As + buf * BM * AKp;
        __half* Bbuf = Bs + buf * BN * AKp;
        #pragma unroll
        for (int i = 0; i < 4; i++) {
            int q = tid + i * 256;
            int r = q >> 3, c = q & 7;
            cp16(smem_u32(Abuf + r * AKp + c * 8), Ag + (size_t)r * K + kt * BKh + c * 8);
        }
        #pragma unroll
        for (int i = 0; i < BN / 32; i++) {
            int q = tid + i * 256;
            int r = q >> 3, c = q & 7;
            cp16(smem_u32(Bbuf + r * AKp + c * 8), Bg + (size_t)r * K + kt * BKh + c * 8);
        }
        asm volatile("cp.async.commit_group;");
    };

    int NTILES = K / BKh;
    loadTile(0, 0);
    for (int kt = 0; kt < NTILES; kt++) {
        int buf = kt & 1;
        asm volatile("cp.async.wait_group 0;");
        __syncthreads();
        if (kt + 1 < NTILES) loadTile(kt + 1, buf ^ 1);

        const __half* Abuf = As + buf * BM * AKp;
        const __half* Bbuf = Bs + buf * BN * AKp;

        #pragma unroll
        for (int ks = 0; ks < 4; ks++) {
            int kb = ks * 16;
            uint32_t af[MT][4], bf[NT][2];
            #pragma unroll
            for (int mt = 0; mt < MT; mt++)
                ldsm4(af[mt][0], af[mt][1], af[mt][2], af[mt][3],
                      smem_u32(Abuf + (wm + mt * 16 + fr) * AKp + kb + fcsel));
            #pragma unroll
            for (int ntp = 0; ntp < 2; ntp++) {
                uint32_t r0, r1, r2, r3;
                ldsm4(r0, r1, r2, r3,
                      smem_u32(Bbuf + (wn + ntp * 16 + fr) * AKp + kb + fcsel));
                bf[2 * ntp][0] = r0; bf[2 * ntp][1] = r2;
                bf[2 * ntp + 1][0] = r1; bf[2 * ntp + 1][1] = r3;
            }
            #pragma unroll
            for (int mt = 0; mt < MT; mt++)
                #pragma unroll
                for (int nt = 0; nt < NT; nt++)
                    mma_f16(acc[mt][nt], af[mt], bf[nt][0], bf[nt][1]);
        }
    }

    #pragma unroll
    for (int mt = 0; mt < MT; mt++) {
        #pragma unroll
        for (int hh = 0; hh < 2; hh++) {
            int row = m0 + wm + mt * 16 + lr + hh * 8;
            #pragma unroll
            for (int nt = 0; nt < NT; nt++) {
                int col = n0 + wn + nt * 8 + 2 * lc;
                float v0 = acc[mt][nt][2 * hh + 0];
                float v1 = acc[mt][nt][2 * hh + 1];
                if (EPI == 0) {
                    *(float2*)&((float*)Cv)[(size_t)row * N + col] = make_float2(v0, v1);
                } else if (EPI == 1) {
                    const float* rr = res + (size_t)row * N + col;
                    v0 += bias[col] + rr[0];
                    v1 += bias[col + 1] + rr[1];
                    *(float2*)&((float*)Cv)[(size_t)row * N + col] = make_float2(v0, v1);
                } else if (EPI == 2) {
                    v0 = gelu_tanh(v0 + bias[col]);
                    v1 = gelu_tanh(v1 + bias[col + 1]);
                    *(uint32_t*)&((__half*)Cv)[(size_t)row * N + col] = packh2(v0, v1);
                } else {
                    *(uint32_t*)&((__half*)Cv)[(size_t)row * N + col] = packh2(v0, v1);
                }
            }
        }
    }
}

template<int EPI, int BN>
__global__ void __launch_bounds__(256, 2) gemm16(
    const __half* __restrict__ A, const __half* __restrict__ Bt, void* __restrict__ C,
    int M, int N, int K, const float* __restrict__ bias, const float* __restrict__ res)
{
    gemm16_core<EPI, BN>(A, Bt, C, M, N, K, bias, res, blockIdx.y * 128, blockIdx.x * BN);
}

__global__ void __launch_bounds__(256, 2) gemm16_qkv(
    const __half* __restrict__ A, const __half* __restrict__ wt,
    __half* __restrict__ C0, __half* __restrict__ C1, __half* __restrict__ C2)
{
    int sel = blockIdx.x >> 2, nb = blockIdx.x & 3;
    const __half* Bt = wt + (sel == 0 ? WT_QU : sel == 1 ? WT_KU : WT_VU);
    __half* C = (sel == 0) ? C0 : (sel == 1) ? C1 : C2;
    gemm16_core<3, 128>(A, Bt, C, BS, HR, Dm, nullptr, nullptr, blockIdx.y * 128, nb * 128);
}

// ---------------- head_proj v3 (tensor cores, unchanged) ----------------
#define HPd 40
#define OTd 72

__global__ void __launch_bounds__(128) head_proj3(
    const __half* __restrict__ Pq, const __half* __restrict__ Pk, const __half* __restrict__ Pv,
    const __half* __restrict__ wv,
    const float* __restrict__ bq, const float* __restrict__ bk, const float* __restrict__ bv,
    __half* __restrict__ Oq, __half* __restrict__ Ok, __half* __restrict__ Ov)
{
    __shared__ __half Pt[64 * HPd];
    __shared__ __half Wt[64 * HPd];
    __shared__ __half Ot[64 * OTd];

    int z = blockIdx.z, h = blockIdx.y;
    int s0 = blockIdx.x * 64;
    const __half* P  = (z == 0) ? Pq : (z == 1) ? Pk : Pv;
    const float* bi  = ((z == 0) ? bq : (z == 1) ? bk : bv) + h * DH;
    __half* O        = (z == 0) ? Oq : (z == 1) ? Ok : Ov;
    const __half* W  = wv + ((size_t)(z * Hh + h)) * DH * Rr;

    int tid = threadIdx.x;
    int w = tid >> 5, lane = tid & 31;
    int lr = lane >> 2, lc = lane & 3;
    int fr = lane & 15;
    int fcsel = (lane >> 4) * 8;

    #pragma unroll
    for (int i = 0; i < 2; i++) {
        int idx = tid + i * 128;
        int r = idx >> 2, c = idx & 3;
        cp16(smem_u32(Pt + r * HPd + c * 8), P + (size_t)(s0 + r) * HR + h * Rr + c * 8);
        cp16(smem_u32(Wt + r * HPd + c * 8), W + (size_t)r * Rr + c * 8);
    }
    asm volatile("cp.async.commit_group;");
    asm volatile("cp.async.wait_group 0;");
    __syncthreads();

    uint32_t af[2][4];
    #pragma unroll
    for (int k = 0; k < 2; k++)
        ldsm4(af[k][0], af[k][1], af[k][2], af[k][3],
              smem_u32(Pt + (w * 16 + fr) * HPd + k * 16 + fcsel));

    float acc[8][4];
    #pragma unroll
    for (int nt = 0; nt < 8; nt++)
        #pragma unroll
        for (int i = 0; i < 4; i++) acc[nt][i] = 0.f;

    #pragma unroll
    for (int k = 0; k < 2; k++) {
        #pragma unroll
        for (int t = 0; t < 4; t++) {
            uint32_t r0, r1, r2, r3;
            ldsm4(r0, r1, r2, r3,
                  smem_u32(Wt + (t * 16 + fr) * HPd + k * 16 + fcsel));
            mma_f16(acc[2 * t],     af[k], r0, r2);
            mma_f16(acc[2 * t + 1], af[k], r1, r3);
        }
    }

    if (z < 2) {
        int bsr0 = s0 + w * 16 + lr;
        #pragma unroll
        for (int hh = 0; hh < 2; hh++) {
            int bs = bsr0 + hh * 8;
            int b = bs >> 11, s = bs & 2047;
            __half* yb = O + (((size_t)(b * Hh + h)) * Ss + s) * DH;
            #pragma unroll
            for (int nt = 0; nt < 8; nt++) {
                int e = nt * 8 + 2 * lc;
                *(uint32_t*)(yb + e) = packh2(acc[nt][2 * hh] + bi[e],
                                              acc[nt][2 * hh + 1] + bi[e + 1]);
            }
        }
    } else {
        int sr0 = w * 16 + lr;
        #pragma unroll
        for (int hh = 0; hh < 2; hh++) {
            int sl = sr0 + hh * 8;
            #pragma unroll
            for (int nt = 0; nt < 8; nt++) {
                int e = nt * 8 + 2 * lc;
                Ot[e * OTd + sl]       = __float2half(acc[nt][2 * hh] + bi[e]);
                Ot[(e + 1) * OTd + sl] = __float2half(acc[nt][2 * hh + 1] + bi[e + 1]);
            }
        }
        __syncthreads();
        int b = s0 >> 11, sbase = s0 & 2047;
        __half* ob = O + ((size_t)(b * Hh + h)) * DH * Ss + sbase;
        #pragma unroll
        for (int i = 0; i < 4; i++) {
            int idx = tid + i * 128;
            int e = idx >> 3, c = idx & 7;
            *(uint4*)(ob + (size_t)e * Ss + c * 8) = *(uint4*)(Ot + e * OTd + c * 8);
        }
    }
}

// ---------------- FP16 attention: double-buffered K/V, single sync/tile ----------------
#define APd 72
// halves: Ks[2][64*APd] + Vt[2][64*APd] + Ps[128*APd]
#define ATTN16_SMEM ((4 * 64 * APd + 128 * APd) * 2)   // 55296 B

__global__ void __launch_bounds__(256, 2) attn_f16(
    const __half* __restrict__ Q, const __half* __restrict__ K,
    const __half* __restrict__ V, __half* __restrict__ Y)
{
    extern __shared__ __half smh[];
    __half* KsB[2] = { smh,               smh + 64 * APd };
    __half* VtB[2] = { smh + 2 * 64 * APd, smh + 3 * 64 * APd };
    __half* Ps     =   smh + 4 * 64 * APd;

    int bh = blockIdx.y;
    int qblk = gridDim.x - 1 - blockIdx.x;
    int q0 = qblk * 128;
    int tid = threadIdx.x;
    int w = tid >> 5, lane = tid & 31;
    int lr = lane >> 2, lc = lane & 3;
    int wq = w * 16;
    int fr = lane & 15;
    int fcsel = (lane >> 4) * 8;

    uint32_t qf[4][4];
    const __half* Qb = Q + ((size_t)bh * Ss + q0 + wq) * DH;
    #pragma unroll
    for (int ks = 0; ks < 4; ks++) {
        qf[ks][0] = *(const uint32_t*)(Qb + (size_t)lr * DH + ks * 16 + 2 * lc);
        qf[ks][1] = *(const uint32_t*)(Qb + (size_t)(lr + 8) * DH + ks * 16 + 2 * lc);
        qf[ks][2] = *(const uint32_t*)(Qb + (size_t)lr * DH + ks * 16 + 8 + 2 * lc);
        qf[ks][3] = *(const uint32_t*)(Qb + (size_t)(lr + 8) * DH + ks * 16 + 8 + 2 * lc);
    }

    const __half* Kg = K + (size_t)bh * Ss * DH;
    const __half* Vg = V + (size_t)bh * DH * Ss;

    auto loadTile = [&](int kt, int buf) {
        __half* Ks = KsB[buf];
        __half* Vt = VtB[buf];
        #pragma unroll
        for (int i = 0; i < 2; i++) {
            int idx = tid + i * 256;
            int r = idx >> 3, c = idx & 7;
            cp16(smem_u32(Ks + r * APd + c * 8), Kg + (size_t)(kt * 64 + r) * DH + c * 8);
            cp16(smem_u32(Vt + r * APd + c * 8), Vg + (size_t)r * Ss + kt * 64 + c * 8);
        }
        asm volatile("cp.async.commit_group;");
    };

    float o[8][4];
    #pragma unroll
    for (int nt = 0; nt < 8; nt++)
        #pragma unroll
        for (int i = 0; i < 4; i++) o[nt][i] = 0.f;
    float m0 = -1e30f, m1 = -1e30f, l0 = 0.f, l1 = 0.f;
    const float scale = 0.125f;

    int ktmax = 2 * qblk + 1;
    loadTile(0, 0);
    for (int kt = 0; kt <= ktmax; kt++) {
        int buf = kt & 1;
        asm volatile("cp.async.wait_group 0;");   // load kt done (1 group in flight)
        __syncthreads();                          // readers of buf^1 (tile kt-1) done
        if (kt < ktmax) loadTile(kt + 1, buf ^ 1);
        __half* Ks = KsB[buf];
        __half* Vt = VtB[buf];

        float s[8][4];
        #pragma unroll
        for (int nt = 0; nt < 8; nt++)
            #pragma unroll
            for (int i = 0; i < 4; i++) s[nt][i] = 0.f;
        #pragma unroll
        for (int ks = 0; ks < 4; ks++) {
            #pragma unroll
            for (int ntp = 0; ntp < 4; ntp++) {
                uint32_t r0, r1, r2, r3;
                ldsm4(r0, r1, r2, r3,
                      smem_u32(Ks + (ntp * 16 + fr) * APd + ks * 16 + fcsel));
                mma_f16(s[2 * ntp],     qf[ks], r0, r2);
                mma_f16(s[2 * ntp + 1], qf[ks], r1, r3);
            }
        }

        bool diag = (kt >= 2 * qblk);
        int r0_ = q0 + wq + lr, r1_ = r0_ + 8;
        int kc0 = kt * 64;
        #pragma unroll
        for (int nt = 0; nt < 8; nt++) {
            int c0 = kc0 + nt * 8 + 2 * lc, c1 = c0 + 1;
            s[nt][0] = (diag && c0 > r0_) ? -1e30f : s[nt][0] * scale;
            s[nt][1] = (diag && c1 > r0_) ? -1e30f : s[nt][1] * scale;
            s[nt][2] = (diag && c0 > r1_) ? -1e30f : s[nt][2] * scale;
            s[nt][3] = (diag && c1 > r1_) ? -1e30f : s[nt][3] * scale;
        }

        float mx0 = -1e30f, mx1 = -1e30f;
        #pragma unroll
        for (int nt = 0; nt < 8; nt++) {
            mx0 = fmaxf(mx0, fmaxf(s[nt][0], s[nt][1]));
            mx1 = fmaxf(mx1, fmaxf(s[nt][2], s[nt][3]));
        }
        mx0 = fmaxf(mx0, __shfl_xor_sync(0xffffffffu, mx0, 1));
        mx0 = fmaxf(mx0, __shfl_xor_sync(0xffffffffu, mx0, 2));
        mx1 = fmaxf(mx1, __shfl_xor_sync(0xffffffffu, mx1, 1));
        mx1 = fmaxf(mx1, __shfl_xor_sync(0xffffffffu, mx1, 2));
        float mn0 = fmaxf(m0, mx0), mn1 = fmaxf(m1, mx1);
        float c0f = __expf(m0 - mn0), c1f = __expf(m1 - mn1);
        l0 *= c0f; l1 *= c1f;
        #pragma unroll
        for (int nt = 0; nt < 8; nt++) {
            o[nt][0] *= c0f; o[nt][1] *= c0f;
            o[nt][2] *= c1f; o[nt][3] *= c1f;
        }
        m0 = mn0; m1 = mn1;

        #pragma unroll
        for (int nt = 0; nt < 8; nt++) {
            int c0 = nt * 8 + 2 * lc;
            float p00 = __expf(s[nt][0] - mn0);
            float p01 = __expf(s[nt][1] - mn0);
            float p10 = __expf(s[nt][2] - mn1);
            float p11 = __expf(s[nt][3] - mn1);
            l0 += p00 + p01; l1 += p10 + p11;
            *(uint32_t*)&Ps[(wq + lr) * APd + c0]     = packh2(p00, p01);
            *(uint32_t*)&Ps[(wq + lr + 8) * APd + c0] = packh2(p10, p11);
        }
        __syncwarp();

        #pragma unroll
        for (int ks = 0; ks < 4; ks++) {
            uint32_t pa[4];
            ldsm4(pa[0], pa[1], pa[2], pa[3],
                  smem_u32(Ps + (wq + fr) * APd + ks * 16 + fcsel));
            #pragma unroll
            for (int ntp = 0; ntp < 4; ntp++) {
                uint32_t r0, r1, r2, r3;
                ldsm4(r0, r1, r2, r3,
                      smem_u32(Vt + (ntp * 16 + fr) * APd + ks * 16 + fcsel));
                mma_f16(o[2 * ntp],     pa, r0, r2);
                mma_f16(o[2 * ntp + 1], pa, r1, r3);
            }
        }
    }

    l0 += __shfl_xor_sync(0xffffffffu, l0, 1);
    l0 += __shfl_xor_sync(0xffffffffu, l0, 2);
    l1 += __shfl_xor_sync(0xffffffffu, l1, 1);
    l1 += __shfl_xor_sync(0xffffffffu, l1, 2);
    float i0 = 1.f / l0, i1 = 1.f / l1;
    int b = bh >> 4, h = bh & 15;
    int row0 = q0 + wq + lr, row1 = row0 + 8;
    __half* y0 = Y + (((size_t)(b * Ss + row0)) * Hh + h) * DH;
    __half* y1 = Y + (((size_t)(b * Ss + row1)) * Hh + h) * DH;
    #pragma unroll
    for (int nt = 0; nt < 8; nt++) {
        int c = nt * 8 + 2 * lc;
        *(uint32_t*)(y0 + c) = packh2(o[nt][0] * i0, o[nt][1] * i0);
        *(uint32_t*)(y1 + c) = packh2(o[nt][2] * i1, o[nt][3] * i1);
    }
}

// ---------------- launch ----------------
extern "C" void kernel_launch(void* const* d_in, const int* in_sizes, int n_in,
                              void* d_out, int out_size) {
    const float* hidden = (const float*)d_in[0];
    const float* ln1_w = (const float*)d_in[2];
    const float* ln1_b = (const float*)d_in[3];
    const float* q_U = (const float*)d_in[4];
    const float* q_V = (const float*)d_in[5];
    const float* q_b = (const float*)d_in[6];
    const float* k_U = (const float*)d_in[7];
    const float* k_V = (const float*)d_in[8];
    const float* k_b = (const float*)d_in[9];
    const float* v_U = (const float*)d_in[10];
    const float* v_V = (const float*)d_in[11];
    const float* v_b = (const float*)d_in[12];
    const float* out_U = (const float*)d_in[13];
    const float* out_V = (const float*)d_in[14];
    const float* out_b = (const float*)d_in[15];
    const float* ln2_w = (const float*)d_in[16];
    const float* ln2_b = (const float*)d_in[17];
    const float* fc1_U = (const float*)d_in[18];
    const float* fc1_V = (const float*)d_in[19];
    const float* fc1_b = (const float*)d_in[20];
    const float* fc2_U = (const float*)d_in[21];
    const float* fc2_V = (const float*)d_in[22];
    const float* fc2_b = (const float*)d_in[23];
    float* out = (float*)d_out;

    __half *x16_, *Pq_, *Pk_, *Pv_, *Q16_, *K16_, *V16_, *Y16_, *t16_, *a16_, *w16_, *wv16_;
    float *h_;
    cudaGetSymbolAddress((void**)&x16_,  g_x16);
    cudaGetSymbolAddress((void**)&Pq_,   g_Pq);
    cudaGetSymbolAddress((void**)&Pk_,   g_Pk);
    cudaGetSymbolAddress((void**)&Pv_,   g_Pv);
    cudaGetSymbolAddress((void**)&Q16_,  g_Q16);
    cudaGetSymbolAddress((void**)&K16_,  g_K16);
    cudaGetSymbolAddress((void**)&V16_,  g_V16);
    cudaGetSymbolAddress((void**)&Y16_,  g_Y16);
    cudaGetSymbolAddress((void**)&t16_,  g_t16);
    cudaGetSymbolAddress((void**)&h_,    g_h);
    cudaGetSymbolAddress((void**)&a16_,  g_a16);
    cudaGetSymbolAddress((void**)&w16_,  g_w16);
    cudaGetSymbolAddress((void**)&wv16_, g_wv16);

    cudaFuncSetAttribute(gemm16_qkv,      cudaFuncAttributeMaxDynamicSharedMemorySize, GEMM16_SMEM(128));
    cudaFuncSetAttribute(gemm16<3, 64>,   cudaFuncAttributeMaxDynamicSharedMemorySize, GEMM16_SMEM(64));
    cudaFuncSetAttribute(gemm16<1, 128>,  cudaFuncAttributeMaxDynamicSharedMemorySize, GEMM16_SMEM(128));
    cudaFuncSetAttribute(gemm16<2, 128>,  cudaFuncAttributeMaxDynamicSharedMemorySize, GEMM16_SMEM(128));
    cudaFuncSetAttribute(attn_f16,        cudaFuncAttributeMaxDynamicSharedMemorySize, ATTN16_SMEM);

    // 0) weight conversion
    conv_w<<<7680, 256>>>(q_U, k_U, v_U, out_U, out_V, fc1_U, fc1_V, fc2_U, fc2_V, w16_);
    {
        dim3 g(Hh, 3);
        conv_v<<<g, 256>>>(q_V, k_V, v_V, wv16_);
    }

    // 1) x = LN1(hidden) -> fp16
    ln_kernel<<<BS, 256>>>(hidden, ln1_w, ln1_b, x16_);

    // 2) Pq/Pk/Pv = x @ {q,k,v}_U  (fp16 out)
    {
        dim3 g(12, BS / 128);
        gemm16_qkv<<<g, 256, GEMM16_SMEM(128)>>>(x16_, w16_, Pq_, Pk_, Pv_);
    }

    // 3) head expansion (tensor cores)
    {
        dim3 g(BS / 64, Hh, 3);
        head_proj3<<<g, 128>>>(Pq_, Pk_, Pv_, wv16_, q_b, k_b, v_b, Q16_, K16_, V16_);
    }

    // 4) causal attention -> fp16 Y
    {
        dim3 g(Ss / 128, Bb * Hh);
        attn_f16<<<g, 256, ATTN16_SMEM>>>(Q16_, K16_, V16_, Y16_);
    }

    // 5) h = hidden + (Y @ out_U) @ out_V + out_b
    {
        dim3 g1(RFC / 64, BS / 128);
        gemm16<3, 64><<<g1, 256, GEMM16_SMEM(64)>>>(Y16_, w16_ + WT_OU, t16_, BS, RFC, Dm, nullptr, nullptr);
        dim3 g2(Dm / 128, BS / 128);
        gemm16<1, 128><<<g2, 256, GEMM16_SMEM(128)>>>(t16_, w16_ + WT_OV, h_, BS, Dm, RFC, out_b, hidden);
    }

    // 6) z = LN2(h) -> fp16
    ln_kernel<<<BS, 256>>>(h_, ln2_w, ln2_b, x16_);

    // 7) a = gelu((z @ fc1_U) @ fc1_V + fc1_b) -> fp16
    {
        dim3 g1(RFC / 64, BS / 128);
        gemm16<3, 64><<<g1, 256, GEMM16_SMEM(64)>>>(x16_, w16_ + WT_F1U, t16_, BS, RFC, Dm, nullptr, nullptr);
        dim3 g2(Ii / 128, BS / 128);
        gemm16<2, 128><<<g2, 256, GEMM16_SMEM(128)>>>(t16_, w16_ + WT_F1V, a16_, BS, Ii, RFC, fc1_b, nullptr);
    }

    // 8) out = h + (a @ fc2_U) @ fc2_V + fc2_b
    {
        dim3 g1(RFC / 64, BS / 128);
        gemm16<3, 64><<<g1, 256, GEMM16_SMEM(64)>>>(a16_, w16_ + WT_F2U, t16_, BS, RFC, Ii, nullptr, nullptr);
        dim3 g2(Dm / 128, BS / 128);
        gemm16<1, 128><<<g2, 256, GEMM16_SMEM(128)>>>(t16_, w16_ + WT_F2V, out, BS, Dm, RFC, fc2_b, h_);
    }
}

// round 15
// speedup vs baseline: 1.8791x; 1.0005x over previous
#include <cuda_runtime.h>
#include <cuda_fp16.h>
#include <math.h>
#include <stdint.h>

// Problem dims (fixed)
#define Dm   1024
#define Hh   16
#define DH   64
#define Rr   32
#define Bb   2
#define Ss   2048
#define BS   (Bb*Ss)        // 4096
#define HR   (Hh*Rr)        // 512
#define Ii   4096
#define RFC  512

// ---------------- scratch ----------------
__device__ __half g_x16[BS*Dm];
__device__ __half g_Q16[Bb*Hh*Ss*DH];
__device__ __half g_K16[Bb*Hh*Ss*DH];
__device__ __half g_V16[Bb*Hh*DH*Ss];      // V TRANSPOSED: [b,h,dh,s]
__device__ __half g_Y16[BS*Dm];
__device__ __half g_t16[BS*RFC];
__device__ float  g_h  [BS*Dm];
__device__ __half g_a16[BS*Ii];
__device__ __half g_w16[7864320];          // fp16 weights, TRANSPOSED [N][K]
__device__ __half g_wv16[3*Hh*DH*Rr];      // q/k/v head weights, per-head TRANSPOSED [e][r]

// transposed-weight offsets (halves)
#define WT_QU   0
#define WT_KU   524288
#define WT_VU   1048576
#define WT_OU   1572864
#define WT_OV   2097152
#define WT_F1U  2621440
#define WT_F1V  3145728
#define WT_F2U  5242880
#define WT_F2V  7340032

// ---------------- PTX helpers ----------------
__device__ __forceinline__ void cp16(uint32_t saddr, const void* gptr) {
    asm volatile("cp.async.cg.shared.global [%0], [%1], 16;" :: "r"(saddr), "l"(gptr));
}
__device__ __forceinline__ uint32_t smem_u32(const void* p) {
    return (uint32_t)__cvta_generic_to_shared(p);
}
__device__ __forceinline__ void ldsm4(uint32_t& r0, uint32_t& r1, uint32_t& r2, uint32_t& r3,
                                      uint32_t addr) {
    asm volatile("ldmatrix.sync.aligned.m8n8.x4.shared.b16 {%0,%1,%2,%3}, [%4];"
                 : "=r"(r0), "=r"(r1), "=r"(r2), "=r"(r3) : "r"(addr));
}
__device__ __forceinline__ void mma_f16(float* d, const uint32_t* a, uint32_t b0, uint32_t b1) {
    asm volatile(
        "mma.sync.aligned.m16n8k16.row.col.f32.f16.f16.f32 "
        "{%0,%1,%2,%3}, {%4,%5,%6,%7}, {%8,%9}, {%0,%1,%2,%3};"
        : "+f"(d[0]), "+f"(d[1]), "+f"(d[2]), "+f"(d[3])
        : "r"(a[0]), "r"(a[1]), "r"(a[2]), "r"(a[3]), "r"(b0), "r"(b1));
}
__device__ __forceinline__ uint32_t packh2(float a, float b) {
    __half2 h = __floats2half2_rn(a, b);
    return *(uint32_t*)&h;
}
__device__ __forceinline__ float gelu_tanh(float x) {
    float u = 0.7978845608f * (x + 0.044715f * x * x * x);
    float t = 1.f - 2.f / (__expf(2.f * u) + 1.f);
    return 0.5f * x * (1.f + t);
}

// ---------------- weight convert + transpose: fp32 [K][N] -> fp16 [N][K] ----------------
__global__ void __launch_bounds__(256) conv_w(
    const float* s0, const float* s1, const float* s2, const float* s3, const float* s4,
    const float* s5, const float* s6, const float* s7, const float* s8, __half* dst)
{
    const int Ksz[9]  = {1024,1024,1024,1024,512,1024,512,4096,512};
    const int Nsz[9]  = {512,512,512,512,1024,512,4096,512,1024};
    const int toff[9] = {0,512,1024,1536,2048,2560,3072,5120,7168};
    const int doff[9] = {WT_QU,WT_KU,WT_VU,WT_OU,WT_OV,WT_F1U,WT_F1V,WT_F2U,WT_F2V};
    int bx = blockIdx.x;
    int i = 0;
    #pragma unroll
    for (int j = 1; j < 9; j++) if (bx >= toff[j]) i = j;
    const float* src = (i==0)?s0:(i==1)?s1:(i==2)?s2:(i==3)?s3:(i==4)?s4:(i==5)?s5:(i==6)?s6:(i==7)?s7:s8;
    int local = bx - toff[i];
    int K = Ksz[i], N = Nsz[i];
    int ntile = N >> 5;
    int tk = local / ntile, tn = local % ntile;

    __shared__ float tsm[32][33];
    int cc = threadIdx.x & 31, r0 = threadIdx.x >> 5;
    #pragma unroll
    for (int j = 0; j < 4; j++) {
        int r = r0 + j * 8;
        tsm[r][cc] = src[(size_t)(tk * 32 + r) * N + tn * 32 + cc];
    }
    __syncthreads();
    __half* d = dst + doff[i];
    #pragma unroll
    for (int j = 0; j < 4; j++) {
        int r = r0 + j * 8;
        d[(size_t)(tn * 32 + r) * K + tk * 32 + cc] = __float2half(tsm[cc][r]);
    }
}

// ---------------- per-head q_V/k_V/v_V: fp32 [h][r][e] -> fp16 [z][h][e][r] ----------------
__global__ void __launch_bounds__(256) conv_v(
    const float* vq, const float* vk, const float* vv, __half* dst)
{
    int h = blockIdx.x, z = blockIdx.y;
    const float* src = ((z == 0) ? vq : (z == 1) ? vk : vv) + (size_t)h * Rr * DH;
    __half* d = dst + ((size_t)(z * Hh + h)) * DH * Rr;
    for (int i = threadIdx.x; i < Rr * DH; i += 256) {
        int r = i / DH, e = i % DH;
        d[e * Rr + r] = __float2half(src[i]);
    }
}

// ---------------- LayerNorm (fp32 in, fp16 out), vectorized ----------------
__global__ void ln_kernel(const float* __restrict__ in, const float* __restrict__ w,
                          const float* __restrict__ b, __half* __restrict__ out) {
    __shared__ float red[8];
    int row = blockIdx.x;
    int t = threadIdx.x;
    const float* x = in + (size_t)row * Dm;

    float4 v = *(const float4*)(x + t * 4);
    float s = v.x + v.y + v.z + v.w;
    #pragma unroll
    for (int o = 16; o; o >>= 1) s += __shfl_xor_sync(0xffffffffu, s, o);
    if ((t & 31) == 0) red[t >> 5] = s;
    __syncthreads();
    float tot = 0.f;
    #pragma unroll
    for (int i = 0; i < 8; i++) tot += red[i];
    float mean = tot * (1.0f / Dm);
    __syncthreads();

    float dx = v.x - mean, dy = v.y - mean, dz = v.z - mean, dw = v.w - mean;
    float vs = dx * dx + dy * dy + dz * dz + dw * dw;
    #pragma unroll
    for (int o = 16; o; o >>= 1) vs += __shfl_xor_sync(0xffffffffu, vs, o);
    if ((t & 31) == 0) red[t >> 5] = vs;
    __syncthreads();
    float vtot = 0.f;
    #pragma unroll
    for (int i = 0; i < 8; i++) vtot += red[i];
    float rstd = rsqrtf(vtot * (1.0f / Dm) + 1e-5f);

    float4 wv = *(const float4*)(w + t * 4);
    float4 bv = *(const float4*)(b + t * 4);
    uint32_t lo = packh2(dx * rstd * wv.x + bv.x, dy * rstd * wv.y + bv.y);
    uint32_t hi = packh2(dz * rstd * wv.z + bv.z, dw * rstd * wv.w + bv.w);
    *(uint2*)(out + (size_t)row * Dm + t * 4) = make_uint2(lo, hi);
}

// ---------------- FP16 GEMM: single-sync double-buffered mainloop ----------------
// EPI: 0 = fp32 out plain; 1 = fp32 out + bias + res; 2 = fp16 out gelu(v+bias); 3 = fp16 out plain
#define BKh 64
#define AKp 72
#define GEMM16_SMEM(BN) ((2 * 128 * AKp + 2 * (BN) * AKp) * 2)

template<int EPI, int BN>
__device__ __forceinline__ void gemm16_core(
    const __half* __restrict__ A, const __half* __restrict__ Bt, void* __restrict__ Cv,
    int M, int N, int K, const float* __restrict__ bias, const float* __restrict__ res,
    int m0, int n0)
{
    constexpr int BM = 128;
    constexpr int WM_ = (BN == 128) ? 2 : 4;
    constexpr int WTM = BM / WM_;
    constexpr int MT = WTM / 16;
    constexpr int NT = 4;

    extern __shared__ __half smh[];
    __half* As = smh;
    __half* Bs = smh + 2 * BM * AKp;

    int tid = threadIdx.x;
    int w = tid >> 5, lane = tid & 31;
    int lr = lane >> 2, lc = lane & 3;
    int wm = (w % WM_) * WTM;
    int wn = (w / WM_) * 32;
    int fr = lane & 15;
    int fcsel = (lane >> 4) * 8;

    float acc[MT][NT][4];
    #pragma unroll
    for (int mt = 0; mt < MT; mt++)
        #pragma unroll
        for (int nt = 0; nt < NT; nt++)
            #pragma unroll
            for (int i = 0; i < 4; i++) acc[mt][nt][i] = 0.f;

    const __half* Ag = A + (size_t)m0 * K;
    const __half* Bg = Bt + (size_t)n0 * K;

    auto loadTile = [&](int kt, int buf) {
        __half* Abuf = As + buf * BM * AKp;
        __half* Bbuf = Bs + buf * BN * AKp;
        #pragma unroll
        for (int i = 0; i < 4; i++) {
            int q = tid + i * 256;
            int r = q >> 3, c = q & 7;
            cp16(smem_u32(Abuf + r * AKp + c * 8), Ag + (size_t)r * K + kt * BKh + c * 8);
        }
        #pragma unroll
        for (int i = 0; i < BN / 32; i++) {
            int q = tid + i * 256;
            int r = q >> 3, c = q & 7;
            cp16(smem_u32(Bbuf + r * AKp + c * 8), Bg + (size_t)r * K + kt * BKh + c * 8);
        }
        asm volatile("cp.async.commit_group;");
    };

    int NTILES = K / BKh;
    loadTile(0, 0);
    for (int kt = 0; kt < NTILES; kt++) {
        int buf = kt & 1;
        asm volatile("cp.async.wait_group 0;");
        __syncthreads();
        if (kt + 1 < NTILES) loadTile(kt + 1, buf ^ 1);

        const __half* Abuf = As + buf * BM * AKp;
        const __half* Bbuf = Bs + buf * BN * AKp;

        #pragma unroll
        for (int ks = 0; ks < 4; ks++) {
            int kb = ks * 16;
            uint32_t af[MT][4], bf[NT][2];
            #pragma unroll
            for (int mt = 0; mt < MT; mt++)
                ldsm4(af[mt][0], af[mt][1], af[mt][2], af[mt][3],
                      smem_u32(Abuf + (wm + mt * 16 + fr) * AKp + kb + fcsel));
            #pragma unroll
            for (int ntp = 0; ntp < 2; ntp++) {
                uint32_t r0, r1, r2, r3;
                ldsm4(r0, r1, r2, r3,
                      smem_u32(Bbuf + (wn + ntp * 16 + fr) * AKp + kb + fcsel));
                bf[2 * ntp][0] = r0; bf[2 * ntp][1] = r2;
                bf[2 * ntp + 1][0] = r1; bf[2 * ntp + 1][1] = r3;
            }
            #pragma unroll
            for (int mt = 0; mt < MT; mt++)
                #pragma unroll
                for (int nt = 0; nt < NT; nt++)
                    mma_f16(acc[mt][nt], af[mt], bf[nt][0], bf[nt][1]);
        }
    }

    #pragma unroll
    for (int mt = 0; mt < MT; mt++) {
        #pragma unroll
        for (int hh = 0; hh < 2; hh++) {
            int row = m0 + wm + mt * 16 + lr + hh * 8;
            #pragma unroll
            for (int nt = 0; nt < NT; nt++) {
                int col = n0 + wn + nt * 8 + 2 * lc;
                float v0 = acc[mt][nt][2 * hh + 0];
                float v1 = acc[mt][nt][2 * hh + 1];
                if (EPI == 0) {
                    *(float2*)&((float*)Cv)[(size_t)row * N + col] = make_float2(v0, v1);
                } else if (EPI == 1) {
                    const float* rr = res + (size_t)row * N + col;
                    v0 += bias[col] + rr[0];
                    v1 += bias[col + 1] + rr[1];
                    *(float2*)&((float*)Cv)[(size_t)row * N + col] = make_float2(v0, v1);
                } else if (EPI == 2) {
                    v0 = gelu_tanh(v0 + bias[col]);
                    v1 = gelu_tanh(v1 + bias[col + 1]);
                    *(uint32_t*)&((__half*)Cv)[(size_t)row * N + col] = packh2(v0, v1);
                } else {
                    *(uint32_t*)&((__half*)Cv)[(size_t)row * N + col] = packh2(v0, v1);
                }
            }
        }
    }
}

template<int EPI, int BN>
__global__ void __launch_bounds__(256, 2) gemm16(
    const __half* __restrict__ A, const __half* __restrict__ Bt, void* __restrict__ C,
    int M, int N, int K, const float* __restrict__ bias, const float* __restrict__ res)
{
    gemm16_core<EPI, BN>(A, Bt, C, M, N, K, bias, res, blockIdx.y * 128, blockIdx.x * BN);
}

// ---------------- FUSED QKV GEMM + head projection ----------------
// CTA: 128 rows x 64 cols of P (= 2 heads), then per-head P @ wv^T -> Q/K (direct) or V (transposed)
#define FWp 40
#define OTp 136
#define FQ_SMEM ((2*128*AKp + 2*64*AKp + 128*AKp + 2*64*FWp) * 2)   // 84,224 B? compute: (18432+9216+9216+5120)*2 = 83,968

__global__ void __launch_bounds__(256, 2) gemm16_qkv_fused(
    const __half* __restrict__ A, const __half* __restrict__ wt, const __half* __restrict__ wv,
    const float* __restrict__ bq, const float* __restrict__ bk, const float* __restrict__ bv,
    __half* __restrict__ Oq, __half* __restrict__ Ok, __half* __restrict__ Ov)
{
    extern __shared__ __half smh[];
    __half* As = smh;                              // [2][128][AKp]
    __half* Bs = smh + 2 * 128 * AKp;              // [2][64][AKp]
    __half* Pt = smh + 2 * 128 * AKp + 2 * 64 * AKp;  // [128][AKp]
    __half* Wt = Pt + 128 * AKp;                   // [2][64][FWp]
    __half* Ot = As;                               // reuse: [64][OTp] (V path)

    int sel = blockIdx.x >> 3, nb = blockIdx.x & 7;
    int m0 = blockIdx.y * 128;
    const __half* Bt = wt + (sel == 0 ? WT_QU : sel == 1 ? WT_KU : WT_VU) + (size_t)(nb * 64) * Dm;
    const float* bsel = (sel == 0) ? bq : (sel == 1) ? bk : bv;
    __half* O = (sel == 0) ? Oq : (sel == 1) ? Ok : Ov;

    int tid = threadIdx.x;
    int w = tid >> 5, lane = tid & 31;
    int lr = lane >> 2, lc = lane & 3;
    int wm = (w & 3) * 32, wn = (w >> 2) * 32;
    int fr = lane & 15;
    int fcsel = (lane >> 4) * 8;

    // stage wv for both heads (joins first tile's commit group)
    #pragma unroll
    for (int i = 0; i < 2; i++) {
        int idx = tid + i * 256;            // 0..511
        int h01 = idx >> 8;
        int q = idx & 255;
        int e = q >> 2, c = q & 3;
        const __half* Wg = wv + ((size_t)(sel * Hh + nb * 2 + h01)) * DH * Rr;
        cp16(smem_u32(Wt + h01 * 64 * FWp + e * FWp + c * 8), Wg + e * Rr + c * 8);
    }

    float acc[2][4][4];
    #pragma unroll
    for (int mt = 0; mt < 2; mt++)
        #pragma unroll
        for (int nt = 0; nt < 4; nt++)
            #pragma unroll
            for (int i = 0; i < 4; i++) acc[mt][nt][i] = 0.f;

    const __half* Ag = A + (size_t)m0 * Dm;

    auto loadTile = [&](int kt, int buf) {
        __half* Abuf = As + buf * 128 * AKp;
        __half* Bbuf = Bs + buf * 64 * AKp;
        #pragma unroll
        for (int i = 0; i < 4; i++) {
            int q = tid + i * 256;
            int r = q >> 3, c = q & 7;
            cp16(smem_u32(Abuf + r * AKp + c * 8), Ag + (size_t)r * Dm + kt * BKh + c * 8);
        }
        #pragma unroll
        for (int i = 0; i < 2; i++) {
            int q = tid + i * 256;
            int r = q >> 3, c = q & 7;
            cp16(smem_u32(Bbuf + r * AKp + c * 8), Bt + (size_t)r * Dm + kt * BKh + c * 8);
        }
        asm volatile("cp.async.commit_group;");
    };

    int NTILES = Dm / BKh;                 // 16
    loadTile(0, 0);
    for (int kt = 0; kt < NTILES; kt++) {
        int buf = kt & 1;
        asm volatile("cp.async.wait_group 0;");
        __syncthreads();
        if (kt + 1 < NTILES) loadTile(kt + 1, buf ^ 1);

        const __half* Abuf = As + buf * 128 * AKp;
        const __half* Bbuf = Bs + buf * 64 * AKp;

        #pragma unroll
        for (int ks = 0; ks < 4; ks++) {
            int kb = ks * 16;
            uint32_t af[2][4], bf[4][2];
            #pragma unroll
            for (int mt = 0; mt < 2; mt++)
                ldsm4(af[mt][0], af[mt][1], af[mt][2], af[mt][3],
                      smem_u32(Abuf + (wm + mt * 16 + fr) * AKp + kb + fcsel));
            #pragma unroll
            for (int ntp = 0; ntp < 2; ntp++) {
                uint32_t r0, r1, r2, r3;
                ldsm4(r0, r1, r2, r3,
                      smem_u32(Bbuf + (wn + ntp * 16 + fr) * AKp + kb + fcsel));
                bf[2 * ntp][0] = r0; bf[2 * ntp][1] = r2;
                bf[2 * ntp + 1][0] = r1; bf[2 * ntp + 1][1] = r3;
            }
            #pragma unroll
            for (int mt = 0; mt < 2; mt++)
                #pragma unroll
                for (int nt = 0; nt < 4; nt++)
                    mma_f16(acc[mt][nt], af[mt], bf[nt][0], bf[nt][1]);
        }
    }

    // epilogue 1: acc -> Pt (fp16, [128 rows][64 cols], stride AKp)
    #pragma unroll
    for (int mt = 0; mt < 2; mt++) {
        #pragma unroll
        for (int hh = 0; hh < 2; hh++) {
            int rowl = wm + mt * 16 + lr + hh * 8;
            #pragma unroll
            for (int nt = 0; nt < 4; nt++) {
                int coll = wn + nt * 8 + 2 * lc;
                *(uint32_t*)&Pt[rowl * AKp + coll] =
                    packh2(acc[mt][nt][2 * hh], acc[mt][nt][2 * hh + 1]);
            }
        }
    }
    __syncthreads();

    // epilogue 2: per-head projection P[128x32] @ wv^T[64x32]
    #pragma unroll
    for (int h01 = 0; h01 < 2; h01++) {
        int hg = nb * 2 + h01;
        const float* bi = bsel + hg * DH;
        uint32_t af2[2][4];
        #pragma unroll
        for (int k = 0; k < 2; k++)
            ldsm4(af2[k][0], af2[k][1], af2[k][2], af2[k][3],
                  smem_u32(Pt + (w * 16 + fr) * AKp + h01 * 32 + k * 16 + fcsel));

        float a2[8][4];
        #pragma unroll
        for (int nt = 0; nt < 8; nt++)
            #pragma unroll
            for (int i = 0; i < 4; i++) a2[nt][i] = 0.f;

        #pragma unroll
        for (int k = 0; k < 2; k++) {
            #pragma unroll
            for (int t = 0; t < 4; t++) {
                uint32_t r0, r1, r2, r3;
                ldsm4(r0, r1, r2, r3,
                      smem_u32(Wt + h01 * 64 * FWp + (t * 16 + fr) * FWp + k * 16 + fcsel));
                mma_f16(a2[2 * t],     af2[k], r0, r2);
                mma_f16(a2[2 * t + 1], af2[k], r1, r3);
            }
        }

        if (sel < 2) {
            // direct store (b,h,s,e)
            #pragma unroll
            for (int hh = 0; hh < 2; hh++) {
                int bs = m0 + w * 16 + lr + hh * 8;
                int b = bs >> 11, s = bs & 2047;
                __half* yb = O + (((size_t)(b * Hh + hg)) * Ss + s) * DH;
                #pragma unroll
                for (int nt = 0; nt < 8; nt++) {
                    int e = nt * 8 + 2 * lc;
                    *(uint32_t*)(yb + e) = packh2(a2[nt][2 * hh] + bi[e],
                                                  a2[nt][2 * hh + 1] + bi[e + 1]);
                }
            }
        } else {
            // V: smem transpose tile then coalesced (b,h,e,s)
            #pragma unroll
            for (int hh = 0; hh < 2; hh++) {
                int sl = w * 16 + lr + hh * 8;
                #pragma unroll
                for (int nt = 0; nt < 8; nt++) {
                    int e = nt * 8 + 2 * lc;
                    Ot[e * OTp + sl]       = __float2half(a2[nt][2 * hh] + bi[e]);
                    Ot[(e + 1) * OTp + sl] = __float2half(a2[nt][2 * hh + 1] + bi[e + 1]);
                }
            }
            __syncthreads();
            int b = m0 >> 11, sbase = m0 & 2047;
            __half* ob = O + ((size_t)(b * Hh + hg)) * DH * Ss + sbase;
            #pragma unroll
            for (int i = 0; i < 4; i++) {
                int idx = tid + i * 256;        // 1024 chunks: 64 e-rows x 16
                int e = idx >> 4, c = idx & 15;
                *(uint4*)(ob + (size_t)e * Ss + c * 8) = *(uint4*)(Ot + e * OTp + c * 8);
            }
            __syncthreads();                    // Ot reused by next head
        }
    }
}

// ---------------- FP16 attention: double-buffered K/V, single sync/tile ----------------
#define APd 72
#define ATTN16_SMEM ((4 * 64 * APd + 128 * APd) * 2)   // 55296 B

__global__ void __launch_bounds__(256, 2) attn_f16(
    const __half* __restrict__ Q, const __half* __restrict__ K,
    const __half* __restrict__ V, __half* __restrict__ Y)
{
    extern __shared__ __half smh[];
    __half* KsB[2] = { smh,               smh + 64 * APd };
    __half* VtB[2] = { smh + 2 * 64 * APd, smh + 3 * 64 * APd };
    __half* Ps     =   smh + 4 * 64 * APd;

    int bh = blockIdx.y;
    int qblk = gridDim.x - 1 - blockIdx.x;
    int q0 = qblk * 128;
    int tid = threadIdx.x;
    int w = tid >> 5, lane = tid & 31;
    int lr = lane >> 2, lc = lane & 3;
    int wq = w * 16;
    int fr = lane & 15;
    int fcsel = (lane >> 4) * 8;

    uint32_t qf[4][4];
    const __half* Qb = Q + ((size_t)bh * Ss + q0 + wq) * DH;
    #pragma unroll
    for (int ks = 0; ks < 4; ks++) {
        qf[ks][0] = *(const uint32_t*)(Qb + (size_t)lr * DH + ks * 16 + 2 * lc);
        qf[ks][1] = *(const uint32_t*)(Qb + (size_t)(lr + 8) * DH + ks * 16 + 2 * lc);
        qf[ks][2] = *(const uint32_t*)(Qb + (size_t)lr * DH + ks * 16 + 8 + 2 * lc);
        qf[ks][3] = *(const uint32_t*)(Qb + (size_t)(lr + 8) * DH + ks * 16 + 8 + 2 * lc);
    }

    const __half* Kg = K + (size_t)bh * Ss * DH;
    const __half* Vg = V + (size_t)bh * DH * Ss;

    auto loadTile = [&](int kt, int buf) {
        __half* Ks = KsB[buf];
        __half* Vt = VtB[buf];
        #pragma unroll
        for (int i = 0; i < 2; i++) {
            int idx = tid + i * 256;
            int r = idx >> 3, c = idx & 7;
            cp16(smem_u32(Ks + r * APd + c * 8), Kg + (size_t)(kt * 64 + r) * DH + c * 8);
            cp16(smem_u32(Vt + r * APd + c * 8), Vg + (size_t)r * Ss + kt * 64 + c * 8);
        }
        asm volatile("cp.async.commit_group;");
    };

    float o[8][4];
    #pragma unroll
    for (int nt = 0; nt < 8; nt++)
        #pragma unroll
        for (int i = 0; i < 4; i++) o[nt][i] = 0.f;
    float m0 = -1e30f, m1 = -1e30f, l0 = 0.f, l1 = 0.f;
    const float scale = 0.125f;

    int ktmax = 2 * qblk + 1;
    loadTile(0, 0);
    for (int kt = 0; kt <= ktmax; kt++) {
        int buf = kt & 1;
        asm volatile("cp.async.wait_group 0;");
        __syncthreads();
        if (kt < ktmax) loadTile(kt + 1, buf ^ 1);
        __half* Ks = KsB[buf];
        __half* Vt = VtB[buf];

        float s[8][4];
        #pragma unroll
        for (int nt = 0; nt < 8; nt++)
            #pragma unroll
            for (int i = 0; i < 4; i++) s[nt][i] = 0.f;
        #pragma unroll
        for (int ks = 0; ks < 4; ks++) {
            #pragma unroll
            for (int ntp = 0; ntp < 4; ntp++) {
                uint32_t r0, r1, r2, r3;
                ldsm4(r0, r1, r2, r3,
                      smem_u32(Ks + (ntp * 16 + fr) * APd + ks * 16 + fcsel));
                mma_f16(s[2 * ntp],     qf[ks], r0, r2);
                mma_f16(s[2 * ntp + 1], qf[ks], r1, r3);
            }
        }

        bool diag = (kt >= 2 * qblk);
        int r0_ = q0 + wq + lr, r1_ = r0_ + 8;
        int kc0 = kt * 64;
        #pragma unroll
        for (int nt = 0; nt < 8; nt++) {
            int c0 = kc0 + nt * 8 + 2 * lc, c1 = c0 + 1;
            s[nt][0] = (diag && c0 > r0_) ? -1e30f : s[nt][0] * scale;
            s[nt][1] = (diag && c1 > r0_) ? -1e30f : s[nt][1] * scale;
            s[nt][2] = (diag && c0 > r1_) ? -1e30f : s[nt][2] * scale;
            s[nt][3] = (diag && c1 > r1_) ? -1e30f : s[nt][3] * scale;
        }

        float mx0 = -1e30f, mx1 = -1e30f;
        #pragma unroll
        for (int nt = 0; nt < 8; nt++) {
            mx0 = fmaxf(mx0, fmaxf(s[nt][0], s[nt][1]));
            mx1 = fmaxf(mx1, fmaxf(s[nt][2], s[nt][3]));
        }
        mx0 = fmaxf(mx0, __shfl_xor_sync(0xffffffffu, mx0, 1));
        mx0 = fmaxf(mx0, __shfl_xor_sync(0xffffffffu, mx0, 2));
        mx1 = fmaxf(mx1, __shfl_xor_sync(0xffffffffu, mx1, 1));
        mx1 = fmaxf(mx1, __shfl_xor_sync(0xffffffffu, mx1, 2));
        float mn0 = fmaxf(m0, mx0), mn1 = fmaxf(m1, mx1);
        float c0f = __expf(m0 - mn0), c1f = __expf(m1 - mn1);
        l0 *= c0f; l1 *= c1f;
        #pragma unroll
        for (int nt = 0; nt < 8; nt++) {
            o[nt][0] *= c0f; o[nt][1] *= c0f;
            o[nt][2] *= c1f; o[nt][3] *= c1f;
        }
        m0 = mn0; m1 = mn1;

        #pragma unroll
        for (int nt = 0; nt < 8; nt++) {
            int c0 = nt * 8 + 2 * lc;
            float p00 = __expf(s[nt][0] - mn0);
            float p01 = __expf(s[nt][1] - mn0);
            float p10 = __expf(s[nt][2] - mn1);
            float p11 = __expf(s[nt][3] - mn1);
            l0 += p00 + p01; l1 += p10 + p11;
            *(uint32_t*)&Ps[(wq + lr) * APd + c0]     = packh2(p00, p01);
            *(uint32_t*)&Ps[(wq + lr + 8) * APd + c0] = packh2(p10, p11);
        }
        __syncwarp();

        #pragma unroll
        for (int ks = 0; ks < 4; ks++) {
            uint32_t pa[4];
            ldsm4(pa[0], pa[1], pa[2], pa[3],
                  smem_u32(Ps + (wq + fr) * APd + ks * 16 + fcsel));
            #pragma unroll
            for (int ntp = 0; ntp < 4; ntp++) {
                uint32_t r0, r1, r2, r3;
                ldsm4(r0, r1, r2, r3,
                      smem_u32(Vt + (ntp * 16 + fr) * APd + ks * 16 + fcsel));
                mma_f16(o[2 * ntp],     pa, r0, r2);
                mma_f16(o[2 * ntp + 1], pa, r1, r3);
            }
        }
    }

    l0 += __shfl_xor_sync(0xffffffffu, l0, 1);
    l0 += __shfl_xor_sync(0xffffffffu, l0, 2);
    l1 += __shfl_xor_sync(0xffffffffu, l1, 1);
    l1 += __shfl_xor_sync(0xffffffffu, l1, 2);
    float i0 = 1.f / l0, i1 = 1.f / l1;
    int b = bh >> 4, h = bh & 15;
    int row0 = q0 + wq + lr, row1 = row0 + 8;
    __half* y0 = Y + (((size_t)(b * Ss + row0)) * Hh + h) * DH;
    __half* y1 = Y + (((size_t)(b * Ss + row1)) * Hh + h) * DH;
    #pragma unroll
    for (int nt = 0; nt < 8; nt++) {
        int c = nt * 8 + 2 * lc;
        *(uint32_t*)(y0 + c) = packh2(o[nt][0] * i0, o[nt][1] * i0);
        *(uint32_t*)(y1 + c) = packh2(o[nt][2] * i1, o[nt][3] * i1);
    }
}

// ---------------- launch ----------------
extern "C" void kernel_launch(void* const* d_in, const int* in_sizes, int n_in,
                              void* d_out, int out_size) {
    const float* hidden = (const float*)d_in[0];
    const float* ln1_w = (const float*)d_in[2];
    const float* ln1_b = (const float*)d_in[3];
    const float* q_U = (const float*)d_in[4];
    const float* q_V = (const float*)d_in[5];
    const float* q_b = (const float*)d_in[6];
    const float* k_U = (const float*)d_in[7];
    const float* k_V = (const float*)d_in[8];
    const float* k_b = (const float*)d_in[9];
    const float* v_U = (const float*)d_in[10];
    const float* v_V = (const float*)d_in[11];
    const float* v_b = (const float*)d_in[12];
    const float* out_U = (const float*)d_in[13];
    const float* out_V = (const float*)d_in[14];
    const float* out_b = (const float*)d_in[15];
    const float* ln2_w = (const float*)d_in[16];
    const float* ln2_b = (const float*)d_in[17];
    const float* fc1_U = (const float*)d_in[18];
    const float* fc1_V = (const float*)d_in[19];
    const float* fc1_b = (const float*)d_in[20];
    const float* fc2_U = (const float*)d_in[21];
    const float* fc2_V = (const float*)d_in[22];
    const float* fc2_b = (const float*)d_in[23];
    float* out = (float*)d_out;

    __half *x16_, *Q16_, *K16_, *V16_, *Y16_, *t16_, *a16_, *w16_, *wv16_;
    float *h_;
    cudaGetSymbolAddress((void**)&x16_,  g_x16);
    cudaGetSymbolAddress((void**)&Q16_,  g_Q16);
    cudaGetSymbolAddress((void**)&K16_,  g_K16);
    cudaGetSymbolAddress((void**)&V16_,  g_V16);
    cudaGetSymbolAddress((void**)&Y16_,  g_Y16);
    cudaGetSymbolAddress((void**)&t16_,  g_t16);
    cudaGetSymbolAddress((void**)&h_,    g_h);
    cudaGetSymbolAddress((void**)&a16_,  g_a16);
    cudaGetSymbolAddress((void**)&w16_,  g_w16);
    cudaGetSymbolAddress((void**)&wv16_, g_wv16);

    cudaFuncSetAttribute(gemm16_qkv_fused, cudaFuncAttributeMaxDynamicSharedMemorySize, FQ_SMEM);
    cudaFuncSetAttribute(gemm16<3, 64>,    cudaFuncAttributeMaxDynamicSharedMemorySize, GEMM16_SMEM(64));
    cudaFuncSetAttribute(gemm16<1, 128>,   cudaFuncAttributeMaxDynamicSharedMemorySize, GEMM16_SMEM(128));
    cudaFuncSetAttribute(gemm16<2, 128>,   cudaFuncAttributeMaxDynamicSharedMemorySize, GEMM16_SMEM(128));
    cudaFuncSetAttribute(attn_f16,         cudaFuncAttributeMaxDynamicSharedMemorySize, ATTN16_SMEM);

    // 0) weight conversion
    conv_w<<<7680, 256>>>(q_U, k_U, v_U, out_U, out_V, fc1_U, fc1_V, fc2_U, fc2_V, w16_);
    {
        dim3 g(Hh, 3);
        conv_v<<<g, 256>>>(q_V, k_V, v_V, wv16_);
    }

    // 1) x = LN1(hidden) -> fp16
    ln_kernel<<<BS, 256>>>(hidden, ln1_w, ln1_b, x16_);

    // 2+3) fused: Pq/Pk/Pv GEMM + head expansion -> Q16/K16/V16
    {
        dim3 g(24, BS / 128);
        gemm16_qkv_fused<<<g, 256, FQ_SMEM>>>(x16_, w16_, wv16_,
                                              q_b, k_b, v_b, Q16_, K16_, V16_);
    }

    // 4) causal attention -> fp16 Y
    {
        dim3 g(Ss / 128, Bb * Hh);
        attn_f16<<<g, 256, ATTN16_SMEM>>>(Q16_, K16_, V16_, Y16_);
    }

    // 5) h = hidden + (Y @ out_U) @ out_V + out_b
    {
        dim3 g1(RFC / 64, BS / 128);
        gemm16<3, 64><<<g1, 256, GEMM16_SMEM(64)>>>(Y16_, w16_ + WT_OU, t16_, BS, RFC, Dm, nullptr, nullptr);
        dim3 g2(Dm / 128, BS / 128);
        gemm16<1, 128><<<g2, 256, GEMM16_SMEM(128)>>>(t16_, w16_ + WT_OV, h_, BS, Dm, RFC, out_b, hidden);
    }

    // 6) z = LN2(h) -> fp16
    ln_kernel<<<BS, 256>>>(h_, ln2_w, ln2_b, x16_);

    // 7) a = gelu((z @ fc1_U) @ fc1_V + fc1_b) -> fp16
    {
        dim3 g1(RFC / 64, BS / 128);
        gemm16<3, 64><<<g1, 256, GEMM16_SMEM(64)>>>(x16_, w16_ + WT_F1U, t16_, BS, RFC, Dm, nullptr, nullptr);
        dim3 g2(Ii / 128, BS / 128);
        gemm16<2, 128><<<g2, 256, GEMM16_SMEM(128)>>>(t16_, w16_ + WT_F1V, a16_, BS, Ii, RFC, fc1_b, nullptr);
    }

    // 8) out = h + (a @ fc2_U) @ fc2_V + fc2_b
    {
        dim3 g1(RFC / 64, BS / 128);
        gemm16<3, 64><<<g1, 256, GEMM16_SMEM(64)>>>(a16_, w16_ + WT_F2U, t16_, BS, RFC, Ii, nullptr, nullptr);
        dim3 g2(Dm / 128, BS / 128);
        gemm16<1, 128><<<g2, 256, GEMM16_SMEM(128)>>>(t16_, w16_ + WT_F2V, out, BS, Dm, RFC, fc2_b, h_);
    }
}